// round 9
// baseline (speedup 1.0000x reference)
#include <cuda_runtime.h>
#include <math.h>

#define Bz 2
#define Sq 2048
#define Dm 1024
#define Hn 16
#define DH 64
#define NREL 129
#define BHN (Bz*Hn)

typedef unsigned long long ull;

__device__ float g_Q[BHN * Sq * DH];
__device__ float g_K[BHN * Sq * DH];
__device__ float g_V[BHN * Sq * DH];

__device__ __forceinline__ ull pack2(float lo, float hi) {
    ull r; asm("mov.b64 %0, {%1, %2};" : "=l"(r) : "f"(lo), "f"(hi)); return r;
}
__device__ __forceinline__ float2 unpack2(ull v) {
    float2 r; asm("mov.b64 {%0, %1}, %2;" : "=f"(r.x), "=f"(r.y) : "l"(v)); return r;
}
__device__ __forceinline__ void fma2(ull& a, ull x, ull y) {
    asm("fma.rn.f32x2 %0, %1, %2, %0;" : "+l"(a) : "l"(x), "l"(y));
}
__device__ __forceinline__ unsigned tf32u(float f) {
    unsigned r; asm("cvt.rna.tf32.f32 %0, %1;" : "=r"(r) : "f"(f)); return r;
}
__device__ __forceinline__ float tf32f(float f) { return __uint_as_float(tf32u(f)); }
__device__ __forceinline__ void mma_tf32(float& c0, float& c1, float& c2, float& c3,
                                         unsigned a0, unsigned a1, unsigned a2, unsigned a3,
                                         unsigned b0, unsigned b1) {
    asm("mma.sync.aligned.m16n8k8.row.col.f32.tf32.tf32.f32 "
        "{%0,%1,%2,%3}, {%4,%5,%6,%7}, {%8,%9}, {%0,%1,%2,%3};"
        : "+f"(c0), "+f"(c1), "+f"(c2), "+f"(c3)
        : "r"(a0), "r"(a1), "r"(a2), "r"(a3), "r"(b0), "r"(b1));
}

// ---------------------------------------------------------------------------
// Kernel 1: QKV projection (FFMA2, fp32 — unchanged, known good).
// ---------------------------------------------------------------------------
__global__ __launch_bounds__(256, 2)
void qkv_proj_kernel(const float* __restrict__ Xq, const float* __restrict__ Xk,
                     const float* __restrict__ Xv,
                     const float* __restrict__ Wq, const float* __restrict__ Wk,
                     const float* __restrict__ Wv,
                     const float* __restrict__ bq, const float* __restrict__ bk,
                     const float* __restrict__ bv)
{
    const float* X; const float* W; const float* bias; float* outp;
    if (blockIdx.z == 0)      { X = Xq; W = Wq; bias = bq; outp = g_Q; }
    else if (blockIdx.z == 1) { X = Xk; W = Wk; bias = bk; outp = g_K; }
    else                      { X = Xv; W = Wv; bias = bv; outp = g_V; }

    __shared__ __align__(16) float Xs[16][132];
    __shared__ __align__(16) float Ws[16][132];

    const int tid = threadIdx.x;
    const int tx = tid & 15, ty = tid >> 4;
    const int m0 = blockIdx.y * 128, n0 = blockIdx.x * 128;
    const int xr = tid & 127, xk = (tid >> 7) * 8;
    const int wr = tid >> 4,  wc = (tid & 15) * 8;

    ull acc[8][4];
    #pragma unroll
    for (int i = 0; i < 8; i++)
        #pragma unroll
        for (int j = 0; j < 4; j++) acc[i][j] = 0ull;

    float4 xa = *(const float4*)&X[(size_t)(m0 + xr) * Dm + xk];
    float4 xb = *(const float4*)&X[(size_t)(m0 + xr) * Dm + xk + 4];
    float4 wa = *(const float4*)&W[(size_t)wr * Dm + n0 + wc];
    float4 wb = *(const float4*)&W[(size_t)wr * Dm + n0 + wc + 4];

    for (int t = 0; t < 64; t++) {
        Xs[xk + 0][xr] = xa.x; Xs[xk + 1][xr] = xa.y;
        Xs[xk + 2][xr] = xa.z; Xs[xk + 3][xr] = xa.w;
        Xs[xk + 4][xr] = xb.x; Xs[xk + 5][xr] = xb.y;
        Xs[xk + 6][xr] = xb.z; Xs[xk + 7][xr] = xb.w;
        *(float4*)&Ws[wr][wc] = wa;
        *(float4*)&Ws[wr][wc + 4] = wb;
        __syncthreads();
        if (t < 63) {
            const int k0 = (t + 1) * 16;
            xa = *(const float4*)&X[(size_t)(m0 + xr) * Dm + k0 + xk];
            xb = *(const float4*)&X[(size_t)(m0 + xr) * Dm + k0 + xk + 4];
            wa = *(const float4*)&W[(size_t)(k0 + wr) * Dm + n0 + wc];
            wb = *(const float4*)&W[(size_t)(k0 + wr) * Dm + n0 + wc + 4];
        }
        #pragma unroll
        for (int kk = 0; kk < 16; kk++) {
            float4 a0 = *(const float4*)&Xs[kk][ty * 8];
            float4 a1 = *(const float4*)&Xs[kk][ty * 8 + 4];
            ulonglong2 b0 = *(const ulonglong2*)&Ws[kk][tx * 4];
            ulonglong2 b1 = *(const ulonglong2*)&Ws[kk][64 + tx * 4];
            ull p;
            p = pack2(a0.x, a0.x); fma2(acc[0][0], p, b0.x); fma2(acc[0][1], p, b0.y); fma2(acc[0][2], p, b1.x); fma2(acc[0][3], p, b1.y);
            p = pack2(a0.y, a0.y); fma2(acc[1][0], p, b0.x); fma2(acc[1][1], p, b0.y); fma2(acc[1][2], p, b1.x); fma2(acc[1][3], p, b1.y);
            p = pack2(a0.z, a0.z); fma2(acc[2][0], p, b0.x); fma2(acc[2][1], p, b0.y); fma2(acc[2][2], p, b1.x); fma2(acc[2][3], p, b1.y);
            p = pack2(a0.w, a0.w); fma2(acc[3][0], p, b0.x); fma2(acc[3][1], p, b0.y); fma2(acc[3][2], p, b1.x); fma2(acc[3][3], p, b1.y);
            p = pack2(a1.x, a1.x); fma2(acc[4][0], p, b0.x); fma2(acc[4][1], p, b0.y); fma2(acc[4][2], p, b1.x); fma2(acc[4][3], p, b1.y);
            p = pack2(a1.y, a1.y); fma2(acc[5][0], p, b0.x); fma2(acc[5][1], p, b0.y); fma2(acc[5][2], p, b1.x); fma2(acc[5][3], p, b1.y);
            p = pack2(a1.z, a1.z); fma2(acc[6][0], p, b0.x); fma2(acc[6][1], p, b0.y); fma2(acc[6][2], p, b1.x); fma2(acc[6][3], p, b1.y);
            p = pack2(a1.w, a1.w); fma2(acc[7][0], p, b0.x); fma2(acc[7][1], p, b0.y); fma2(acc[7][2], p, b1.x); fma2(acc[7][3], p, b1.y);
        }
        __syncthreads();
    }

    float4 bl = *(const float4*)&bias[n0 + tx * 4];
    float4 bh = *(const float4*)&bias[n0 + 64 + tx * 4];
    const int h0 = n0 >> 6;
    #pragma unroll
    for (int i = 0; i < 8; i++) {
        const int m = m0 + ty * 8 + i, bb = m >> 11, s = m & 2047;
        float2 c0 = unpack2(acc[i][0]), c1 = unpack2(acc[i][1]);
        float4 v = make_float4(c0.x + bl.x, c0.y + bl.y, c1.x + bl.z, c1.y + bl.w);
        *(float4*)&outp[((size_t)((bb * Hn + h0) * Sq + s)) * DH + tx * 4] = v;
        c0 = unpack2(acc[i][2]); c1 = unpack2(acc[i][3]);
        v = make_float4(c0.x + bh.x, c0.y + bh.y, c1.x + bh.z, c1.y + bh.w);
        *(float4*)&outp[((size_t)((bb * Hn + h0 + 1) * Sq + s)) * DH + tx * 4] = v;
    }
}

// ---------------------------------------------------------------------------
// Kernel 2: flash attention, tf32 mma, 512 threads (16 warps), n-split pairs.
// Conflict-free fragment layouts: Kt[d][j] / Vs[j][dc] at stride 72.
// ---------------------------------------------------------------------------
#define QS_O 0        // Qs[128][68] natural, tf32, pre-scaled by 0.125
#define KT_O 8704     // Kt[2][64][72]  K transposed [d][j]
#define VS_O 17920    // Vs[2][64][72]  V natural [j][dc]
#define PS_O 27136    // Ps[128][68] natural tf32  (relS overlay [129][66])
#define PB_O 35840    // pb[128][132] fp32 (pre-scaled by 0.125)
#define MK_O 52736    // maskS[68]
#define RD_O 52804    // red[2][128] cross-warp partials
#define SMF  53060

extern __shared__ __align__(16) float sm[];

__global__ __launch_bounds__(512, 1)
void attn_kernel(const float* __restrict__ mask,
                 const float* __restrict__ rel,
                 float* __restrict__ out)
{
    float* Qs = sm + QS_O;
    float* Kt = sm + KT_O;
    float* Vs = sm + VS_O;
    float* Ps = sm + PS_O;
    float* pb = sm + PB_O;
    float* maskS = sm + MK_O;
    float* red = sm + RD_O;
    float* relS = sm + PS_O;   // stride 66, dead after pb phase

    const int tid = threadIdx.x;
    const int w = tid >> 5, lane = tid & 31;
    const int wq = w >> 1, wn = w & 1;
    const int grp = lane >> 2, tig = lane & 3;
    const int bh = blockIdx.y, b = bh >> 4, h = bh & 15;
    const int q0 = blockIdx.x * 128;

    const float* Qg = g_Q + (size_t)bh * (Sq * DH);
    const float* Kg = g_K + (size_t)bh * (Sq * DH);
    const float* Vg = g_V + (size_t)bh * (Sq * DH);
    const float* maskb = mask + (size_t)b * Sq;

    // ---- stage Q (tf32, pre-scaled by 1/8) ----
    {
        const int qr = tid & 127, qc = (tid >> 7) * 16;
        #pragma unroll
        for (int u = 0; u < 4; u++) {
            float4 v = *(const float4*)&Qg[(size_t)(q0 + qr) * DH + qc + 4 * u];
            float4 t = make_float4(tf32f(0.125f * v.x), tf32f(0.125f * v.y),
                                   tf32f(0.125f * v.z), tf32f(0.125f * v.w));
            *(float4*)&Qs[qr * 68 + qc + 4 * u] = t;
        }
    }
    // ---- stage rel (fp32, stride 66) ----
    for (int i = tid; i < NREL * 32; i += 512) {
        int t = i >> 5, dp = i & 31;
        *(float2*)&relS[t * 66 + 2 * dp] = *(const float2*)&rel[t * DH + 2 * dp];
    }
    // ---- prefetch tile 0 K/V/mask into regs ----
    const int krow = tid & 63, kd0 = (tid >> 6) * 8;
    float4 kr4[2], vr4[2], mv;
    #pragma unroll
    for (int c = 0; c < 2; c++) {
        kr4[c] = *(const float4*)&Kg[(size_t)krow * DH + kd0 + 4 * c];
        vr4[c] = *(const float4*)&Vg[(size_t)krow * DH + kd0 + 4 * c];
    }
    if (tid < 16) mv = *(const float4*)&maskb[tid * 4];
    __syncthreads();

    // ---- pb[r][t] = (q_r/8) . rel_t  (FFMA2, d-packed, 4 rows/thread) ----
    {
        const int tx = tid & 15, ty = tid >> 4;   // ty 0..31
        const int rbase = ty * 4;
        ull pa[4][9];
        #pragma unroll
        for (int i = 0; i < 4; i++)
            #pragma unroll
            for (int tt = 0; tt < 9; tt++) pa[i][tt] = 0ull;
        for (int dp = 0; dp < 32; dp++) {
            ull qv[4];
            #pragma unroll
            for (int i = 0; i < 4; i++)
                qv[i] = *(const ull*)&Qs[(rbase + i) * 68 + 2 * dp];
            #pragma unroll
            for (int tt = 0; tt < 9; tt++) {
                int t = tx + 16 * tt;
                if (t < NREL) {
                    ull rv = *(const ull*)&relS[t * 66 + 2 * dp];
                    fma2(pa[0][tt], qv[0], rv);
                    fma2(pa[1][tt], qv[1], rv);
                    fma2(pa[2][tt], qv[2], rv);
                    fma2(pa[3][tt], qv[3], rv);
                }
            }
        }
        #pragma unroll
        for (int tt = 0; tt < 9; tt++) {
            int t = tx + 16 * tt;
            if (t < NREL) {
                #pragma unroll
                for (int i = 0; i < 4; i++) {
                    float2 f = unpack2(pa[i][tt]);
                    pb[(rbase + i) * 132 + t] = f.x + f.y;
                }
            }
        }
    }
    __syncthreads();

    const int rlo = wq * 16 + grp, rhi = rlo + 8;
    const int rglo = q0 + rlo, rghi = q0 + rhi;
    const float pLo_l = pb[rlo * 132], pHi_l = pb[rlo * 132 + 128];
    const float pLo_h = pb[rhi * 132], pHi_h = pb[rhi * 132 + 128];

    float o[4][4];
    #pragma unroll
    for (int nn = 0; nn < 4; nn++)
        #pragma unroll
        for (int c = 0; c < 4; c++) o[nn][c] = 0.f;
    float m_lo = -INFINITY, m_hi = -INFINITY, l_lo = 0.f, l_hi = 0.f;

    for (int kt = 0; kt < 32; kt++) {
        const int buf = kt & 1;
        const int k0 = kt * 64;
        float* Kb = Kt + buf * 4608;
        float* Vb = Vs + buf * 4608;

        // ---- stage this tile: K transposed (stride 72), V natural (stride 72) ----
        #pragma unroll
        for (int c = 0; c < 2; c++) {
            const int d = kd0 + 4 * c;
            Kb[(d + 0) * 72 + krow] = tf32f(kr4[c].x);
            Kb[(d + 1) * 72 + krow] = tf32f(kr4[c].y);
            Kb[(d + 2) * 72 + krow] = tf32f(kr4[c].z);
            Kb[(d + 3) * 72 + krow] = tf32f(kr4[c].w);
            float4 t = make_float4(tf32f(vr4[c].x), tf32f(vr4[c].y),
                                   tf32f(vr4[c].z), tf32f(vr4[c].w));
            *(float4*)&Vb[krow * 72 + d] = t;
        }
        if (tid < 16) *(float4*)&maskS[tid * 4] = mv;
        // ---- prefetch next tile ----
        if (kt < 31) {
            const float* Kn = Kg + (size_t)(k0 + 64) * DH;
            const float* Vn = Vg + (size_t)(k0 + 64) * DH;
            #pragma unroll
            for (int c = 0; c < 2; c++) {
                kr4[c] = *(const float4*)&Kn[(size_t)krow * DH + kd0 + 4 * c];
                vr4[c] = *(const float4*)&Vn[(size_t)krow * DH + kd0 + 4 * c];
            }
            if (tid < 16) mv = *(const float4*)&maskb[k0 + 64 + tid * 4];
        }
        __syncthreads();   // A: tile staged

        // ---- scores (this warp's 4 n-groups) ----
        float sc[4][4];
        #pragma unroll
        for (int nn = 0; nn < 4; nn++)
            #pragma unroll
            for (int c = 0; c < 4; c++) sc[nn][c] = 0.f;
        #pragma unroll
        for (int kk = 0; kk < 8; kk++) {
            unsigned a0 = __float_as_uint(Qs[rlo * 68 + kk * 8 + tig]);
            unsigned a1 = __float_as_uint(Qs[rhi * 68 + kk * 8 + tig]);
            unsigned a2 = __float_as_uint(Qs[rlo * 68 + kk * 8 + tig + 4]);
            unsigned a3 = __float_as_uint(Qs[rhi * 68 + kk * 8 + tig + 4]);
            #pragma unroll
            for (int nn = 0; nn < 4; nn++) {
                const int n = wn * 4 + nn;
                unsigned b0 = __float_as_uint(Kb[(kk * 8 + tig) * 72 + n * 8 + grp]);
                unsigned b1 = __float_as_uint(Kb[(kk * 8 + tig + 4) * 72 + n * 8 + grp]);
                mma_tf32(sc[nn][0], sc[nn][1], sc[nn][2], sc[nn][3], a0, a1, a2, a3, b0, b1);
            }
        }

        // ---- bias + mask, partial max ----
        const int ddmin = k0 - (q0 + 127), ddmax = k0 + 63 - q0;
        const bool gen = (ddmax > -64) && (ddmin < 64);
        const float bC_l = (ddmin >= 64) ? pHi_l : pLo_l;
        const float bC_h = (ddmin >= 64) ? pHi_h : pLo_h;
        float mx_lo = -INFINITY, mx_hi = -INFINITY;
        #pragma unroll
        for (int nn = 0; nn < 4; nn++) {
            const int c0 = (wn * 4 + nn) * 8 + 2 * tig;
            float2 mk = *(const float2*)&maskS[c0];
            float b00, b01, b10, b11;
            if (gen) {
                int d0 = k0 + c0 - rglo;
                int t00 = d0     < -64 ? 0 : (d0     > 64 ? 128 : d0 + 64);
                int t01 = d0 + 1 < -64 ? 0 : (d0 + 1 > 64 ? 128 : d0 + 65);
                int d1 = k0 + c0 - rghi;
                int t10 = d1     < -64 ? 0 : (d1     > 64 ? 128 : d1 + 64);
                int t11 = d1 + 1 < -64 ? 0 : (d1 + 1 > 64 ? 128 : d1 + 65);
                b00 = pb[rlo * 132 + t00]; b01 = pb[rlo * 132 + t01];
                b10 = pb[rhi * 132 + t10]; b11 = pb[rhi * 132 + t11];
            } else { b00 = b01 = bC_l; b10 = b11 = bC_h; }
            sc[nn][0] = sc[nn][0] + b00 + mk.x;
            sc[nn][1] = sc[nn][1] + b01 + mk.y;
            sc[nn][2] = sc[nn][2] + b10 + mk.x;
            sc[nn][3] = sc[nn][3] + b11 + mk.y;
            mx_lo = fmaxf(mx_lo, fmaxf(sc[nn][0], sc[nn][1]));
            mx_hi = fmaxf(mx_hi, fmaxf(sc[nn][2], sc[nn][3]));
        }
        mx_lo = fmaxf(mx_lo, __shfl_xor_sync(0xffffffffu, mx_lo, 1, 4));
        mx_lo = fmaxf(mx_lo, __shfl_xor_sync(0xffffffffu, mx_lo, 2, 4));
        mx_hi = fmaxf(mx_hi, __shfl_xor_sync(0xffffffffu, mx_hi, 1, 4));
        mx_hi = fmaxf(mx_hi, __shfl_xor_sync(0xffffffffu, mx_hi, 2, 4));
        if ((lane & 3) == 0) {
            red[wn * 128 + rlo] = mx_lo;
            red[wn * 128 + rhi] = mx_hi;
        }
        __syncthreads();   // B: partial maxima visible
        mx_lo = fmaxf(red[rlo], red[128 + rlo]);
        mx_hi = fmaxf(red[rhi], red[128 + rhi]);

        const float mn_lo = fmaxf(m_lo, mx_lo), mn_hi = fmaxf(m_hi, mx_hi);
        const float al_lo = __expf(m_lo - mn_lo), al_hi = __expf(m_hi - mn_hi);
        float rs_lo = 0.f, rs_hi = 0.f;
        #pragma unroll
        for (int nn = 0; nn < 4; nn++) {
            sc[nn][0] = __expf(sc[nn][0] - mn_lo); rs_lo += sc[nn][0];
            sc[nn][1] = __expf(sc[nn][1] - mn_lo); rs_lo += sc[nn][1];
            sc[nn][2] = __expf(sc[nn][2] - mn_hi); rs_hi += sc[nn][2];
            sc[nn][3] = __expf(sc[nn][3] - mn_hi); rs_hi += sc[nn][3];
        }
        rs_lo += __shfl_xor_sync(0xffffffffu, rs_lo, 1, 4);
        rs_lo += __shfl_xor_sync(0xffffffffu, rs_lo, 2, 4);
        rs_hi += __shfl_xor_sync(0xffffffffu, rs_hi, 1, 4);
        rs_hi += __shfl_xor_sync(0xffffffffu, rs_hi, 2, 4);
        l_lo = l_lo * al_lo + rs_lo; m_lo = mn_lo;   // warp-local partial l
        l_hi = l_hi * al_hi + rs_hi; m_hi = mn_hi;
        #pragma unroll
        for (int nn = 0; nn < 4; nn++) {
            o[nn][0] *= al_lo; o[nn][1] *= al_lo;
            o[nn][2] *= al_hi; o[nn][3] *= al_hi;
        }
        // ---- stage P (tf32), this warp's 32 cols ----
        #pragma unroll
        for (int nn = 0; nn < 4; nn++) {
            const int c0 = (wn * 4 + nn) * 8 + 2 * tig;
            *(float2*)&Ps[rlo * 68 + c0] = make_float2(tf32f(sc[nn][0]), tf32f(sc[nn][1]));
            *(float2*)&Ps[rhi * 68 + c0] = make_float2(tf32f(sc[nn][2]), tf32f(sc[nn][3]));
        }
        __syncthreads();   // C: P complete

        // ---- O += P V (this warp's 4 dc-groups) ----
        #pragma unroll
        for (int jj = 0; jj < 8; jj++) {
            unsigned a0 = __float_as_uint(Ps[rlo * 68 + jj * 8 + tig]);
            unsigned a1 = __float_as_uint(Ps[rhi * 68 + jj * 8 + tig]);
            unsigned a2 = __float_as_uint(Ps[rlo * 68 + jj * 8 + tig + 4]);
            unsigned a3 = __float_as_uint(Ps[rhi * 68 + jj * 8 + tig + 4]);
            #pragma unroll
            for (int nn = 0; nn < 4; nn++) {
                const int n = wn * 4 + nn;
                unsigned b0 = __float_as_uint(Vb[(jj * 8 + tig) * 72 + n * 8 + grp]);
                unsigned b1 = __float_as_uint(Vb[(jj * 8 + tig + 4) * 72 + n * 8 + grp]);
                mma_tf32(o[nn][0], o[nn][1], o[nn][2], o[nn][3], a0, a1, a2, a3, b0, b1);
            }
        }
    }

    // ---- combine l partials across warp pair, then write out ----
    if ((lane & 3) == 0) {
        red[wn * 128 + rlo] = l_lo;
        red[wn * 128 + rhi] = l_hi;
    }
    __syncthreads();
    const float inv_lo = 1.f / (red[rlo] + red[128 + rlo]);
    const float inv_hi = 1.f / (red[rhi] + red[128 + rhi]);
    #pragma unroll
    for (int nn = 0; nn < 4; nn++) {
        const int col = h * DH + (wn * 4 + nn) * 8 + 2 * tig;
        *(float2*)&out[((size_t)(b * Sq + rglo)) * Dm + col] =
            make_float2(o[nn][0] * inv_lo, o[nn][1] * inv_lo);
        *(float2*)&out[((size_t)(b * Sq + rghi)) * Dm + col] =
            make_float2(o[nn][2] * inv_hi, o[nn][3] * inv_hi);
    }
}

extern "C" void kernel_launch(void* const* d_in, const int* in_sizes, int n_in,
                              void* d_out, int out_size)
{
    const float* query = (const float*)d_in[0];
    const float* key   = (const float*)d_in[1];
    const float* value = (const float*)d_in[2];
    const float* mask  = (const float*)d_in[3];
    const float* Wq    = (const float*)d_in[4];
    const float* bq    = (const float*)d_in[5];
    const float* Wk    = (const float*)d_in[6];
    const float* bk    = (const float*)d_in[7];
    const float* Wv    = (const float*)d_in[8];
    const float* bv    = (const float*)d_in[9];
    const float* rel   = (const float*)d_in[10];
    float* out = (float*)d_out;
    (void)in_sizes; (void)n_in; (void)out_size;

    const int ATTN_SMEM = SMF * (int)sizeof(float);
    cudaFuncSetAttribute(attn_kernel,
                         cudaFuncAttributeMaxDynamicSharedMemorySize, ATTN_SMEM);

    dim3 gemm_grid(Dm / 128, (Bz * Sq) / 128, 3);
    qkv_proj_kernel<<<gemm_grid, 256>>>(query, key, value, Wq, Wk, Wv, bq, bk, bv);

    dim3 attn_grid(Sq / 128, Bz * Hn);
    attn_kernel<<<attn_grid, 512, ATTN_SMEM>>>(mask, rel, out);
}

// round 10
// speedup vs baseline: 1.0250x; 1.0250x over previous
#include <cuda_runtime.h>
#include <math.h>

#define Bz 2
#define Sq 2048
#define Dm 1024
#define Hn 16
#define DH 64
#define NREL 129
#define BHN (Bz*Hn)

typedef unsigned long long ull;

__device__ float g_Q[BHN * Sq * DH];
__device__ float g_K[BHN * Sq * DH];
__device__ float g_V[BHN * Sq * DH];

__device__ __forceinline__ ull pack2(float lo, float hi) {
    ull r; asm("mov.b64 %0, {%1, %2};" : "=l"(r) : "f"(lo), "f"(hi)); return r;
}
__device__ __forceinline__ float2 unpack2(ull v) {
    float2 r; asm("mov.b64 {%0, %1}, %2;" : "=f"(r.x), "=f"(r.y) : "l"(v)); return r;
}
__device__ __forceinline__ void fma2(ull& a, ull x, ull y) {
    asm("fma.rn.f32x2 %0, %1, %2, %0;" : "+l"(a) : "l"(x), "l"(y));
}
__device__ __forceinline__ unsigned tf32u(float f) {
    unsigned r; asm("cvt.rna.tf32.f32 %0, %1;" : "=r"(r) : "f"(f)); return r;
}
__device__ __forceinline__ float tf32f(float f) { return __uint_as_float(tf32u(f)); }
__device__ __forceinline__ void mma_tf32(float& c0, float& c1, float& c2, float& c3,
                                         unsigned a0, unsigned a1, unsigned a2, unsigned a3,
                                         unsigned b0, unsigned b1) {
    asm("mma.sync.aligned.m16n8k8.row.col.f32.tf32.tf32.f32 "
        "{%0,%1,%2,%3}, {%4,%5,%6,%7}, {%8,%9}, {%0,%1,%2,%3};"
        : "+f"(c0), "+f"(c1), "+f"(c2), "+f"(c3)
        : "r"(a0), "r"(a1), "r"(a2), "r"(a3), "r"(b0), "r"(b1));
}
__device__ __forceinline__ void ldsm4(unsigned& r0, unsigned& r1, unsigned& r2, unsigned& r3,
                                      unsigned addr) {
    asm volatile("ldmatrix.sync.aligned.m8n8.x4.shared.b16 {%0,%1,%2,%3}, [%4];"
        : "=r"(r0), "=r"(r1), "=r"(r2), "=r"(r3) : "r"(addr));
}
__device__ __forceinline__ unsigned smem_u32(const void* p) {
    return (unsigned)__cvta_generic_to_shared(p);
}

// ---------------------------------------------------------------------------
// Kernel 1: QKV projection (FFMA2, fp32 — unchanged, known good).
// ---------------------------------------------------------------------------
__global__ __launch_bounds__(256, 2)
void qkv_proj_kernel(const float* __restrict__ Xq, const float* __restrict__ Xk,
                     const float* __restrict__ Xv,
                     const float* __restrict__ Wq, const float* __restrict__ Wk,
                     const float* __restrict__ Wv,
                     const float* __restrict__ bq, const float* __restrict__ bk,
                     const float* __restrict__ bv)
{
    const float* X; const float* W; const float* bias; float* outp;
    if (blockIdx.z == 0)      { X = Xq; W = Wq; bias = bq; outp = g_Q; }
    else if (blockIdx.z == 1) { X = Xk; W = Wk; bias = bk; outp = g_K; }
    else                      { X = Xv; W = Wv; bias = bv; outp = g_V; }

    __shared__ __align__(16) float Xs[16][132];
    __shared__ __align__(16) float Ws[16][132];

    const int tid = threadIdx.x;
    const int tx = tid & 15, ty = tid >> 4;
    const int m0 = blockIdx.y * 128, n0 = blockIdx.x * 128;
    const int xr = tid & 127, xk = (tid >> 7) * 8;
    const int wr = tid >> 4,  wc = (tid & 15) * 8;

    ull acc[8][4];
    #pragma unroll
    for (int i = 0; i < 8; i++)
        #pragma unroll
        for (int j = 0; j < 4; j++) acc[i][j] = 0ull;

    float4 xa = *(const float4*)&X[(size_t)(m0 + xr) * Dm + xk];
    float4 xb = *(const float4*)&X[(size_t)(m0 + xr) * Dm + xk + 4];
    float4 wa = *(const float4*)&W[(size_t)wr * Dm + n0 + wc];
    float4 wb = *(const float4*)&W[(size_t)wr * Dm + n0 + wc + 4];

    for (int t = 0; t < 64; t++) {
        Xs[xk + 0][xr] = xa.x; Xs[xk + 1][xr] = xa.y;
        Xs[xk + 2][xr] = xa.z; Xs[xk + 3][xr] = xa.w;
        Xs[xk + 4][xr] = xb.x; Xs[xk + 5][xr] = xb.y;
        Xs[xk + 6][xr] = xb.z; Xs[xk + 7][xr] = xb.w;
        *(float4*)&Ws[wr][wc] = wa;
        *(float4*)&Ws[wr][wc + 4] = wb;
        __syncthreads();
        if (t < 63) {
            const int k0 = (t + 1) * 16;
            xa = *(const float4*)&X[(size_t)(m0 + xr) * Dm + k0 + xk];
            xb = *(const float4*)&X[(size_t)(m0 + xr) * Dm + k0 + xk + 4];
            wa = *(const float4*)&W[(size_t)(k0 + wr) * Dm + n0 + wc];
            wb = *(const float4*)&W[(size_t)(k0 + wr) * Dm + n0 + wc + 4];
        }
        #pragma unroll
        for (int kk = 0; kk < 16; kk++) {
            float4 a0 = *(const float4*)&Xs[kk][ty * 8];
            float4 a1 = *(const float4*)&Xs[kk][ty * 8 + 4];
            ulonglong2 b0 = *(const ulonglong2*)&Ws[kk][tx * 4];
            ulonglong2 b1 = *(const ulonglong2*)&Ws[kk][64 + tx * 4];
            ull p;
            p = pack2(a0.x, a0.x); fma2(acc[0][0], p, b0.x); fma2(acc[0][1], p, b0.y); fma2(acc[0][2], p, b1.x); fma2(acc[0][3], p, b1.y);
            p = pack2(a0.y, a0.y); fma2(acc[1][0], p, b0.x); fma2(acc[1][1], p, b0.y); fma2(acc[1][2], p, b1.x); fma2(acc[1][3], p, b1.y);
            p = pack2(a0.z, a0.z); fma2(acc[2][0], p, b0.x); fma2(acc[2][1], p, b0.y); fma2(acc[2][2], p, b1.x); fma2(acc[2][3], p, b1.y);
            p = pack2(a0.w, a0.w); fma2(acc[3][0], p, b0.x); fma2(acc[3][1], p, b0.y); fma2(acc[3][2], p, b1.x); fma2(acc[3][3], p, b1.y);
            p = pack2(a1.x, a1.x); fma2(acc[4][0], p, b0.x); fma2(acc[4][1], p, b0.y); fma2(acc[4][2], p, b1.x); fma2(acc[4][3], p, b1.y);
            p = pack2(a1.y, a1.y); fma2(acc[5][0], p, b0.x); fma2(acc[5][1], p, b0.y); fma2(acc[5][2], p, b1.x); fma2(acc[5][3], p, b1.y);
            p = pack2(a1.z, a1.z); fma2(acc[6][0], p, b0.x); fma2(acc[6][1], p, b0.y); fma2(acc[6][2], p, b1.x); fma2(acc[6][3], p, b1.y);
            p = pack2(a1.w, a1.w); fma2(acc[7][0], p, b0.x); fma2(acc[7][1], p, b0.y); fma2(acc[7][2], p, b1.x); fma2(acc[7][3], p, b1.y);
        }
        __syncthreads();
    }

    float4 bl = *(const float4*)&bias[n0 + tx * 4];
    float4 bh = *(const float4*)&bias[n0 + 64 + tx * 4];
    const int h0 = n0 >> 6;
    #pragma unroll
    for (int i = 0; i < 8; i++) {
        const int m = m0 + ty * 8 + i, bb = m >> 11, s = m & 2047;
        float2 c0 = unpack2(acc[i][0]), c1 = unpack2(acc[i][1]);
        float4 v = make_float4(c0.x + bl.x, c0.y + bl.y, c1.x + bl.z, c1.y + bl.w);
        *(float4*)&outp[((size_t)((bb * Hn + h0) * Sq + s)) * DH + tx * 4] = v;
        c0 = unpack2(acc[i][2]); c1 = unpack2(acc[i][3]);
        v = make_float4(c0.x + bh.x, c0.y + bh.y, c1.x + bh.z, c1.y + bh.w);
        *(float4*)&outp[((size_t)((bb * Hn + h0 + 1) * Sq + s)) * DH + tx * 4] = v;
    }
}

// ---------------------------------------------------------------------------
// Kernel 2: flash attention, tf32 mma + ldmatrix, 256 threads (8 warps),
// Q fragments register-resident, warp-local softmax.
// ---------------------------------------------------------------------------
#define QS_O 0        // Qs[128][68] natural, tf32, pre-scaled by 0.125
#define KS_O 8704     // Ks[2][64][68] natural [j][d], tf32
#define VT_O 17408    // Vt[2][64][68] transposed [dc][j], tf32
#define PS_O 26112    // Ps[128][68] natural tf32  (relS overlay [129][66])
#define PB_O 34816    // pb[128][132] fp32 (pre-scaled by 0.125)
#define MK_O 51712    // maskS[68]
#define SMF  51780

extern __shared__ __align__(16) float sm[];

__global__ __launch_bounds__(256, 1)
void attn_kernel(const float* __restrict__ mask,
                 const float* __restrict__ rel,
                 float* __restrict__ out)
{
    float* Qs = sm + QS_O;
    float* Ks = sm + KS_O;
    float* Vt = sm + VT_O;
    float* Ps = sm + PS_O;
    float* pb = sm + PB_O;
    float* maskS = sm + MK_O;
    float* relS = sm + PS_O;   // stride 66, dead after pb phase

    const int tid = threadIdx.x;
    const int w = tid >> 5, lane = tid & 31;
    const int grp = lane >> 2, tig = lane & 3;
    const int bh = blockIdx.y, b = bh >> 4, h = bh & 15;
    const int q0 = blockIdx.x * 128;

    const float* Qg = g_Q + (size_t)bh * (Sq * DH);
    const float* Kg = g_K + (size_t)bh * (Sq * DH);
    const float* Vg = g_V + (size_t)bh * (Sq * DH);
    const float* maskb = mask + (size_t)b * Sq;

    // ---- stage Q (tf32, pre-scaled by 1/8) ----
    {
        const int qr = tid & 127, qc = (tid >> 7) * 32;
        #pragma unroll
        for (int u = 0; u < 8; u++) {
            float4 v = *(const float4*)&Qg[(size_t)(q0 + qr) * DH + qc + 4 * u];
            float4 t = make_float4(tf32f(0.125f * v.x), tf32f(0.125f * v.y),
                                   tf32f(0.125f * v.z), tf32f(0.125f * v.w));
            *(float4*)&Qs[qr * 68 + qc + 4 * u] = t;
        }
    }
    // ---- stage rel (fp32, stride 66) ----
    for (int i = tid; i < NREL * 32; i += 256) {
        int t = i >> 5, dp = i & 31;
        *(float2*)&relS[t * 66 + 2 * dp] = *(const float2*)&rel[t * DH + 2 * dp];
    }
    // ---- prefetch tile 0 K/V/mask ----
    const int krow = tid & 63, kd0 = (tid >> 6) * 16;
    float4 kr4[4], vr4[4], mv;
    #pragma unroll
    for (int c = 0; c < 4; c++) {
        kr4[c] = *(const float4*)&Kg[(size_t)krow * DH + kd0 + 4 * c];
        vr4[c] = *(const float4*)&Vg[(size_t)krow * DH + kd0 + 4 * c];
    }
    if (tid < 16) mv = *(const float4*)&maskb[tid * 4];
    __syncthreads();

    // ---- pb[r][t] = (q_r/8) . rel_t  (FFMA2, d-packed) ----
    {
        const int tx = tid & 15, ty = tid >> 4;
        #pragma unroll
        for (int pass = 0; pass < 2; pass++) {
            const int rbase = ty * 8 + pass * 4;
            ull pa[4][9];
            #pragma unroll
            for (int i = 0; i < 4; i++)
                #pragma unroll
                for (int tt = 0; tt < 9; tt++) pa[i][tt] = 0ull;
            for (int dp = 0; dp < 32; dp++) {
                ull qv[4];
                #pragma unroll
                for (int i = 0; i < 4; i++)
                    qv[i] = *(const ull*)&Qs[(rbase + i) * 68 + 2 * dp];
                #pragma unroll
                for (int tt = 0; tt < 9; tt++) {
                    int t = tx + 16 * tt;
                    if (t < NREL) {
                        ull rv = *(const ull*)&relS[t * 66 + 2 * dp];
                        fma2(pa[0][tt], qv[0], rv);
                        fma2(pa[1][tt], qv[1], rv);
                        fma2(pa[2][tt], qv[2], rv);
                        fma2(pa[3][tt], qv[3], rv);
                    }
                }
            }
            #pragma unroll
            for (int tt = 0; tt < 9; tt++) {
                int t = tx + 16 * tt;
                if (t < NREL) {
                    #pragma unroll
                    for (int i = 0; i < 4; i++) {
                        float2 f = unpack2(pa[i][tt]);
                        pb[(rbase + i) * 132 + t] = f.x + f.y;
                    }
                }
            }
        }
    }
    __syncthreads();

    // ---- hoist Q a-fragments into registers (8 LDSM.x4) ----
    const int rbase = w * 16;
    const int rlo = rbase + grp, rhi = rlo + 8;
    const int rglo = q0 + rlo, rghi = q0 + rhi;
    // a-frag lane offset: row = (lane&7) + ((lane>>3)&1)*8, chunk = (lane>>4)
    const unsigned aoff = (unsigned)(((lane & 7) + ((lane >> 3) & 1) * 8) * 272
                                     + (lane >> 4) * 16);
    // b-frag lane offset: row = ((lane>>4)<<3) + (lane&7), chunk = (lane>>3)&1
    const unsigned boff = (unsigned)((((lane >> 4) << 3) + (lane & 7)) * 272
                                     + ((lane >> 3) & 1) * 16);
    unsigned qa[8][4];
    {
        const unsigned qbase = smem_u32(Qs) + (unsigned)(rbase * 272) + aoff;
        #pragma unroll
        for (int kk = 0; kk < 8; kk++)
            ldsm4(qa[kk][0], qa[kk][1], qa[kk][2], qa[kk][3], qbase + kk * 32);
    }
    const float pLo_l = pb[rlo * 132], pHi_l = pb[rlo * 132 + 128];
    const float pLo_h = pb[rhi * 132], pHi_h = pb[rhi * 132 + 128];
    const unsigned ksb = smem_u32(Ks) + boff;
    const unsigned vtb = smem_u32(Vt) + boff;
    const unsigned psb = smem_u32(Ps) + (unsigned)(rbase * 272) + aoff;

    float o[8][4];
    #pragma unroll
    for (int n = 0; n < 8; n++)
        #pragma unroll
        for (int c = 0; c < 4; c++) o[n][c] = 0.f;
    float m_lo = -INFINITY, m_hi = -INFINITY, l_lo = 0.f, l_hi = 0.f;

    for (int kt = 0; kt < 32; kt++) {
        const int buf = kt & 1;
        const int k0 = kt * 64;
        float* Kb = Ks + buf * 4352;
        float* Vb = Vt + buf * 4352;

        // ---- stage tile: K natural (float4), V transposed (scalar) ----
        #pragma unroll
        for (int c = 0; c < 4; c++) {
            const int d = kd0 + 4 * c;
            float4 t = make_float4(tf32f(kr4[c].x), tf32f(kr4[c].y),
                                   tf32f(kr4[c].z), tf32f(kr4[c].w));
            *(float4*)&Kb[krow * 68 + d] = t;
            Vb[(d + 0) * 68 + krow] = tf32f(vr4[c].x);
            Vb[(d + 1) * 68 + krow] = tf32f(vr4[c].y);
            Vb[(d + 2) * 68 + krow] = tf32f(vr4[c].z);
            Vb[(d + 3) * 68 + krow] = tf32f(vr4[c].w);
        }
        if (tid < 16) *(float4*)&maskS[tid * 4] = mv;
        if (kt < 31) {
            const float* Kn = Kg + (size_t)(k0 + 64) * DH;
            const float* Vn = Vg + (size_t)(k0 + 64) * DH;
            #pragma unroll
            for (int c = 0; c < 4; c++) {
                kr4[c] = *(const float4*)&Kn[(size_t)krow * DH + kd0 + 4 * c];
                vr4[c] = *(const float4*)&Vn[(size_t)krow * DH + kd0 + 4 * c];
            }
            if (tid < 16) mv = *(const float4*)&maskb[k0 + 64 + tid * 4];
        }
        __syncthreads();   // A: tile staged

        // ---- scores: S = Q K^T (b-frags via LDSM.x4, 2 n-groups per load) ----
        float sc[8][4];
        #pragma unroll
        for (int n = 0; n < 8; n++)
            #pragma unroll
            for (int c = 0; c < 4; c++) sc[n][c] = 0.f;
        const unsigned kbuf = ksb + (unsigned)(buf * 17408);
        #pragma unroll
        for (int kk = 0; kk < 8; kk++) {
            #pragma unroll
            for (int np = 0; np < 4; np++) {
                unsigned b0, b1, b2, b3;
                ldsm4(b0, b1, b2, b3, kbuf + np * 4352 + kk * 32);
                mma_tf32(sc[2*np][0], sc[2*np][1], sc[2*np][2], sc[2*np][3],
                         qa[kk][0], qa[kk][1], qa[kk][2], qa[kk][3], b0, b1);
                mma_tf32(sc[2*np+1][0], sc[2*np+1][1], sc[2*np+1][2], sc[2*np+1][3],
                         qa[kk][0], qa[kk][1], qa[kk][2], qa[kk][3], b2, b3);
            }
        }

        // ---- bias + mask + warp-local online softmax ----
        const int ddmin = k0 - (q0 + 127), ddmax = k0 + 63 - q0;
        const bool gen = (ddmax > -64) && (ddmin < 64);
        const float bC_l = (ddmin >= 64) ? pHi_l : pLo_l;
        const float bC_h = (ddmin >= 64) ? pHi_h : pLo_h;
        float mx_lo = -INFINITY, mx_hi = -INFINITY;
        #pragma unroll
        for (int n = 0; n < 8; n++) {
            const int c0 = n * 8 + 2 * tig;
            float2 mk = *(const float2*)&maskS[c0];
            float b00, b01, b10, b11;
            if (gen) {
                int d0 = k0 + c0 - rglo;
                int t00 = d0     < -64 ? 0 : (d0     > 64 ? 128 : d0 + 64);
                int t01 = d0 + 1 < -64 ? 0 : (d0 + 1 > 64 ? 128 : d0 + 65);
                int d1 = k0 + c0 - rghi;
                int t10 = d1     < -64 ? 0 : (d1     > 64 ? 128 : d1 + 64);
                int t11 = d1 + 1 < -64 ? 0 : (d1 + 1 > 64 ? 128 : d1 + 65);
                b00 = pb[rlo * 132 + t00]; b01 = pb[rlo * 132 + t01];
                b10 = pb[rhi * 132 + t10]; b11 = pb[rhi * 132 + t11];
            } else { b00 = b01 = bC_l; b10 = b11 = bC_h; }
            sc[n][0] = sc[n][0] + b00 + mk.x;
            sc[n][1] = sc[n][1] + b01 + mk.y;
            sc[n][2] = sc[n][2] + b10 + mk.x;
            sc[n][3] = sc[n][3] + b11 + mk.y;
            mx_lo = fmaxf(mx_lo, fmaxf(sc[n][0], sc[n][1]));
            mx_hi = fmaxf(mx_hi, fmaxf(sc[n][2], sc[n][3]));
        }
        mx_lo = fmaxf(mx_lo, __shfl_xor_sync(0xffffffffu, mx_lo, 1, 4));
        mx_lo = fmaxf(mx_lo, __shfl_xor_sync(0xffffffffu, mx_lo, 2, 4));
        mx_hi = fmaxf(mx_hi, __shfl_xor_sync(0xffffffffu, mx_hi, 1, 4));
        mx_hi = fmaxf(mx_hi, __shfl_xor_sync(0xffffffffu, mx_hi, 2, 4));
        const float mn_lo = fmaxf(m_lo, mx_lo), mn_hi = fmaxf(m_hi, mx_hi);
        const float al_lo = __expf(m_lo - mn_lo), al_hi = __expf(m_hi - mn_hi);
        float rs_lo = 0.f, rs_hi = 0.f;
        #pragma unroll
        for (int n = 0; n < 8; n++) {
            sc[n][0] = __expf(sc[n][0] - mn_lo); rs_lo += sc[n][0];
            sc[n][1] = __expf(sc[n][1] - mn_lo); rs_lo += sc[n][1];
            sc[n][2] = __expf(sc[n][2] - mn_hi); rs_hi += sc[n][2];
            sc[n][3] = __expf(sc[n][3] - mn_hi); rs_hi += sc[n][3];
        }
        rs_lo += __shfl_xor_sync(0xffffffffu, rs_lo, 1, 4);
        rs_lo += __shfl_xor_sync(0xffffffffu, rs_lo, 2, 4);
        rs_hi += __shfl_xor_sync(0xffffffffu, rs_hi, 1, 4);
        rs_hi += __shfl_xor_sync(0xffffffffu, rs_hi, 2, 4);
        l_lo = l_lo * al_lo + rs_lo; m_lo = mn_lo;
        l_hi = l_hi * al_hi + rs_hi; m_hi = mn_hi;
        #pragma unroll
        for (int n = 0; n < 8; n++) {
            o[n][0] *= al_lo; o[n][1] *= al_lo;
            o[n][2] *= al_hi; o[n][3] *= al_hi;
        }
        // ---- stage P (tf32) ----
        #pragma unroll
        for (int n = 0; n < 8; n++) {
            const int c0 = n * 8 + 2 * tig;
            *(float2*)&Ps[rlo * 68 + c0] = make_float2(tf32f(sc[n][0]), tf32f(sc[n][1]));
            *(float2*)&Ps[rhi * 68 + c0] = make_float2(tf32f(sc[n][2]), tf32f(sc[n][3]));
        }
        __syncthreads();   // B: P complete

        // ---- O += P V (P a-frags + V b-frags via LDSM) ----
        const unsigned vbuf = vtb + (unsigned)(buf * 17408);
        #pragma unroll
        for (int jj = 0; jj < 8; jj++) {
            unsigned pa0, pa1, pa2, pa3;
            ldsm4(pa0, pa1, pa2, pa3, psb + jj * 32);
            #pragma unroll
            for (int np = 0; np < 4; np++) {
                unsigned b0, b1, b2, b3;
                ldsm4(b0, b1, b2, b3, vbuf + np * 4352 + jj * 32);
                mma_tf32(o[2*np][0], o[2*np][1], o[2*np][2], o[2*np][3],
                         pa0, pa1, pa2, pa3, b0, b1);
                mma_tf32(o[2*np+1][0], o[2*np+1][1], o[2*np+1][2], o[2*np+1][3],
                         pa0, pa1, pa2, pa3, b2, b3);
            }
        }
    }

    // ---- epilogue ----
    const float inv_lo = 1.f / l_lo, inv_hi = 1.f / l_hi;
    #pragma unroll
    for (int n = 0; n < 8; n++) {
        const int col = h * DH + n * 8 + 2 * tig;
        *(float2*)&out[((size_t)(b * Sq + rglo)) * Dm + col] =
            make_float2(o[n][0] * inv_lo, o[n][1] * inv_lo);
        *(float2*)&out[((size_t)(b * Sq + rghi)) * Dm + col] =
            make_float2(o[n][2] * inv_hi, o[n][3] * inv_hi);
    }
}

extern "C" void kernel_launch(void* const* d_in, const int* in_sizes, int n_in,
                              void* d_out, int out_size)
{
    const float* query = (const float*)d_in[0];
    const float* key   = (const float*)d_in[1];
    const float* value = (const float*)d_in[2];
    const float* mask  = (const float*)d_in[3];
    const float* Wq    = (const float*)d_in[4];
    const float* bq    = (const float*)d_in[5];
    const float* Wk    = (const float*)d_in[6];
    const float* bk    = (const float*)d_in[7];
    const float* Wv    = (const float*)d_in[8];
    const float* bv    = (const float*)d_in[9];
    const float* rel   = (const float*)d_in[10];
    float* out = (float*)d_out;
    (void)in_sizes; (void)n_in; (void)out_size;

    const int ATTN_SMEM = SMF * (int)sizeof(float);
    cudaFuncSetAttribute(attn_kernel,
                         cudaFuncAttributeMaxDynamicSharedMemorySize, ATTN_SMEM);

    dim3 gemm_grid(Dm / 128, (Bz * Sq) / 128, 3);
    qkv_proj_kernel<<<gemm_grid, 256>>>(query, key, value, Wq, Wk, Wv, bq, bk, bv);

    dim3 attn_grid(Sq / 128, Bz * Hn);
    attn_kernel<<<attn_grid, 256, ATTN_SMEM>>>(mask, rel, out);
}

// round 11
// speedup vs baseline: 1.2345x; 1.2043x over previous
#include <cuda_runtime.h>
#include <math.h>

#define Bz 2
#define Sq 2048
#define Dm 1024
#define Hn 16
#define DH 64
#define NREL 129
#define BHN (Bz*Hn)

typedef unsigned long long ull;

__device__ float g_Q[BHN * Sq * DH];
__device__ float g_K[BHN * Sq * DH];
__device__ float g_V[BHN * Sq * DH];

__device__ __forceinline__ ull pack2(float lo, float hi) {
    ull r; asm("mov.b64 %0, {%1, %2};" : "=l"(r) : "f"(lo), "f"(hi)); return r;
}
__device__ __forceinline__ float2 unpack2(ull v) {
    float2 r; asm("mov.b64 {%0, %1}, %2;" : "=f"(r.x), "=f"(r.y) : "l"(v)); return r;
}
__device__ __forceinline__ void fma2(ull& a, ull x, ull y) {
    asm("fma.rn.f32x2 %0, %1, %2, %0;" : "+l"(a) : "l"(x), "l"(y));
}
__device__ __forceinline__ unsigned tf32u(float f) {
    unsigned r; asm("cvt.rna.tf32.f32 %0, %1;" : "=r"(r) : "f"(f)); return r;
}
__device__ __forceinline__ float tf32f(float f) { return __uint_as_float(tf32u(f)); }
__device__ __forceinline__ void mma_tf32(float& c0, float& c1, float& c2, float& c3,
                                         unsigned a0, unsigned a1, unsigned a2, unsigned a3,
                                         unsigned b0, unsigned b1) {
    asm("mma.sync.aligned.m16n8k8.row.col.f32.tf32.tf32.f32 "
        "{%0,%1,%2,%3}, {%4,%5,%6,%7}, {%8,%9}, {%0,%1,%2,%3};"
        : "+f"(c0), "+f"(c1), "+f"(c2), "+f"(c3)
        : "r"(a0), "r"(a1), "r"(a2), "r"(a3), "r"(b0), "r"(b1));
}
__device__ __forceinline__ void ldsm4(unsigned& r0, unsigned& r1, unsigned& r2, unsigned& r3,
                                      unsigned addr) {
    asm volatile("ldmatrix.sync.aligned.m8n8.x4.shared.b16 {%0,%1,%2,%3}, [%4];"
        : "=r"(r0), "=r"(r1), "=r"(r2), "=r"(r3) : "r"(addr));
}
__device__ __forceinline__ unsigned smem_u32(const void* p) {
    return (unsigned)__cvta_generic_to_shared(p);
}

// ---------------------------------------------------------------------------
// Kernel 1: QKV projection on tf32 mma.sync. 128x64x16 tiles, 256 threads,
// 8 warps (4m x 2n), 32x32 per warp, double-buffered smem, 2 CTAs/SM.
// grid (16, 32, 3).
// ---------------------------------------------------------------------------
__global__ __launch_bounds__(256, 2)
void qkv_proj_kernel(const float* __restrict__ Xq, const float* __restrict__ Xk,
                     const float* __restrict__ Xv,
                     const float* __restrict__ Wq, const float* __restrict__ Wk,
                     const float* __restrict__ Wv,
                     const float* __restrict__ bq, const float* __restrict__ bk,
                     const float* __restrict__ bv)
{
    const float* X; const float* W; const float* bias; float* outp;
    if (blockIdx.z == 0)      { X = Xq; W = Wq; bias = bq; outp = g_Q; }
    else if (blockIdx.z == 1) { X = Xk; W = Wk; bias = bk; outp = g_K; }
    else                      { X = Xv; W = Wv; bias = bv; outp = g_V; }

    __shared__ __align__(16) float Xs[2][128 * 20];   // [m][k] natural, tf32
    __shared__ __align__(16) float Wt[2][64 * 20];    // [n][k] transposed, tf32

    const int tid = threadIdx.x;
    const int lane = tid & 31, w = tid >> 5;
    const int wm = w >> 1, wn = w & 1;                 // 4m x 2n warp grid
    const int grp = lane >> 2, tig = lane & 3;
    const int m0 = blockIdx.y * 128, n0 = blockIdx.x * 64;

    // staging assignments
    const int xr = tid >> 1, xc = (tid & 1) * 8;       // X: row, k-chunk
    const int wk = tid & 15, wn4 = (tid >> 4) * 4;     // W: k-row, n-chunk

    // fragment lane offsets (bytes), cloned from the working attn layout,
    // row stride 272B -> 80B
    const unsigned aoff = (unsigned)(((lane & 7) + ((lane >> 3) & 1) * 8) * 80
                                     + (lane >> 4) * 16);
    const unsigned boff = (unsigned)(((((lane >> 4) << 3) + (lane & 7))) * 80
                                     + ((lane >> 3) & 1) * 16);

    float acc[2][4][4];
    #pragma unroll
    for (int mi = 0; mi < 2; mi++)
        #pragma unroll
        for (int ni = 0; ni < 4; ni++)
            #pragma unroll
            for (int c = 0; c < 4; c++) acc[mi][ni][c] = 0.f;

    const float* Xp = X + (size_t)(m0 + xr) * Dm + xc;
    const float* Wp = W + (size_t)wk * Dm + n0 + wn4;

    float4 xa = *(const float4*)Xp;
    float4 xb = *(const float4*)(Xp + 4);
    float4 wv4 = *(const float4*)Wp;

    // stage buffer 0
    {
        float* xd = &Xs[0][xr * 20 + xc];
        *(float4*)xd = make_float4(tf32f(xa.x), tf32f(xa.y), tf32f(xa.z), tf32f(xa.w));
        *(float4*)(xd + 4) = make_float4(tf32f(xb.x), tf32f(xb.y), tf32f(xb.z), tf32f(xb.w));
        Wt[0][(wn4 + 0) * 20 + wk] = tf32f(wv4.x);
        Wt[0][(wn4 + 1) * 20 + wk] = tf32f(wv4.y);
        Wt[0][(wn4 + 2) * 20 + wk] = tf32f(wv4.z);
        Wt[0][(wn4 + 3) * 20 + wk] = tf32f(wv4.w);
    }
    __syncthreads();

    for (int t = 0; t < 64; t++) {
        const int cur = t & 1;
        if (t < 63) {
            xa = *(const float4*)(Xp + (t + 1) * 16);
            xb = *(const float4*)(Xp + (t + 1) * 16 + 4);
            wv4 = *(const float4*)(Wp + (size_t)(t + 1) * 16 * Dm);
        }
        const unsigned xbase = smem_u32(&Xs[cur][0]) + (unsigned)(wm * 32 * 80) + aoff;
        const unsigned wbase = smem_u32(&Wt[cur][0]) + (unsigned)(wn * 32 * 80) + boff;
        #pragma unroll
        for (int kk = 0; kk < 2; kk++) {
            unsigned a0[4], a1[4];
            ldsm4(a0[0], a0[1], a0[2], a0[3], xbase + kk * 32);
            ldsm4(a1[0], a1[1], a1[2], a1[3], xbase + 16 * 80 + kk * 32);
            #pragma unroll
            for (int np = 0; np < 2; np++) {
                unsigned b0, b1, b2, b3;
                ldsm4(b0, b1, b2, b3, wbase + np * 16 * 80 + kk * 32);
                mma_tf32(acc[0][2*np][0], acc[0][2*np][1], acc[0][2*np][2], acc[0][2*np][3],
                         a0[0], a0[1], a0[2], a0[3], b0, b1);
                mma_tf32(acc[0][2*np+1][0], acc[0][2*np+1][1], acc[0][2*np+1][2], acc[0][2*np+1][3],
                         a0[0], a0[1], a0[2], a0[3], b2, b3);
                mma_tf32(acc[1][2*np][0], acc[1][2*np][1], acc[1][2*np][2], acc[1][2*np][3],
                         a1[0], a1[1], a1[2], a1[3], b0, b1);
                mma_tf32(acc[1][2*np+1][0], acc[1][2*np+1][1], acc[1][2*np+1][2], acc[1][2*np+1][3],
                         a1[0], a1[1], a1[2], a1[3], b2, b3);
            }
        }
        if (t < 63) {
            const int nxt = cur ^ 1;
            float* xd = &Xs[nxt][xr * 20 + xc];
            *(float4*)xd = make_float4(tf32f(xa.x), tf32f(xa.y), tf32f(xa.z), tf32f(xa.w));
            *(float4*)(xd + 4) = make_float4(tf32f(xb.x), tf32f(xb.y), tf32f(xb.z), tf32f(xb.w));
            Wt[nxt][(wn4 + 0) * 20 + wk] = tf32f(wv4.x);
            Wt[nxt][(wn4 + 1) * 20 + wk] = tf32f(wv4.y);
            Wt[nxt][(wn4 + 2) * 20 + wk] = tf32f(wv4.z);
            Wt[nxt][(wn4 + 3) * 20 + wk] = tf32f(wv4.w);
        }
        __syncthreads();
    }

    // ---- epilogue: +bias, head-split store (n-tile == one head) ----
    const int h = blockIdx.x;
    #pragma unroll
    for (int mi = 0; mi < 2; mi++) {
        const int mlo = m0 + wm * 32 + mi * 16 + grp;
        const int mhi = mlo + 8;
        const int blo = mlo >> 11, slo = mlo & 2047;
        const int bhi = mhi >> 11, shi = mhi & 2047;
        #pragma unroll
        for (int ni = 0; ni < 4; ni++) {
            const int col = wn * 32 + ni * 8 + 2 * tig;
            const float b0v = bias[n0 + col], b1v = bias[n0 + col + 1];
            *(float2*)&outp[((size_t)((blo * Hn + h) * Sq + slo)) * DH + col] =
                make_float2(acc[mi][ni][0] + b0v, acc[mi][ni][1] + b1v);
            *(float2*)&outp[((size_t)((bhi * Hn + h) * Sq + shi)) * DH + col] =
                make_float2(acc[mi][ni][2] + b0v, acc[mi][ni][3] + b1v);
        }
    }
}

// ---------------------------------------------------------------------------
// Kernel 2: flash attention, tf32 mma + ldmatrix (round-10, unchanged).
// ---------------------------------------------------------------------------
#define QS_O 0
#define KS_O 8704
#define VT_O 17408
#define PS_O 26112
#define PB_O 34816
#define MK_O 51712
#define SMF  51780

extern __shared__ __align__(16) float sm[];

__global__ __launch_bounds__(256, 1)
void attn_kernel(const float* __restrict__ mask,
                 const float* __restrict__ rel,
                 float* __restrict__ out)
{
    float* Qs = sm + QS_O;
    float* Ks = sm + KS_O;
    float* Vt = sm + VT_O;
    float* Ps = sm + PS_O;
    float* pb = sm + PB_O;
    float* maskS = sm + MK_O;
    float* relS = sm + PS_O;

    const int tid = threadIdx.x;
    const int w = tid >> 5, lane = tid & 31;
    const int grp = lane >> 2, tig = lane & 3;
    const int bh = blockIdx.y, b = bh >> 4, h = bh & 15;
    const int q0 = blockIdx.x * 128;

    const float* Qg = g_Q + (size_t)bh * (Sq * DH);
    const float* Kg = g_K + (size_t)bh * (Sq * DH);
    const float* Vg = g_V + (size_t)bh * (Sq * DH);
    const float* maskb = mask + (size_t)b * Sq;

    {
        const int qr = tid & 127, qc = (tid >> 7) * 32;
        #pragma unroll
        for (int u = 0; u < 8; u++) {
            float4 v = *(const float4*)&Qg[(size_t)(q0 + qr) * DH + qc + 4 * u];
            float4 t = make_float4(tf32f(0.125f * v.x), tf32f(0.125f * v.y),
                                   tf32f(0.125f * v.z), tf32f(0.125f * v.w));
            *(float4*)&Qs[qr * 68 + qc + 4 * u] = t;
        }
    }
    for (int i = tid; i < NREL * 32; i += 256) {
        int t = i >> 5, dp = i & 31;
        *(float2*)&relS[t * 66 + 2 * dp] = *(const float2*)&rel[t * DH + 2 * dp];
    }
    const int krow = tid & 63, kd0 = (tid >> 6) * 16;
    float4 kr4[4], vr4[4], mv;
    #pragma unroll
    for (int c = 0; c < 4; c++) {
        kr4[c] = *(const float4*)&Kg[(size_t)krow * DH + kd0 + 4 * c];
        vr4[c] = *(const float4*)&Vg[(size_t)krow * DH + kd0 + 4 * c];
    }
    if (tid < 16) mv = *(const float4*)&maskb[tid * 4];
    __syncthreads();

    {
        const int tx = tid & 15, ty = tid >> 4;
        #pragma unroll
        for (int pass = 0; pass < 2; pass++) {
            const int rbase = ty * 8 + pass * 4;
            ull pa[4][9];
            #pragma unroll
            for (int i = 0; i < 4; i++)
                #pragma unroll
                for (int tt = 0; tt < 9; tt++) pa[i][tt] = 0ull;
            for (int dp = 0; dp < 32; dp++) {
                ull qv[4];
                #pragma unroll
                for (int i = 0; i < 4; i++)
                    qv[i] = *(const ull*)&Qs[(rbase + i) * 68 + 2 * dp];
                #pragma unroll
                for (int tt = 0; tt < 9; tt++) {
                    int t = tx + 16 * tt;
                    if (t < NREL) {
                        ull rv = *(const ull*)&relS[t * 66 + 2 * dp];
                        fma2(pa[0][tt], qv[0], rv);
                        fma2(pa[1][tt], qv[1], rv);
                        fma2(pa[2][tt], qv[2], rv);
                        fma2(pa[3][tt], qv[3], rv);
                    }
                }
            }
            #pragma unroll
            for (int tt = 0; tt < 9; tt++) {
                int t = tx + 16 * tt;
                if (t < NREL) {
                    #pragma unroll
                    for (int i = 0; i < 4; i++) {
                        float2 f = unpack2(pa[i][tt]);
                        pb[(rbase + i) * 132 + t] = f.x + f.y;
                    }
                }
            }
        }
    }
    __syncthreads();

    const int rbase = w * 16;
    const int rlo = rbase + grp, rhi = rlo + 8;
    const int rglo = q0 + rlo, rghi = q0 + rhi;
    const unsigned aoff = (unsigned)(((lane & 7) + ((lane >> 3) & 1) * 8) * 272
                                     + (lane >> 4) * 16);
    const unsigned boff = (unsigned)((((lane >> 4) << 3) + (lane & 7)) * 272
                                     + ((lane >> 3) & 1) * 16);
    unsigned qa[8][4];
    {
        const unsigned qbase = smem_u32(Qs) + (unsigned)(rbase * 272) + aoff;
        #pragma unroll
        for (int kk = 0; kk < 8; kk++)
            ldsm4(qa[kk][0], qa[kk][1], qa[kk][2], qa[kk][3], qbase + kk * 32);
    }
    const float pLo_l = pb[rlo * 132], pHi_l = pb[rlo * 132 + 128];
    const float pLo_h = pb[rhi * 132], pHi_h = pb[rhi * 132 + 128];
    const unsigned ksb = smem_u32(Ks) + boff;
    const unsigned vtb = smem_u32(Vt) + boff;
    const unsigned psb = smem_u32(Ps) + (unsigned)(rbase * 272) + aoff;

    float o[8][4];
    #pragma unroll
    for (int n = 0; n < 8; n++)
        #pragma unroll
        for (int c = 0; c < 4; c++) o[n][c] = 0.f;
    float m_lo = -INFINITY, m_hi = -INFINITY, l_lo = 0.f, l_hi = 0.f;

    for (int kt = 0; kt < 32; kt++) {
        const int buf = kt & 1;
        const int k0 = kt * 64;
        float* Kb = Ks + buf * 4352;
        float* Vb = Vt + buf * 4352;

        #pragma unroll
        for (int c = 0; c < 4; c++) {
            const int d = kd0 + 4 * c;
            float4 t = make_float4(tf32f(kr4[c].x), tf32f(kr4[c].y),
                                   tf32f(kr4[c].z), tf32f(kr4[c].w));
            *(float4*)&Kb[krow * 68 + d] = t;
            Vb[(d + 0) * 68 + krow] = tf32f(vr4[c].x);
            Vb[(d + 1) * 68 + krow] = tf32f(vr4[c].y);
            Vb[(d + 2) * 68 + krow] = tf32f(vr4[c].z);
            Vb[(d + 3) * 68 + krow] = tf32f(vr4[c].w);
        }
        if (tid < 16) *(float4*)&maskS[tid * 4] = mv;
        if (kt < 31) {
            const float* Kn = Kg + (size_t)(k0 + 64) * DH;
            const float* Vn = Vg + (size_t)(k0 + 64) * DH;
            #pragma unroll
            for (int c = 0; c < 4; c++) {
                kr4[c] = *(const float4*)&Kn[(size_t)krow * DH + kd0 + 4 * c];
                vr4[c] = *(const float4*)&Vn[(size_t)krow * DH + kd0 + 4 * c];
            }
            if (tid < 16) mv = *(const float4*)&maskb[k0 + 64 + tid * 4];
        }
        __syncthreads();

        float sc[8][4];
        #pragma unroll
        for (int n = 0; n < 8; n++)
            #pragma unroll
            for (int c = 0; c < 4; c++) sc[n][c] = 0.f;
        const unsigned kbuf = ksb + (unsigned)(buf * 17408);
        #pragma unroll
        for (int kk = 0; kk < 8; kk++) {
            #pragma unroll
            for (int np = 0; np < 4; np++) {
                unsigned b0, b1, b2, b3;
                ldsm4(b0, b1, b2, b3, kbuf + np * 4352 + kk * 32);
                mma_tf32(sc[2*np][0], sc[2*np][1], sc[2*np][2], sc[2*np][3],
                         qa[kk][0], qa[kk][1], qa[kk][2], qa[kk][3], b0, b1);
                mma_tf32(sc[2*np+1][0], sc[2*np+1][1], sc[2*np+1][2], sc[2*np+1][3],
                         qa[kk][0], qa[kk][1], qa[kk][2], qa[kk][3], b2, b3);
            }
        }

        const int ddmin = k0 - (q0 + 127), ddmax = k0 + 63 - q0;
        const bool gen = (ddmax > -64) && (ddmin < 64);
        const float bC_l = (ddmin >= 64) ? pHi_l : pLo_l;
        const float bC_h = (ddmin >= 64) ? pHi_h : pLo_h;
        float mx_lo = -INFINITY, mx_hi = -INFINITY;
        #pragma unroll
        for (int n = 0; n < 8; n++) {
            const int c0 = n * 8 + 2 * tig;
            float2 mk = *(const float2*)&maskS[c0];
            float b00, b01, b10, b11;
            if (gen) {
                int d0 = k0 + c0 - rglo;
                int t00 = d0     < -64 ? 0 : (d0     > 64 ? 128 : d0 + 64);
                int t01 = d0 + 1 < -64 ? 0 : (d0 + 1 > 64 ? 128 : d0 + 65);
                int d1 = k0 + c0 - rghi;
                int t10 = d1     < -64 ? 0 : (d1     > 64 ? 128 : d1 + 64);
                int t11 = d1 + 1 < -64 ? 0 : (d1 + 1 > 64 ? 128 : d1 + 65);
                b00 = pb[rlo * 132 + t00]; b01 = pb[rlo * 132 + t01];
                b10 = pb[rhi * 132 + t10]; b11 = pb[rhi * 132 + t11];
            } else { b00 = b01 = bC_l; b10 = b11 = bC_h; }
            sc[n][0] = sc[n][0] + b00 + mk.x;
            sc[n][1] = sc[n][1] + b01 + mk.y;
            sc[n][2] = sc[n][2] + b10 + mk.x;
            sc[n][3] = sc[n][3] + b11 + mk.y;
            mx_lo = fmaxf(mx_lo, fmaxf(sc[n][0], sc[n][1]));
            mx_hi = fmaxf(mx_hi, fmaxf(sc[n][2], sc[n][3]));
        }
        mx_lo = fmaxf(mx_lo, __shfl_xor_sync(0xffffffffu, mx_lo, 1, 4));
        mx_lo = fmaxf(mx_lo, __shfl_xor_sync(0xffffffffu, mx_lo, 2, 4));
        mx_hi = fmaxf(mx_hi, __shfl_xor_sync(0xffffffffu, mx_hi, 1, 4));
        mx_hi = fmaxf(mx_hi, __shfl_xor_sync(0xffffffffu, mx_hi, 2, 4));
        const float mn_lo = fmaxf(m_lo, mx_lo), mn_hi = fmaxf(m_hi, mx_hi);
        const float al_lo = __expf(m_lo - mn_lo), al_hi = __expf(m_hi - mn_hi);
        float rs_lo = 0.f, rs_hi = 0.f;
        #pragma unroll
        for (int n = 0; n < 8; n++) {
            sc[n][0] = __expf(sc[n][0] - mn_lo); rs_lo += sc[n][0];
            sc[n][1] = __expf(sc[n][1] - mn_lo); rs_lo += sc[n][1];
            sc[n][2] = __expf(sc[n][2] - mn_hi); rs_hi += sc[n][2];
            sc[n][3] = __expf(sc[n][3] - mn_hi); rs_hi += sc[n][3];
        }
        rs_lo += __shfl_xor_sync(0xffffffffu, rs_lo, 1, 4);
        rs_lo += __shfl_xor_sync(0xffffffffu, rs_lo, 2, 4);
        rs_hi += __shfl_xor_sync(0xffffffffu, rs_hi, 1, 4);
        rs_hi += __shfl_xor_sync(0xffffffffu, rs_hi, 2, 4);
        l_lo = l_lo * al_lo + rs_lo; m_lo = mn_lo;
        l_hi = l_hi * al_hi + rs_hi; m_hi = mn_hi;
        #pragma unroll
        for (int n = 0; n < 8; n++) {
            o[n][0] *= al_lo; o[n][1] *= al_lo;
            o[n][2] *= al_hi; o[n][3] *= al_hi;
        }
        #pragma unroll
        for (int n = 0; n < 8; n++) {
            const int c0 = n * 8 + 2 * tig;
            *(float2*)&Ps[rlo * 68 + c0] = make_float2(tf32f(sc[n][0]), tf32f(sc[n][1]));
            *(float2*)&Ps[rhi * 68 + c0] = make_float2(tf32f(sc[n][2]), tf32f(sc[n][3]));
        }
        __syncthreads();

        const unsigned vbuf = vtb + (unsigned)(buf * 17408);
        #pragma unroll
        for (int jj = 0; jj < 8; jj++) {
            unsigned pa0, pa1, pa2, pa3;
            ldsm4(pa0, pa1, pa2, pa3, psb + jj * 32);
            #pragma unroll
            for (int np = 0; np < 4; np++) {
                unsigned b0, b1, b2, b3;
                ldsm4(b0, b1, b2, b3, vbuf + np * 4352 + jj * 32);
                mma_tf32(o[2*np][0], o[2*np][1], o[2*np][2], o[2*np][3],
                         pa0, pa1, pa2, pa3, b0, b1);
                mma_tf32(o[2*np+1][0], o[2*np+1][1], o[2*np+1][2], o[2*np+1][3],
                         pa0, pa1, pa2, pa3, b2, b3);
            }
        }
    }

    const float inv_lo = 1.f / l_lo, inv_hi = 1.f / l_hi;
    #pragma unroll
    for (int n = 0; n < 8; n++) {
        const int col = h * DH + n * 8 + 2 * tig;
        *(float2*)&out[((size_t)(b * Sq + rglo)) * Dm + col] =
            make_float2(o[n][0] * inv_lo, o[n][1] * inv_lo);
        *(float2*)&out[((size_t)(b * Sq + rghi)) * Dm + col] =
            make_float2(o[n][2] * inv_hi, o[n][3] * inv_hi);
    }
}

extern "C" void kernel_launch(void* const* d_in, const int* in_sizes, int n_in,
                              void* d_out, int out_size)
{
    const float* query = (const float*)d_in[0];
    const float* key   = (const float*)d_in[1];
    const float* value = (const float*)d_in[2];
    const float* mask  = (const float*)d_in[3];
    const float* Wq    = (const float*)d_in[4];
    const float* bq    = (const float*)d_in[5];
    const float* Wk    = (const float*)d_in[6];
    const float* bk    = (const float*)d_in[7];
    const float* Wv    = (const float*)d_in[8];
    const float* bv    = (const float*)d_in[9];
    const float* rel   = (const float*)d_in[10];
    float* out = (float*)d_out;
    (void)in_sizes; (void)n_in; (void)out_size;

    const int ATTN_SMEM = SMF * (int)sizeof(float);
    cudaFuncSetAttribute(attn_kernel,
                         cudaFuncAttributeMaxDynamicSharedMemorySize, ATTN_SMEM);

    dim3 gemm_grid(Dm / 64, (Bz * Sq) / 128, 3);
    qkv_proj_kernel<<<gemm_grid, 256>>>(query, key, value, Wq, Wk, Wv, bq, bk, bv);

    dim3 attn_grid(Sq / 128, Bz * Hn);
    attn_kernel<<<attn_grid, 256, ATTN_SMEM>>>(mask, rel, out);
}

// round 12
// speedup vs baseline: 1.3232x; 1.0719x over previous
#include <cuda_runtime.h>
#include <cuda_bf16.h>
#include <math.h>

#define Bz 2
#define Sq 2048
#define Dm 1024
#define Hn 16
#define DH 64
#define NREL 129
#define BHN (Bz*Hn)

typedef unsigned long long ull;

__device__ float g_Q[BHN * Sq * DH];
__device__ float g_K[BHN * Sq * DH];
__device__ float g_V[BHN * Sq * DH];

__device__ __forceinline__ ull pack2(float lo, float hi) {
    ull r; asm("mov.b64 %0, {%1, %2};" : "=l"(r) : "f"(lo), "f"(hi)); return r;
}
__device__ __forceinline__ float2 unpack2(ull v) {
    float2 r; asm("mov.b64 {%0, %1}, %2;" : "=f"(r.x), "=f"(r.y) : "l"(v)); return r;
}
__device__ __forceinline__ void fma2(ull& a, ull x, ull y) {
    asm("fma.rn.f32x2 %0, %1, %2, %0;" : "+l"(a) : "l"(x), "l"(y));
}
__device__ __forceinline__ unsigned tf32u(float f) {
    unsigned r; asm("cvt.rna.tf32.f32 %0, %1;" : "=r"(r) : "f"(f)); return r;
}
__device__ __forceinline__ float tf32f(float f) { return __uint_as_float(tf32u(f)); }
__device__ __forceinline__ void mma_tf32(float& c0, float& c1, float& c2, float& c3,
                                         unsigned a0, unsigned a1, unsigned a2, unsigned a3,
                                         unsigned b0, unsigned b1) {
    asm("mma.sync.aligned.m16n8k8.row.col.f32.tf32.tf32.f32 "
        "{%0,%1,%2,%3}, {%4,%5,%6,%7}, {%8,%9}, {%0,%1,%2,%3};"
        : "+f"(c0), "+f"(c1), "+f"(c2), "+f"(c3)
        : "r"(a0), "r"(a1), "r"(a2), "r"(a3), "r"(b0), "r"(b1));
}
__device__ __forceinline__ void ldsm4(unsigned& r0, unsigned& r1, unsigned& r2, unsigned& r3,
                                      unsigned addr) {
    asm volatile("ldmatrix.sync.aligned.m8n8.x4.shared.b16 {%0,%1,%2,%3}, [%4];"
        : "=r"(r0), "=r"(r1), "=r"(r2), "=r"(r3) : "r"(addr));
}
__device__ __forceinline__ unsigned smem_u32(const void* p) {
    return (unsigned)__cvta_generic_to_shared(p);
}

// ---------------------------------------------------------------------------
// Kernel 1: QKV projection on tf32 mma.sync (round-11, unchanged — known good)
// ---------------------------------------------------------------------------
__global__ __launch_bounds__(256, 2)
void qkv_proj_kernel(const float* __restrict__ Xq, const float* __restrict__ Xk,
                     const float* __restrict__ Xv,
                     const float* __restrict__ Wq, const float* __restrict__ Wk,
                     const float* __restrict__ Wv,
                     const float* __restrict__ bq, const float* __restrict__ bk,
                     const float* __restrict__ bv)
{
    const float* X; const float* W; const float* bias; float* outp;
    if (blockIdx.z == 0)      { X = Xq; W = Wq; bias = bq; outp = g_Q; }
    else if (blockIdx.z == 1) { X = Xk; W = Wk; bias = bk; outp = g_K; }
    else                      { X = Xv; W = Wv; bias = bv; outp = g_V; }

    __shared__ __align__(16) float Xs[2][128 * 20];
    __shared__ __align__(16) float Wt[2][64 * 20];

    const int tid = threadIdx.x;
    const int lane = tid & 31, w = tid >> 5;
    const int wm = w >> 1, wn = w & 1;
    const int grp = lane >> 2, tig = lane & 3;
    const int m0 = blockIdx.y * 128, n0 = blockIdx.x * 64;

    const int xr = tid >> 1, xc = (tid & 1) * 8;
    const int wk = tid & 15, wn4 = (tid >> 4) * 4;

    const unsigned aoff = (unsigned)(((lane & 7) + ((lane >> 3) & 1) * 8) * 80
                                     + (lane >> 4) * 16);
    const unsigned boff = (unsigned)(((((lane >> 4) << 3) + (lane & 7))) * 80
                                     + ((lane >> 3) & 1) * 16);

    float acc[2][4][4];
    #pragma unroll
    for (int mi = 0; mi < 2; mi++)
        #pragma unroll
        for (int ni = 0; ni < 4; ni++)
            #pragma unroll
            for (int c = 0; c < 4; c++) acc[mi][ni][c] = 0.f;

    const float* Xp = X + (size_t)(m0 + xr) * Dm + xc;
    const float* Wp = W + (size_t)wk * Dm + n0 + wn4;

    float4 xa = *(const float4*)Xp;
    float4 xb = *(const float4*)(Xp + 4);
    float4 wv4 = *(const float4*)Wp;

    {
        float* xd = &Xs[0][xr * 20 + xc];
        *(float4*)xd = make_float4(tf32f(xa.x), tf32f(xa.y), tf32f(xa.z), tf32f(xa.w));
        *(float4*)(xd + 4) = make_float4(tf32f(xb.x), tf32f(xb.y), tf32f(xb.z), tf32f(xb.w));
        Wt[0][(wn4 + 0) * 20 + wk] = tf32f(wv4.x);
        Wt[0][(wn4 + 1) * 20 + wk] = tf32f(wv4.y);
        Wt[0][(wn4 + 2) * 20 + wk] = tf32f(wv4.z);
        Wt[0][(wn4 + 3) * 20 + wk] = tf32f(wv4.w);
    }
    __syncthreads();

    for (int t = 0; t < 64; t++) {
        const int cur = t & 1;
        if (t < 63) {
            xa = *(const float4*)(Xp + (t + 1) * 16);
            xb = *(const float4*)(Xp + (t + 1) * 16 + 4);
            wv4 = *(const float4*)(Wp + (size_t)(t + 1) * 16 * Dm);
        }
        const unsigned xbase = smem_u32(&Xs[cur][0]) + (unsigned)(wm * 32 * 80) + aoff;
        const unsigned wbase = smem_u32(&Wt[cur][0]) + (unsigned)(wn * 32 * 80) + boff;
        #pragma unroll
        for (int kk = 0; kk < 2; kk++) {
            unsigned a0[4], a1[4];
            ldsm4(a0[0], a0[1], a0[2], a0[3], xbase + kk * 32);
            ldsm4(a1[0], a1[1], a1[2], a1[3], xbase + 16 * 80 + kk * 32);
            #pragma unroll
            for (int np = 0; np < 2; np++) {
                unsigned b0, b1, b2, b3;
                ldsm4(b0, b1, b2, b3, wbase + np * 16 * 80 + kk * 32);
                mma_tf32(acc[0][2*np][0], acc[0][2*np][1], acc[0][2*np][2], acc[0][2*np][3],
                         a0[0], a0[1], a0[2], a0[3], b0, b1);
                mma_tf32(acc[0][2*np+1][0], acc[0][2*np+1][1], acc[0][2*np+1][2], acc[0][2*np+1][3],
                         a0[0], a0[1], a0[2], a0[3], b2, b3);
                mma_tf32(acc[1][2*np][0], acc[1][2*np][1], acc[1][2*np][2], acc[1][2*np][3],
                         a1[0], a1[1], a1[2], a1[3], b0, b1);
                mma_tf32(acc[1][2*np+1][0], acc[1][2*np+1][1], acc[1][2*np+1][2], acc[1][2*np+1][3],
                         a1[0], a1[1], a1[2], a1[3], b2, b3);
            }
        }
        if (t < 63) {
            const int nxt = cur ^ 1;
            float* xd = &Xs[nxt][xr * 20 + xc];
            *(float4*)xd = make_float4(tf32f(xa.x), tf32f(xa.y), tf32f(xa.z), tf32f(xa.w));
            *(float4*)(xd + 4) = make_float4(tf32f(xb.x), tf32f(xb.y), tf32f(xb.z), tf32f(xb.w));
            Wt[nxt][(wn4 + 0) * 20 + wk] = tf32f(wv4.x);
            Wt[nxt][(wn4 + 1) * 20 + wk] = tf32f(wv4.y);
            Wt[nxt][(wn4 + 2) * 20 + wk] = tf32f(wv4.z);
            Wt[nxt][(wn4 + 3) * 20 + wk] = tf32f(wv4.w);
        }
        __syncthreads();
    }

    const int h = blockIdx.x;
    #pragma unroll
    for (int mi = 0; mi < 2; mi++) {
        const int mlo = m0 + wm * 32 + mi * 16 + grp;
        const int mhi = mlo + 8;
        const int blo = mlo >> 11, slo = mlo & 2047;
        const int bhi = mhi >> 11, shi = mhi & 2047;
        #pragma unroll
        for (int ni = 0; ni < 4; ni++) {
            const int col = wn * 32 + ni * 8 + 2 * tig;
            const float b0v = bias[n0 + col], b1v = bias[n0 + col + 1];
            *(float2*)&outp[((size_t)((blo * Hn + h) * Sq + slo)) * DH + col] =
                make_float2(acc[mi][ni][0] + b0v, acc[mi][ni][1] + b1v);
            *(float2*)&outp[((size_t)((bhi * Hn + h) * Sq + shi)) * DH + col] =
                make_float2(acc[mi][ni][2] + b0v, acc[mi][ni][3] + b1v);
        }
    }
}

// ---------------------------------------------------------------------------
// Kernel 2: flash attention, tf32 mma + ldmatrix, 101 KB smem -> 2 CTAs/SM.
// Ps overlays Qs (Q frags hoisted), K/V single-buffered, pb in bf16.
// ---------------------------------------------------------------------------
#define QS_O 0        // Qs[128][68] tf32 (pre-scaled); becomes Ps after hoist
#define KS_O 8704     // Ks[64][68] natural [j][d]
#define VT_O 13056    // Vt[64][68] transposed [dc][j]
#define MK_O 17408    // maskS[68]
#define PBH_O 17476   // pbh: bf16[128][132] = 8448 floats
#define SMF  25924    // total floats = 103,696 bytes
// relS overlay: fp32 [129][66] at KS_O (fits in Ks+Vt = 8704 floats)

extern __shared__ __align__(16) float sm[];

__global__ __launch_bounds__(256, 2)
void attn_kernel(const float* __restrict__ mask,
                 const float* __restrict__ rel,
                 float* __restrict__ out)
{
    float* Qs = sm + QS_O;       // also Ps after hoist
    float* Ps = sm + QS_O;
    float* Ks = sm + KS_O;
    float* Vt = sm + VT_O;
    float* maskS = sm + MK_O;
    __nv_bfloat16* pbh = (__nv_bfloat16*)(sm + PBH_O);
    float* relS = sm + KS_O;

    const int tid = threadIdx.x;
    const int w = tid >> 5, lane = tid & 31;
    const int grp = lane >> 2, tig = lane & 3;
    const int bh = blockIdx.y, b = bh >> 4, h = bh & 15;
    const int q0 = blockIdx.x * 128;

    const float* Qg = g_Q + (size_t)bh * (Sq * DH);
    const float* Kg = g_K + (size_t)bh * (Sq * DH);
    const float* Vg = g_V + (size_t)bh * (Sq * DH);
    const float* maskb = mask + (size_t)b * Sq;

    // ---- stage Q (tf32, pre-scaled by 1/8) ----
    {
        const int qr = tid & 127, qc = (tid >> 7) * 32;
        #pragma unroll
        for (int u = 0; u < 8; u++) {
            float4 v = *(const float4*)&Qg[(size_t)(q0 + qr) * DH + qc + 4 * u];
            float4 t = make_float4(tf32f(0.125f * v.x), tf32f(0.125f * v.y),
                                   tf32f(0.125f * v.z), tf32f(0.125f * v.w));
            *(float4*)&Qs[qr * 68 + qc + 4 * u] = t;
        }
    }
    // ---- stage rel (fp32, stride 66, overlaid on Ks/Vt) ----
    for (int i = tid; i < NREL * 32; i += 256) {
        int t = i >> 5, dp = i & 31;
        *(float2*)&relS[t * 66 + 2 * dp] = *(const float2*)&rel[t * DH + 2 * dp];
    }
    __syncthreads();

    // ---- pb[r][t] = (q_r/8) . rel_t  (FFMA2, d-packed) -> bf16 table ----
    {
        const int tx = tid & 15, ty = tid >> 4;
        #pragma unroll
        for (int pass = 0; pass < 2; pass++) {
            const int rb = ty * 8 + pass * 4;
            ull pa[4][9];
            #pragma unroll
            for (int i = 0; i < 4; i++)
                #pragma unroll
                for (int tt = 0; tt < 9; tt++) pa[i][tt] = 0ull;
            for (int dp = 0; dp < 32; dp++) {
                ull qv[4];
                #pragma unroll
                for (int i = 0; i < 4; i++)
                    qv[i] = *(const ull*)&Qs[(rb + i) * 68 + 2 * dp];
                #pragma unroll
                for (int tt = 0; tt < 9; tt++) {
                    int t = tx + 16 * tt;
                    if (t < NREL) {
                        ull rv = *(const ull*)&relS[t * 66 + 2 * dp];
                        fma2(pa[0][tt], qv[0], rv);
                        fma2(pa[1][tt], qv[1], rv);
                        fma2(pa[2][tt], qv[2], rv);
                        fma2(pa[3][tt], qv[3], rv);
                    }
                }
            }
            #pragma unroll
            for (int tt = 0; tt < 9; tt++) {
                int t = tx + 16 * tt;
                if (t < NREL) {
                    #pragma unroll
                    for (int i = 0; i < 4; i++) {
                        float2 f = unpack2(pa[i][tt]);
                        pbh[(rb + i) * 132 + t] = __float2bfloat16(f.x + f.y);
                    }
                }
            }
        }
    }
    __syncthreads();   // pb done; relS dead

    // ---- hoist Q a-fragments into registers (Qs becomes Ps after this) ----
    const int rbase = w * 16;
    const int rlo = rbase + grp, rhi = rlo + 8;
    const int rglo = q0 + rlo, rghi = q0 + rhi;
    const unsigned aoff = (unsigned)(((lane & 7) + ((lane >> 3) & 1) * 8) * 272
                                     + (lane >> 4) * 16);
    const unsigned boff = (unsigned)((((lane >> 4) << 3) + (lane & 7)) * 272
                                     + ((lane >> 3) & 1) * 16);
    unsigned qa[8][4];
    {
        const unsigned qbase = smem_u32(Qs) + (unsigned)(rbase * 272) + aoff;
        #pragma unroll
        for (int kk = 0; kk < 8; kk++)
            ldsm4(qa[kk][0], qa[kk][1], qa[kk][2], qa[kk][3], qbase + kk * 32);
    }
    __syncwarp();
    const float pLo_l = __bfloat162float(pbh[rlo * 132]);
    const float pHi_l = __bfloat162float(pbh[rlo * 132 + 128]);
    const float pLo_h = __bfloat162float(pbh[rhi * 132]);
    const float pHi_h = __bfloat162float(pbh[rhi * 132 + 128]);
    const unsigned ksb = smem_u32(Ks) + boff;
    const unsigned vtb = smem_u32(Vt) + boff;
    const unsigned psb = smem_u32(Ps) + (unsigned)(rbase * 272) + aoff;

    const int krow = tid & 63, kd0 = (tid >> 6) * 16;

    float o[8][4];
    #pragma unroll
    for (int n = 0; n < 8; n++)
        #pragma unroll
        for (int c = 0; c < 4; c++) o[n][c] = 0.f;
    float m_lo = -INFINITY, m_hi = -INFINITY, l_lo = 0.f, l_hi = 0.f;

    for (int kt = 0; kt < 32; kt++) {
        const int k0 = kt * 64;
        __syncthreads();   // prev tile fully consumed (and hoist done at kt=0)

        // ---- stage tile: LDG -> cvt -> STS (K natural, V transposed) ----
        {
            const float* Kr = Kg + (size_t)(k0 + krow) * DH + kd0;
            const float* Vr = Vg + (size_t)(k0 + krow) * DH + kd0;
            #pragma unroll
            for (int c = 0; c < 4; c++) {
                float4 kv = *(const float4*)(Kr + 4 * c);
                float4 vv = *(const float4*)(Vr + 4 * c);
                const int d = kd0 + 4 * c;
                *(float4*)&Ks[krow * 68 + d] =
                    make_float4(tf32f(kv.x), tf32f(kv.y), tf32f(kv.z), tf32f(kv.w));
                Vt[(d + 0) * 68 + krow] = tf32f(vv.x);
                Vt[(d + 1) * 68 + krow] = tf32f(vv.y);
                Vt[(d + 2) * 68 + krow] = tf32f(vv.z);
                Vt[(d + 3) * 68 + krow] = tf32f(vv.w);
            }
            if (tid < 16)
                *(float4*)&maskS[tid * 4] = *(const float4*)&maskb[k0 + tid * 4];
        }
        __syncthreads();   // tile staged

        // ---- scores ----
        float sc[8][4];
        #pragma unroll
        for (int n = 0; n < 8; n++)
            #pragma unroll
            for (int c = 0; c < 4; c++) sc[n][c] = 0.f;
        #pragma unroll
        for (int kk = 0; kk < 8; kk++) {
            #pragma unroll
            for (int np = 0; np < 4; np++) {
                unsigned b0, b1, b2, b3;
                ldsm4(b0, b1, b2, b3, ksb + np * 4352 + kk * 32);
                mma_tf32(sc[2*np][0], sc[2*np][1], sc[2*np][2], sc[2*np][3],
                         qa[kk][0], qa[kk][1], qa[kk][2], qa[kk][3], b0, b1);
                mma_tf32(sc[2*np+1][0], sc[2*np+1][1], sc[2*np+1][2], sc[2*np+1][3],
                         qa[kk][0], qa[kk][1], qa[kk][2], qa[kk][3], b2, b3);
            }
        }

        // ---- bias + mask + warp-local online softmax ----
        const int ddmin = k0 - (q0 + 127), ddmax = k0 + 63 - q0;
        const bool gen = (ddmax > -64) && (ddmin < 64);
        const float bC_l = (ddmin >= 64) ? pHi_l : pLo_l;
        const float bC_h = (ddmin >= 64) ? pHi_h : pLo_h;
        float mx_lo = -INFINITY, mx_hi = -INFINITY;
        #pragma unroll
        for (int n = 0; n < 8; n++) {
            const int c0 = n * 8 + 2 * tig;
            float2 mk = *(const float2*)&maskS[c0];
            float b00, b01, b10, b11;
            if (gen) {
                int d0 = k0 + c0 - rglo;
                int t00 = d0     < -64 ? 0 : (d0     > 64 ? 128 : d0 + 64);
                int t01 = d0 + 1 < -64 ? 0 : (d0 + 1 > 64 ? 128 : d0 + 65);
                int d1 = k0 + c0 - rghi;
                int t10 = d1     < -64 ? 0 : (d1     > 64 ? 128 : d1 + 64);
                int t11 = d1 + 1 < -64 ? 0 : (d1 + 1 > 64 ? 128 : d1 + 65);
                b00 = __bfloat162float(pbh[rlo * 132 + t00]);
                b01 = __bfloat162float(pbh[rlo * 132 + t01]);
                b10 = __bfloat162float(pbh[rhi * 132 + t10]);
                b11 = __bfloat162float(pbh[rhi * 132 + t11]);
            } else { b00 = b01 = bC_l; b10 = b11 = bC_h; }
            sc[n][0] = sc[n][0] + b00 + mk.x;
            sc[n][1] = sc[n][1] + b01 + mk.y;
            sc[n][2] = sc[n][2] + b10 + mk.x;
            sc[n][3] = sc[n][3] + b11 + mk.y;
            mx_lo = fmaxf(mx_lo, fmaxf(sc[n][0], sc[n][1]));
            mx_hi = fmaxf(mx_hi, fmaxf(sc[n][2], sc[n][3]));
        }
        mx_lo = fmaxf(mx_lo, __shfl_xor_sync(0xffffffffu, mx_lo, 1, 4));
        mx_lo = fmaxf(mx_lo, __shfl_xor_sync(0xffffffffu, mx_lo, 2, 4));
        mx_hi = fmaxf(mx_hi, __shfl_xor_sync(0xffffffffu, mx_hi, 1, 4));
        mx_hi = fmaxf(mx_hi, __shfl_xor_sync(0xffffffffu, mx_hi, 2, 4));
        const float mn_lo = fmaxf(m_lo, mx_lo), mn_hi = fmaxf(m_hi, mx_hi);
        const float al_lo = __expf(m_lo - mn_lo), al_hi = __expf(m_hi - mn_hi);
        float rs_lo = 0.f, rs_hi = 0.f;
        #pragma unroll
        for (int n = 0; n < 8; n++) {
            sc[n][0] = __expf(sc[n][0] - mn_lo); rs_lo += sc[n][0];
            sc[n][1] = __expf(sc[n][1] - mn_lo); rs_lo += sc[n][1];
            sc[n][2] = __expf(sc[n][2] - mn_hi); rs_hi += sc[n][2];
            sc[n][3] = __expf(sc[n][3] - mn_hi); rs_hi += sc[n][3];
        }
        rs_lo += __shfl_xor_sync(0xffffffffu, rs_lo, 1, 4);
        rs_lo += __shfl_xor_sync(0xffffffffu, rs_lo, 2, 4);
        rs_hi += __shfl_xor_sync(0xffffffffu, rs_hi, 1, 4);
        rs_hi += __shfl_xor_sync(0xffffffffu, rs_hi, 2, 4);
        l_lo = l_lo * al_lo + rs_lo; m_lo = mn_lo;
        l_hi = l_hi * al_hi + rs_hi; m_hi = mn_hi;
        #pragma unroll
        for (int n = 0; n < 8; n++) {
            o[n][0] *= al_lo; o[n][1] *= al_lo;
            o[n][2] *= al_hi; o[n][3] *= al_hi;
        }
        // ---- stage P (tf32) — warp-local rows, warp sync only ----
        __syncwarp();
        #pragma unroll
        for (int n = 0; n < 8; n++) {
            const int c0 = n * 8 + 2 * tig;
            *(float2*)&Ps[rlo * 68 + c0] = make_float2(tf32f(sc[n][0]), tf32f(sc[n][1]));
            *(float2*)&Ps[rhi * 68 + c0] = make_float2(tf32f(sc[n][2]), tf32f(sc[n][3]));
        }
        __syncwarp();

        // ---- O += P V ----
        #pragma unroll
        for (int jj = 0; jj < 8; jj++) {
            unsigned pa0, pa1, pa2, pa3;
            ldsm4(pa0, pa1, pa2, pa3, psb + jj * 32);
            #pragma unroll
            for (int np = 0; np < 4; np++) {
                unsigned b0, b1, b2, b3;
                ldsm4(b0, b1, b2, b3, vtb + np * 4352 + jj * 32);
                mma_tf32(o[2*np][0], o[2*np][1], o[2*np][2], o[2*np][3],
                         pa0, pa1, pa2, pa3, b0, b1);
                mma_tf32(o[2*np+1][0], o[2*np+1][1], o[2*np+1][2], o[2*np+1][3],
                         pa0, pa1, pa2, pa3, b2, b3);
            }
        }
    }

    // ---- epilogue ----
    const float inv_lo = 1.f / l_lo, inv_hi = 1.f / l_hi;
    #pragma unroll
    for (int n = 0; n < 8; n++) {
        const int col = h * DH + n * 8 + 2 * tig;
        *(float2*)&out[((size_t)(b * Sq + rglo)) * Dm + col] =
            make_float2(o[n][0] * inv_lo, o[n][1] * inv_lo);
        *(float2*)&out[((size_t)(b * Sq + rghi)) * Dm + col] =
            make_float2(o[n][2] * inv_hi, o[n][3] * inv_hi);
    }
}

extern "C" void kernel_launch(void* const* d_in, const int* in_sizes, int n_in,
                              void* d_out, int out_size)
{
    const float* query = (const float*)d_in[0];
    const float* key   = (const float*)d_in[1];
    const float* value = (const float*)d_in[2];
    const float* mask  = (const float*)d_in[3];
    const float* Wq    = (const float*)d_in[4];
    const float* bq    = (const float*)d_in[5];
    const float* Wk    = (const float*)d_in[6];
    const float* bk    = (const float*)d_in[7];
    const float* Wv    = (const float*)d_in[8];
    const float* bv    = (const float*)d_in[9];
    const float* rel   = (const float*)d_in[10];
    float* out = (float*)d_out;
    (void)in_sizes; (void)n_in; (void)out_size;

    const int ATTN_SMEM = SMF * (int)sizeof(float);
    cudaFuncSetAttribute(attn_kernel,
                         cudaFuncAttributeMaxDynamicSharedMemorySize, ATTN_SMEM);

    dim3 gemm_grid(Dm / 64, (Bz * Sq) / 128, 3);
    qkv_proj_kernel<<<gemm_grid, 256>>>(query, key, value, Wq, Wk, Wv, bq, bk, bv);

    dim3 attn_grid(Sq / 128, Bz * Hn);
    attn_kernel<<<attn_grid, 256, ATTN_SMEM>>>(mask, rel, out);
}

// round 13
// speedup vs baseline: 1.6361x; 1.2365x over previous
#include <cuda_runtime.h>
#include <cuda_bf16.h>
#include <cuda_fp16.h>
#include <math.h>

#define Bz 2
#define Sq 2048
#define Dm 1024
#define Hn 16
#define DH 64
#define NREL 129
#define BHN (Bz*Hn)

typedef unsigned long long ull;

__device__ float g_Q[BHN * Sq * DH];
__device__ float g_K[BHN * Sq * DH];
__device__ float g_V[BHN * Sq * DH];

__device__ __forceinline__ ull pack2(float lo, float hi) {
    ull r; asm("mov.b64 %0, {%1, %2};" : "=l"(r) : "f"(lo), "f"(hi)); return r;
}
__device__ __forceinline__ float2 unpack2(ull v) {
    float2 r; asm("mov.b64 {%0, %1}, %2;" : "=f"(r.x), "=f"(r.y) : "l"(v)); return r;
}
__device__ __forceinline__ void fma2(ull& a, ull x, ull y) {
    asm("fma.rn.f32x2 %0, %1, %2, %0;" : "+l"(a) : "l"(x), "l"(y));
}
__device__ __forceinline__ unsigned tf32u(float f) {
    unsigned r; asm("cvt.rna.tf32.f32 %0, %1;" : "=r"(r) : "f"(f)); return r;
}
__device__ __forceinline__ float tf32f(float f) { return __uint_as_float(tf32u(f)); }
__device__ __forceinline__ void mma_tf32(float& c0, float& c1, float& c2, float& c3,
                                         unsigned a0, unsigned a1, unsigned a2, unsigned a3,
                                         unsigned b0, unsigned b1) {
    asm("mma.sync.aligned.m16n8k8.row.col.f32.tf32.tf32.f32 "
        "{%0,%1,%2,%3}, {%4,%5,%6,%7}, {%8,%9}, {%0,%1,%2,%3};"
        : "+f"(c0), "+f"(c1), "+f"(c2), "+f"(c3)
        : "r"(a0), "r"(a1), "r"(a2), "r"(a3), "r"(b0), "r"(b1));
}
__device__ __forceinline__ void mma_f16(float& c0, float& c1, float& c2, float& c3,
                                        unsigned a0, unsigned a1, unsigned a2, unsigned a3,
                                        unsigned b0, unsigned b1) {
    asm("mma.sync.aligned.m16n8k16.row.col.f32.f16.f16.f32 "
        "{%0,%1,%2,%3}, {%4,%5,%6,%7}, {%8,%9}, {%0,%1,%2,%3};"
        : "+f"(c0), "+f"(c1), "+f"(c2), "+f"(c3)
        : "r"(a0), "r"(a1), "r"(a2), "r"(a3), "r"(b0), "r"(b1));
}
__device__ __forceinline__ void ldsm4(unsigned& r0, unsigned& r1, unsigned& r2, unsigned& r3,
                                      unsigned addr) {
    asm volatile("ldmatrix.sync.aligned.m8n8.x4.shared.b16 {%0,%1,%2,%3}, [%4];"
        : "=r"(r0), "=r"(r1), "=r"(r2), "=r"(r3) : "r"(addr));
}
__device__ __forceinline__ void ldsm4t(unsigned& r0, unsigned& r1, unsigned& r2, unsigned& r3,
                                       unsigned addr) {
    asm volatile("ldmatrix.sync.aligned.m8n8.x4.trans.shared.b16 {%0,%1,%2,%3}, [%4];"
        : "=r"(r0), "=r"(r1), "=r"(r2), "=r"(r3) : "r"(addr));
}
__device__ __forceinline__ unsigned smem_u32(const void* p) {
    return (unsigned)__cvta_generic_to_shared(p);
}
__device__ __forceinline__ unsigned h2u(float a, float b) {
    __half2 h = __floats2half2_rn(a, b);
    return *(unsigned*)&h;
}

// ---------------------------------------------------------------------------
// Kernel 1: QKV projection on tf32 mma.sync (round-11, unchanged — known good)
// ---------------------------------------------------------------------------
__global__ __launch_bounds__(256, 2)
void qkv_proj_kernel(const float* __restrict__ Xq, const float* __restrict__ Xk,
                     const float* __restrict__ Xv,
                     const float* __restrict__ Wq, const float* __restrict__ Wk,
                     const float* __restrict__ Wv,
                     const float* __restrict__ bq, const float* __restrict__ bk,
                     const float* __restrict__ bv)
{
    const float* X; const float* W; const float* bias; float* outp;
    if (blockIdx.z == 0)      { X = Xq; W = Wq; bias = bq; outp = g_Q; }
    else if (blockIdx.z == 1) { X = Xk; W = Wk; bias = bk; outp = g_K; }
    else                      { X = Xv; W = Wv; bias = bv; outp = g_V; }

    __shared__ __align__(16) float Xs[2][128 * 20];
    __shared__ __align__(16) float Wt[2][64 * 20];

    const int tid = threadIdx.x;
    const int lane = tid & 31, w = tid >> 5;
    const int wm = w >> 1, wn = w & 1;
    const int grp = lane >> 2, tig = lane & 3;
    const int m0 = blockIdx.y * 128, n0 = blockIdx.x * 64;

    const int xr = tid >> 1, xc = (tid & 1) * 8;
    const int wk = tid & 15, wn4 = (tid >> 4) * 4;

    const unsigned aoff = (unsigned)(((lane & 7) + ((lane >> 3) & 1) * 8) * 80
                                     + (lane >> 4) * 16);
    const unsigned boff = (unsigned)(((((lane >> 4) << 3) + (lane & 7))) * 80
                                     + ((lane >> 3) & 1) * 16);

    float acc[2][4][4];
    #pragma unroll
    for (int mi = 0; mi < 2; mi++)
        #pragma unroll
        for (int ni = 0; ni < 4; ni++)
            #pragma unroll
            for (int c = 0; c < 4; c++) acc[mi][ni][c] = 0.f;

    const float* Xp = X + (size_t)(m0 + xr) * Dm + xc;
    const float* Wp = W + (size_t)wk * Dm + n0 + wn4;

    float4 xa = *(const float4*)Xp;
    float4 xb = *(const float4*)(Xp + 4);
    float4 wv4 = *(const float4*)Wp;

    {
        float* xd = &Xs[0][xr * 20 + xc];
        *(float4*)xd = make_float4(tf32f(xa.x), tf32f(xa.y), tf32f(xa.z), tf32f(xa.w));
        *(float4*)(xd + 4) = make_float4(tf32f(xb.x), tf32f(xb.y), tf32f(xb.z), tf32f(xb.w));
        Wt[0][(wn4 + 0) * 20 + wk] = tf32f(wv4.x);
        Wt[0][(wn4 + 1) * 20 + wk] = tf32f(wv4.y);
        Wt[0][(wn4 + 2) * 20 + wk] = tf32f(wv4.z);
        Wt[0][(wn4 + 3) * 20 + wk] = tf32f(wv4.w);
    }
    __syncthreads();

    for (int t = 0; t < 64; t++) {
        const int cur = t & 1;
        if (t < 63) {
            xa = *(const float4*)(Xp + (t + 1) * 16);
            xb = *(const float4*)(Xp + (t + 1) * 16 + 4);
            wv4 = *(const float4*)(Wp + (size_t)(t + 1) * 16 * Dm);
        }
        const unsigned xbase = smem_u32(&Xs[cur][0]) + (unsigned)(wm * 32 * 80) + aoff;
        const unsigned wbase = smem_u32(&Wt[cur][0]) + (unsigned)(wn * 32 * 80) + boff;
        #pragma unroll
        for (int kk = 0; kk < 2; kk++) {
            unsigned a0[4], a1[4];
            ldsm4(a0[0], a0[1], a0[2], a0[3], xbase + kk * 32);
            ldsm4(a1[0], a1[1], a1[2], a1[3], xbase + 16 * 80 + kk * 32);
            #pragma unroll
            for (int np = 0; np < 2; np++) {
                unsigned b0, b1, b2, b3;
                ldsm4(b0, b1, b2, b3, wbase + np * 16 * 80 + kk * 32);
                mma_tf32(acc[0][2*np][0], acc[0][2*np][1], acc[0][2*np][2], acc[0][2*np][3],
                         a0[0], a0[1], a0[2], a0[3], b0, b1);
                mma_tf32(acc[0][2*np+1][0], acc[0][2*np+1][1], acc[0][2*np+1][2], acc[0][2*np+1][3],
                         a0[0], a0[1], a0[2], a0[3], b2, b3);
                mma_tf32(acc[1][2*np][0], acc[1][2*np][1], acc[1][2*np][2], acc[1][2*np][3],
                         a1[0], a1[1], a1[2], a1[3], b0, b1);
                mma_tf32(acc[1][2*np+1][0], acc[1][2*np+1][1], acc[1][2*np+1][2], acc[1][2*np+1][3],
                         a1[0], a1[1], a1[2], a1[3], b2, b3);
            }
        }
        if (t < 63) {
            const int nxt = cur ^ 1;
            float* xd = &Xs[nxt][xr * 20 + xc];
            *(float4*)xd = make_float4(tf32f(xa.x), tf32f(xa.y), tf32f(xa.z), tf32f(xa.w));
            *(float4*)(xd + 4) = make_float4(tf32f(xb.x), tf32f(xb.y), tf32f(xb.z), tf32f(xb.w));
            Wt[nxt][(wn4 + 0) * 20 + wk] = tf32f(wv4.x);
            Wt[nxt][(wn4 + 1) * 20 + wk] = tf32f(wv4.y);
            Wt[nxt][(wn4 + 2) * 20 + wk] = tf32f(wv4.z);
            Wt[nxt][(wn4 + 3) * 20 + wk] = tf32f(wv4.w);
        }
        __syncthreads();
    }

    const int h = blockIdx.x;
    #pragma unroll
    for (int mi = 0; mi < 2; mi++) {
        const int mlo = m0 + wm * 32 + mi * 16 + grp;
        const int mhi = mlo + 8;
        const int blo = mlo >> 11, slo = mlo & 2047;
        const int bhi = mhi >> 11, shi = mhi & 2047;
        #pragma unroll
        for (int ni = 0; ni < 4; ni++) {
            const int col = wn * 32 + ni * 8 + 2 * tig;
            const float b0v = bias[n0 + col], b1v = bias[n0 + col + 1];
            *(float2*)&outp[((size_t)((blo * Hn + h) * Sq + slo)) * DH + col] =
                make_float2(acc[mi][ni][0] + b0v, acc[mi][ni][1] + b1v);
            *(float2*)&outp[((size_t)((bhi * Hn + h) * Sq + shi)) * DH + col] =
                make_float2(acc[mi][ni][2] + b0v, acc[mi][ni][3] + b1v);
        }
    }
}

// ---------------------------------------------------------------------------
// Kernel 2: flash attention on fp16 mma (m16n8k16). 89 KB smem, 2 CTAs/SM,
// K/V double-buffered (reg prefetch), V natural + ldmatrix.trans, 1 sync/tile.
// ---------------------------------------------------------------------------
#define QS_O 0        // Qh fp16 [128][72] (pre-scaled 1/8); Ps overlay after hoist
#define KS_O 4608     // Kh fp16 [2][64][72] natural [j][d]
#define VS_O 9216     // Vh fp16 [2][64][72] natural [j][dc]
#define MK_O 13824    // maskS[2][68] fp32
#define PBH_O 13960   // pbh bf16[128][132]
#define SMF  22408
// relS overlay fp32 [129][66] at KS_O (Kh+Vh region, pre-loop only)

extern __shared__ __align__(16) float sm[];

__global__ __launch_bounds__(256, 2)
void attn_kernel(const float* __restrict__ mask,
                 const float* __restrict__ rel,
                 float* __restrict__ out)
{
    __half* Qh = (__half*)(sm + QS_O);     // also Ps after hoist
    __half* Kh = (__half*)(sm + KS_O);
    __half* Vh = (__half*)(sm + VS_O);
    float* maskS = sm + MK_O;
    __nv_bfloat16* pbh = (__nv_bfloat16*)(sm + PBH_O);
    float* relS = sm + KS_O;

    const int tid = threadIdx.x;
    const int w = tid >> 5, lane = tid & 31;
    const int grp = lane >> 2, tig = lane & 3;
    const int bh = blockIdx.y, b = bh >> 4, h = bh & 15;
    const int q0 = blockIdx.x * 128;

    const float* Qg = g_Q + (size_t)bh * (Sq * DH);
    const float* Kg = g_K + (size_t)bh * (Sq * DH);
    const float* Vg = g_V + (size_t)bh * (Sq * DH);
    const float* maskb = mask + (size_t)b * Sq;

    // ---- stage Q (fp16, pre-scaled 1/8), stride 72 halves ----
    {
        const int qr = tid & 127, qc = (tid >> 7) * 32;
        #pragma unroll
        for (int u = 0; u < 4; u++) {
            float4 v0 = *(const float4*)&Qg[(size_t)(q0 + qr) * DH + qc + 8 * u];
            float4 v1 = *(const float4*)&Qg[(size_t)(q0 + qr) * DH + qc + 8 * u + 4];
            uint4 pk;
            pk.x = h2u(0.125f * v0.x, 0.125f * v0.y);
            pk.y = h2u(0.125f * v0.z, 0.125f * v0.w);
            pk.z = h2u(0.125f * v1.x, 0.125f * v1.y);
            pk.w = h2u(0.125f * v1.z, 0.125f * v1.w);
            *(uint4*)&Qh[qr * 72 + qc + 8 * u] = pk;
        }
    }
    // ---- stage rel (fp32 stride 66, overlaid on Kh/Vh) ----
    for (int i = tid; i < NREL * 32; i += 256) {
        int t = i >> 5, dp = i & 31;
        *(float2*)&relS[t * 66 + 2 * dp] = *(const float2*)&rel[t * DH + 2 * dp];
    }
    __syncthreads();

    // ---- pb[r][t] = (q_r/8) . rel_t  (fp32 accum via FFMA2) -> bf16 table ----
    {
        const int tx = tid & 15, ty = tid >> 4;
        #pragma unroll
        for (int pass = 0; pass < 2; pass++) {
            const int rb = ty * 8 + pass * 4;
            ull pa[4][9];
            #pragma unroll
            for (int i = 0; i < 4; i++)
                #pragma unroll
                for (int tt = 0; tt < 9; tt++) pa[i][tt] = 0ull;
            for (int dp = 0; dp < 32; dp++) {
                ull qv[4];
                #pragma unroll
                for (int i = 0; i < 4; i++) {
                    __half2 qh = *(const __half2*)&Qh[(rb + i) * 72 + 2 * dp];
                    float2 qf = __half22float2(qh);
                    qv[i] = pack2(qf.x, qf.y);
                }
                #pragma unroll
                for (int tt = 0; tt < 9; tt++) {
                    int t = tx + 16 * tt;
                    if (t < NREL) {
                        ull rv = *(const ull*)&relS[t * 66 + 2 * dp];
                        fma2(pa[0][tt], qv[0], rv);
                        fma2(pa[1][tt], qv[1], rv);
                        fma2(pa[2][tt], qv[2], rv);
                        fma2(pa[3][tt], qv[3], rv);
                    }
                }
            }
            #pragma unroll
            for (int tt = 0; tt < 9; tt++) {
                int t = tx + 16 * tt;
                if (t < NREL) {
                    #pragma unroll
                    for (int i = 0; i < 4; i++) {
                        float2 f = unpack2(pa[i][tt]);
                        pbh[(rb + i) * 132 + t] = __float2bfloat16(f.x + f.y);
                    }
                }
            }
        }
    }
    __syncthreads();   // pb done; relS (Kh/Vh region) free

    // ---- hoist Q a-fragments (fp16, m16n8k16): 4 ldsm.x4 ----
    const int rbase = w * 16;
    const int rlo = rbase + grp, rhi = rlo + 8;
    const int rglo = q0 + rlo, rghi = q0 + rhi;
    // a-frag: row = lane&15, col-chunk = lane>>4 (16B)
    const unsigned aoffH = (unsigned)((lane & 15) * 144 + (lane >> 4) * 16);
    // K b-frag (non-trans): row j = ((lane>>4)<<3)+(lane&7), d-chunk = (lane>>3)&1
    const unsigned boffK = (unsigned)(((((lane >> 4) << 3) + (lane & 7))) * 144
                                      + ((lane >> 3) & 1) * 16);
    // V b-frag (trans): row j = ((lane>>3)&1)*8+(lane&7), dc-chunk = lane>>4
    const unsigned boffV = (unsigned)((((lane & 7) + ((lane >> 3) & 1) * 8)) * 144
                                      + (lane >> 4) * 16);
    unsigned qa[4][4];
    {
        const unsigned qbase = smem_u32(Qh) + (unsigned)(rbase * 144) + aoffH;
        #pragma unroll
        for (int kk = 0; kk < 4; kk++)
            ldsm4(qa[kk][0], qa[kk][1], qa[kk][2], qa[kk][3], qbase + kk * 32);
    }
    __syncwarp();
    const float pLo_l = __bfloat162float(pbh[rlo * 132]);
    const float pHi_l = __bfloat162float(pbh[rlo * 132 + 128]);
    const float pLo_h = __bfloat162float(pbh[rhi * 132]);
    const float pHi_h = __bfloat162float(pbh[rhi * 132 + 128]);
    const unsigned ksb = smem_u32(Kh) + boffK;
    const unsigned vsb = smem_u32(Vh) + boffV;
    const unsigned psb = smem_u32(Qh) + (unsigned)(rbase * 144) + aoffH;

    // ---- prologue: LDG tile 0 into packed-half registers ----
    const int krow = tid & 63, kd0 = (tid >> 6) * 16;
    uint4 krh[2], vrh[2];
    float4 mv;
    {
        const float* Kr = Kg + (size_t)krow * DH + kd0;
        const float* Vr = Vg + (size_t)krow * DH + kd0;
        #pragma unroll
        for (int c = 0; c < 2; c++) {
            float4 f0 = *(const float4*)(Kr + 8 * c);
            float4 f1 = *(const float4*)(Kr + 8 * c + 4);
            krh[c] = make_uint4(h2u(f0.x, f0.y), h2u(f0.z, f0.w),
                                h2u(f1.x, f1.y), h2u(f1.z, f1.w));
            f0 = *(const float4*)(Vr + 8 * c);
            f1 = *(const float4*)(Vr + 8 * c + 4);
            vrh[c] = make_uint4(h2u(f0.x, f0.y), h2u(f0.z, f0.w),
                                h2u(f1.x, f1.y), h2u(f1.z, f1.w));
        }
        if (tid < 16) mv = *(const float4*)&maskb[tid * 4];
    }

    float o[8][4];
    #pragma unroll
    for (int n = 0; n < 8; n++)
        #pragma unroll
        for (int c = 0; c < 4; c++) o[n][c] = 0.f;
    float m_lo = -INFINITY, m_hi = -INFINITY, l_lo = 0.f, l_hi = 0.f;

    for (int kt = 0; kt < 32; kt++) {
        const int buf = kt & 1;
        const int k0 = kt * 64;

        // ---- stage tile kt from registers ----
        {
            __half* Kd = Kh + buf * 4608;
            __half* Vd = Vh + buf * 4608;
            #pragma unroll
            for (int c = 0; c < 2; c++) {
                *(uint4*)&Kd[krow * 72 + kd0 + 8 * c] = krh[c];
                *(uint4*)&Vd[krow * 72 + kd0 + 8 * c] = vrh[c];
            }
            if (tid < 16) *(float4*)&maskS[buf * 68 + tid * 4] = mv;
        }
        // ---- prefetch tile kt+1 ----
        if (kt < 31) {
            const float* Kr = Kg + (size_t)(k0 + 64 + krow) * DH + kd0;
            const float* Vr = Vg + (size_t)(k0 + 64 + krow) * DH + kd0;
            #pragma unroll
            for (int c = 0; c < 2; c++) {
                float4 f0 = *(const float4*)(Kr + 8 * c);
                float4 f1 = *(const float4*)(Kr + 8 * c + 4);
                krh[c] = make_uint4(h2u(f0.x, f0.y), h2u(f0.z, f0.w),
                                    h2u(f1.x, f1.y), h2u(f1.z, f1.w));
                f0 = *(const float4*)(Vr + 8 * c);
                f1 = *(const float4*)(Vr + 8 * c + 4);
                vrh[c] = make_uint4(h2u(f0.x, f0.y), h2u(f0.z, f0.w),
                                    h2u(f1.x, f1.y), h2u(f1.z, f1.w));
            }
            if (tid < 16) mv = *(const float4*)&maskb[k0 + 64 + tid * 4];
        }
        __syncthreads();   // tile kt staged everywhere

        // ---- scores: S = Q K^T (fp16 mma, 16 ldsm + 32 mma) ----
        float sc[8][4];
        #pragma unroll
        for (int n = 0; n < 8; n++)
            #pragma unroll
            for (int c = 0; c < 4; c++) sc[n][c] = 0.f;
        const unsigned kbuf = ksb + (unsigned)(buf * 9216);
        #pragma unroll
        for (int kk = 0; kk < 4; kk++) {
            #pragma unroll
            for (int np = 0; np < 4; np++) {
                unsigned b0, b1, b2, b3;
                ldsm4(b0, b1, b2, b3, kbuf + np * 2304 + kk * 32);
                mma_f16(sc[2*np][0], sc[2*np][1], sc[2*np][2], sc[2*np][3],
                        qa[kk][0], qa[kk][1], qa[kk][2], qa[kk][3], b0, b1);
                mma_f16(sc[2*np+1][0], sc[2*np+1][1], sc[2*np+1][2], sc[2*np+1][3],
                        qa[kk][0], qa[kk][1], qa[kk][2], qa[kk][3], b2, b3);
            }
        }

        // ---- bias + mask + warp-local online softmax ----
        const float* mk = maskS + buf * 68;
        const int ddmin = k0 - (q0 + 127), ddmax = k0 + 63 - q0;
        const bool gen = (ddmax > -64) && (ddmin < 64);
        const float bC_l = (ddmin >= 64) ? pHi_l : pLo_l;
        const float bC_h = (ddmin >= 64) ? pHi_h : pLo_h;
        float mx_lo = -INFINITY, mx_hi = -INFINITY;
        #pragma unroll
        for (int n = 0; n < 8; n++) {
            const int c0 = n * 8 + 2 * tig;
            float2 mk2 = *(const float2*)&mk[c0];
            float b00, b01, b10, b11;
            if (gen) {
                int d0 = k0 + c0 - rglo;
                int t00 = d0     < -64 ? 0 : (d0     > 64 ? 128 : d0 + 64);
                int t01 = d0 + 1 < -64 ? 0 : (d0 + 1 > 64 ? 128 : d0 + 65);
                int d1 = k0 + c0 - rghi;
                int t10 = d1     < -64 ? 0 : (d1     > 64 ? 128 : d1 + 64);
                int t11 = d1 + 1 < -64 ? 0 : (d1 + 1 > 64 ? 128 : d1 + 65);
                b00 = __bfloat162float(pbh[rlo * 132 + t00]);
                b01 = __bfloat162float(pbh[rlo * 132 + t01]);
                b10 = __bfloat162float(pbh[rhi * 132 + t10]);
                b11 = __bfloat162float(pbh[rhi * 132 + t11]);
            } else { b00 = b01 = bC_l; b10 = b11 = bC_h; }
            sc[n][0] = sc[n][0] + b00 + mk2.x;
            sc[n][1] = sc[n][1] + b01 + mk2.y;
            sc[n][2] = sc[n][2] + b10 + mk2.x;
            sc[n][3] = sc[n][3] + b11 + mk2.y;
            mx_lo = fmaxf(mx_lo, fmaxf(sc[n][0], sc[n][1]));
            mx_hi = fmaxf(mx_hi, fmaxf(sc[n][2], sc[n][3]));
        }
        mx_lo = fmaxf(mx_lo, __shfl_xor_sync(0xffffffffu, mx_lo, 1, 4));
        mx_lo = fmaxf(mx_lo, __shfl_xor_sync(0xffffffffu, mx_lo, 2, 4));
        mx_hi = fmaxf(mx_hi, __shfl_xor_sync(0xffffffffu, mx_hi, 1, 4));
        mx_hi = fmaxf(mx_hi, __shfl_xor_sync(0xffffffffu, mx_hi, 2, 4));
        const float mn_lo = fmaxf(m_lo, mx_lo), mn_hi = fmaxf(m_hi, mx_hi);
        const float al_lo = __expf(m_lo - mn_lo), al_hi = __expf(m_hi - mn_hi);
        float rs_lo = 0.f, rs_hi = 0.f;
        #pragma unroll
        for (int n = 0; n < 8; n++) {
            sc[n][0] = __expf(sc[n][0] - mn_lo); rs_lo += sc[n][0];
            sc[n][1] = __expf(sc[n][1] - mn_lo); rs_lo += sc[n][1];
            sc[n][2] = __expf(sc[n][2] - mn_hi); rs_hi += sc[n][2];
            sc[n][3] = __expf(sc[n][3] - mn_hi); rs_hi += sc[n][3];
        }
        rs_lo += __shfl_xor_sync(0xffffffffu, rs_lo, 1, 4);
        rs_lo += __shfl_xor_sync(0xffffffffu, rs_lo, 2, 4);
        rs_hi += __shfl_xor_sync(0xffffffffu, rs_hi, 1, 4);
        rs_hi += __shfl_xor_sync(0xffffffffu, rs_hi, 2, 4);
        l_lo = l_lo * al_lo + rs_lo; m_lo = mn_lo;
        l_hi = l_hi * al_hi + rs_hi; m_hi = mn_hi;
        #pragma unroll
        for (int n = 0; n < 8; n++) {
            o[n][0] *= al_lo; o[n][1] *= al_lo;
            o[n][2] *= al_hi; o[n][3] *= al_hi;
        }
        // ---- stage P (fp16, warp-local rows) ----
        __syncwarp();
        #pragma unroll
        for (int n = 0; n < 8; n++) {
            const int c0 = n * 8 + 2 * tig;
            *(unsigned*)&Qh[rlo * 72 + c0] = h2u(sc[n][0], sc[n][1]);
            *(unsigned*)&Qh[rhi * 72 + c0] = h2u(sc[n][2], sc[n][3]);
        }
        __syncwarp();

        // ---- O += P V (V natural + ldmatrix.trans) ----
        const unsigned vbuf = vsb + (unsigned)(buf * 9216);
        #pragma unroll
        for (int jj = 0; jj < 4; jj++) {
            unsigned pa0, pa1, pa2, pa3;
            ldsm4(pa0, pa1, pa2, pa3, psb + jj * 32);
            #pragma unroll
            for (int np = 0; np < 4; np++) {
                unsigned b0, b1, b2, b3;
                ldsm4t(b0, b1, b2, b3, vbuf + jj * 2304 + np * 32);
                mma_f16(o[2*np][0], o[2*np][1], o[2*np][2], o[2*np][3],
                        pa0, pa1, pa2, pa3, b0, b1);
                mma_f16(o[2*np+1][0], o[2*np+1][1], o[2*np+1][2], o[2*np+1][3],
                        pa0, pa1, pa2, pa3, b2, b3);
            }
        }
    }

    // ---- epilogue ----
    const float inv_lo = 1.f / l_lo, inv_hi = 1.f / l_hi;
    #pragma unroll
    for (int n = 0; n < 8; n++) {
        const int col = h * DH + n * 8 + 2 * tig;
        *(float2*)&out[((size_t)(b * Sq + rglo)) * Dm + col] =
            make_float2(o[n][0] * inv_lo, o[n][1] * inv_lo);
        *(float2*)&out[((size_t)(b * Sq + rghi)) * Dm + col] =
            make_float2(o[n][2] * inv_hi, o[n][3] * inv_hi);
    }
}

extern "C" void kernel_launch(void* const* d_in, const int* in_sizes, int n_in,
                              void* d_out, int out_size)
{
    const float* query = (const float*)d_in[0];
    const float* key   = (const float*)d_in[1];
    const float* value = (const float*)d_in[2];
    const float* mask  = (const float*)d_in[3];
    const float* Wq    = (const float*)d_in[4];
    const float* bq    = (const float*)d_in[5];
    const float* Wk    = (const float*)d_in[6];
    const float* bk    = (const float*)d_in[7];
    const float* Wv    = (const float*)d_in[8];
    const float* bv    = (const float*)d_in[9];
    const float* rel   = (const float*)d_in[10];
    float* out = (float*)d_out;
    (void)in_sizes; (void)n_in; (void)out_size;

    const int ATTN_SMEM = SMF * (int)sizeof(float);
    cudaFuncSetAttribute(attn_kernel,
                         cudaFuncAttributeMaxDynamicSharedMemorySize, ATTN_SMEM);

    dim3 gemm_grid(Dm / 64, (Bz * Sq) / 128, 3);
    qkv_proj_kernel<<<gemm_grid, 256>>>(query, key, value, Wq, Wk, Wv, bq, bk, bv);

    dim3 attn_grid(Sq / 128, Bz * Hn);
    attn_kernel<<<attn_grid, 256, ATTN_SMEM>>>(mask, rel, out);
}

// round 14
// speedup vs baseline: 2.0691x; 1.2647x over previous
#include <cuda_runtime.h>
#include <cuda_bf16.h>
#include <cuda_fp16.h>
#include <math.h>

#define Bz 2
#define Sq 2048
#define Dm 1024
#define Hn 16
#define DH 64
#define NREL 129
#define BHN (Bz*Hn)

typedef unsigned long long ull;

__device__ float g_Q[BHN * Sq * DH];
__device__ float g_K[BHN * Sq * DH];
__device__ float g_V[BHN * Sq * DH];

__device__ __forceinline__ ull pack2(float lo, float hi) {
    ull r; asm("mov.b64 %0, {%1, %2};" : "=l"(r) : "f"(lo), "f"(hi)); return r;
}
__device__ __forceinline__ float2 unpack2(ull v) {
    float2 r; asm("mov.b64 {%0, %1}, %2;" : "=f"(r.x), "=f"(r.y) : "l"(v)); return r;
}
__device__ __forceinline__ void fma2(ull& a, ull x, ull y) {
    asm("fma.rn.f32x2 %0, %1, %2, %0;" : "+l"(a) : "l"(x), "l"(y));
}
__device__ __forceinline__ void mma_f16(float& c0, float& c1, float& c2, float& c3,
                                        unsigned a0, unsigned a1, unsigned a2, unsigned a3,
                                        unsigned b0, unsigned b1) {
    asm("mma.sync.aligned.m16n8k16.row.col.f32.f16.f16.f32 "
        "{%0,%1,%2,%3}, {%4,%5,%6,%7}, {%8,%9}, {%0,%1,%2,%3};"
        : "+f"(c0), "+f"(c1), "+f"(c2), "+f"(c3)
        : "r"(a0), "r"(a1), "r"(a2), "r"(a3), "r"(b0), "r"(b1));
}
__device__ __forceinline__ void ldsm4(unsigned& r0, unsigned& r1, unsigned& r2, unsigned& r3,
                                      unsigned addr) {
    asm volatile("ldmatrix.sync.aligned.m8n8.x4.shared.b16 {%0,%1,%2,%3}, [%4];"
        : "=r"(r0), "=r"(r1), "=r"(r2), "=r"(r3) : "r"(addr));
}
__device__ __forceinline__ void ldsm4t(unsigned& r0, unsigned& r1, unsigned& r2, unsigned& r3,
                                       unsigned addr) {
    asm volatile("ldmatrix.sync.aligned.m8n8.x4.trans.shared.b16 {%0,%1,%2,%3}, [%4];"
        : "=r"(r0), "=r"(r1), "=r"(r2), "=r"(r3) : "r"(addr));
}
__device__ __forceinline__ unsigned smem_u32(const void* p) {
    return (unsigned)__cvta_generic_to_shared(p);
}
__device__ __forceinline__ unsigned h2u(float a, float b) {
    __half2 h = __floats2half2_rn(a, b);
    return *(unsigned*)&h;
}

// ---------------------------------------------------------------------------
// Kernel 1: QKV projection on fp16 mma (m16n8k16). 128x64 tile, k-step 32,
// 32 iters, 8 warps (4m x 2n), W natural + ldmatrix.trans, 2 CTAs/SM.
// grid (16, 32, 3).
// ---------------------------------------------------------------------------
__global__ __launch_bounds__(256, 2)
void qkv_proj_kernel(const float* __restrict__ Xq, const float* __restrict__ Xk,
                     const float* __restrict__ Xv,
                     const float* __restrict__ Wq, const float* __restrict__ Wk,
                     const float* __restrict__ Wv,
                     const float* __restrict__ bq, const float* __restrict__ bk,
                     const float* __restrict__ bv)
{
    const float* X; const float* W; const float* bias; float* outp;
    if (blockIdx.z == 0)      { X = Xq; W = Wq; bias = bq; outp = g_Q; }
    else if (blockIdx.z == 1) { X = Xk; W = Wk; bias = bk; outp = g_V; }
    else                      { X = Xv; W = Wv; bias = bv; outp = g_V; }
    // NOTE: fix aliasing above — set properly below (avoid accidental overwrite)
    if (blockIdx.z == 0)      { outp = g_Q; }
    else if (blockIdx.z == 1) { outp = g_K; }
    else                      { outp = g_V; }

    __shared__ __align__(16) __half Xh[2][128 * 40];   // [m][k] natural, 80B rows
    __shared__ __align__(16) __half Wh[2][32 * 72];    // [k][n] natural, 144B rows

    const int tid = threadIdx.x;
    const int lane = tid & 31, w = tid >> 5;
    const int wm = w >> 1, wn = w & 1;
    const int grp = lane >> 2, tig = lane & 3;
    const int m0 = blockIdx.y * 128, n0 = blockIdx.x * 64;

    const int xr = tid >> 1, xc = (tid & 1) * 16;      // X: row, 16-half k-chunk
    const int wkr = tid >> 3, wnc = (tid & 7) * 8;     // W: k-row, 8-half n-chunk

    // fragment lane offsets (cloned from attn fp16 kernel)
    const unsigned aoffX = (unsigned)((lane & 15) * 80 + (lane >> 4) * 16);
    const unsigned boffW = (unsigned)(((lane & 7) + ((lane >> 3) & 1) * 8) * 144
                                      + (lane >> 4) * 16);

    float acc[2][4][4];
    #pragma unroll
    for (int mi = 0; mi < 2; mi++)
        #pragma unroll
        for (int ni = 0; ni < 4; ni++)
            #pragma unroll
            for (int c = 0; c < 4; c++) acc[mi][ni][c] = 0.f;

    const float* Xp = X + (size_t)(m0 + xr) * Dm + xc;
    const float* Wp = W + (size_t)wkr * Dm + n0 + wnc;

    float4 x0 = *(const float4*)Xp;
    float4 x1 = *(const float4*)(Xp + 4);
    float4 x2 = *(const float4*)(Xp + 8);
    float4 x3 = *(const float4*)(Xp + 12);
    float4 w0 = *(const float4*)Wp;
    float4 w1 = *(const float4*)(Wp + 4);

    // stage buffer 0
    {
        uint4 p;
        p.x = h2u(x0.x, x0.y); p.y = h2u(x0.z, x0.w);
        p.z = h2u(x1.x, x1.y); p.w = h2u(x1.z, x1.w);
        *(uint4*)&Xh[0][xr * 40 + xc] = p;
        p.x = h2u(x2.x, x2.y); p.y = h2u(x2.z, x2.w);
        p.z = h2u(x3.x, x3.y); p.w = h2u(x3.z, x3.w);
        *(uint4*)&Xh[0][xr * 40 + xc + 8] = p;
        p.x = h2u(w0.x, w0.y); p.y = h2u(w0.z, w0.w);
        p.z = h2u(w1.x, w1.y); p.w = h2u(w1.z, w1.w);
        *(uint4*)&Wh[0][wkr * 72 + wnc] = p;
    }
    __syncthreads();

    for (int t = 0; t < 32; t++) {
        const int cur = t & 1;
        if (t < 31) {
            const float* Xn = Xp + (t + 1) * 32;
            const float* Wn = Wp + (size_t)(t + 1) * 32 * Dm;
            x0 = *(const float4*)Xn;
            x1 = *(const float4*)(Xn + 4);
            x2 = *(const float4*)(Xn + 8);
            x3 = *(const float4*)(Xn + 12);
            w0 = *(const float4*)Wn;
            w1 = *(const float4*)(Wn + 4);
        }
        const unsigned xb = smem_u32(&Xh[cur][0]) + (unsigned)(wm * 32 * 80) + aoffX;
        const unsigned wb = smem_u32(&Wh[cur][0]) + (unsigned)(wn * 64) + boffW;
        #pragma unroll
        for (int kk = 0; kk < 2; kk++) {
            unsigned a0[4], a1[4];
            ldsm4(a0[0], a0[1], a0[2], a0[3], xb + kk * 32);
            ldsm4(a1[0], a1[1], a1[2], a1[3], xb + 16 * 80 + kk * 32);
            #pragma unroll
            for (int np = 0; np < 2; np++) {
                unsigned b0, b1, b2, b3;
                ldsm4t(b0, b1, b2, b3, wb + kk * 2304 + np * 32);
                mma_f16(acc[0][2*np][0], acc[0][2*np][1], acc[0][2*np][2], acc[0][2*np][3],
                        a0[0], a0[1], a0[2], a0[3], b0, b1);
                mma_f16(acc[0][2*np+1][0], acc[0][2*np+1][1], acc[0][2*np+1][2], acc[0][2*np+1][3],
                        a0[0], a0[1], a0[2], a0[3], b2, b3);
                mma_f16(acc[1][2*np][0], acc[1][2*np][1], acc[1][2*np][2], acc[1][2*np][3],
                        a1[0], a1[1], a1[2], a1[3], b0, b1);
                mma_f16(acc[1][2*np+1][0], acc[1][2*np+1][1], acc[1][2*np+1][2], acc[1][2*np+1][3],
                        a1[0], a1[1], a1[2], a1[3], b2, b3);
            }
        }
        if (t < 31) {
            const int nxt = cur ^ 1;
            uint4 p;
            p.x = h2u(x0.x, x0.y); p.y = h2u(x0.z, x0.w);
            p.z = h2u(x1.x, x1.y); p.w = h2u(x1.z, x1.w);
            *(uint4*)&Xh[nxt][xr * 40 + xc] = p;
            p.x = h2u(x2.x, x2.y); p.y = h2u(x2.z, x2.w);
            p.z = h2u(x3.x, x3.y); p.w = h2u(x3.z, x3.w);
            *(uint4*)&Xh[nxt][xr * 40 + xc + 8] = p;
            p.x = h2u(w0.x, w0.y); p.y = h2u(w0.z, w0.w);
            p.z = h2u(w1.x, w1.y); p.w = h2u(w1.z, w1.w);
            *(uint4*)&Wh[nxt][wkr * 72 + wnc] = p;
        }
        __syncthreads();
    }

    // ---- epilogue: +bias, head-split store (n-tile == one head) ----
    const int h = blockIdx.x;
    #pragma unroll
    for (int mi = 0; mi < 2; mi++) {
        const int mlo = m0 + wm * 32 + mi * 16 + grp;
        const int mhi = mlo + 8;
        const int blo = mlo >> 11, slo = mlo & 2047;
        const int bhi = mhi >> 11, shi = mhi & 2047;
        #pragma unroll
        for (int ni = 0; ni < 4; ni++) {
            const int col = wn * 32 + ni * 8 + 2 * tig;
            const float b0v = bias[n0 + col], b1v = bias[n0 + col + 1];
            *(float2*)&outp[((size_t)((blo * Hn + h) * Sq + slo)) * DH + col] =
                make_float2(acc[mi][ni][0] + b0v, acc[mi][ni][1] + b1v);
            *(float2*)&outp[((size_t)((bhi * Hn + h) * Sq + shi)) * DH + col] =
                make_float2(acc[mi][ni][2] + b0v, acc[mi][ni][3] + b1v);
        }
    }
}

// ---------------------------------------------------------------------------
// Kernel 2: flash attention on fp16 mma (round-13, unchanged — known good).
// ---------------------------------------------------------------------------
#define QS_O 0
#define KS_O 4608
#define VS_O 9216
#define MK_O 13824
#define PBH_O 13960
#define SMF  22408

extern __shared__ __align__(16) float sm[];

__global__ __launch_bounds__(256, 2)
void attn_kernel(const float* __restrict__ mask,
                 const float* __restrict__ rel,
                 float* __restrict__ out)
{
    __half* Qh = (__half*)(sm + QS_O);
    __half* Kh = (__half*)(sm + KS_O);
    __half* Vh = (__half*)(sm + VS_O);
    float* maskS = sm + MK_O;
    __nv_bfloat16* pbh = (__nv_bfloat16*)(sm + PBH_O);
    float* relS = sm + KS_O;

    const int tid = threadIdx.x;
    const int w = tid >> 5, lane = tid & 31;
    const int grp = lane >> 2, tig = lane & 3;
    const int bh = blockIdx.y, b = bh >> 4, h = bh & 15;
    const int q0 = blockIdx.x * 128;

    const float* Qg = g_Q + (size_t)bh * (Sq * DH);
    const float* Kg = g_K + (size_t)bh * (Sq * DH);
    const float* Vg = g_V + (size_t)bh * (Sq * DH);
    const float* maskb = mask + (size_t)b * Sq;

    {
        const int qr = tid & 127, qc = (tid >> 7) * 32;
        #pragma unroll
        for (int u = 0; u < 4; u++) {
            float4 v0 = *(const float4*)&Qg[(size_t)(q0 + qr) * DH + qc + 8 * u];
            float4 v1 = *(const float4*)&Qg[(size_t)(q0 + qr) * DH + qc + 8 * u + 4];
            uint4 pk;
            pk.x = h2u(0.125f * v0.x, 0.125f * v0.y);
            pk.y = h2u(0.125f * v0.z, 0.125f * v0.w);
            pk.z = h2u(0.125f * v1.x, 0.125f * v1.y);
            pk.w = h2u(0.125f * v1.z, 0.125f * v1.w);
            *(uint4*)&Qh[qr * 72 + qc + 8 * u] = pk;
        }
    }
    for (int i = tid; i < NREL * 32; i += 256) {
        int t = i >> 5, dp = i & 31;
        *(float2*)&relS[t * 66 + 2 * dp] = *(const float2*)&rel[t * DH + 2 * dp];
    }
    __syncthreads();

    {
        const int tx = tid & 15, ty = tid >> 4;
        #pragma unroll
        for (int pass = 0; pass < 2; pass++) {
            const int rb = ty * 8 + pass * 4;
            ull pa[4][9];
            #pragma unroll
            for (int i = 0; i < 4; i++)
                #pragma unroll
                for (int tt = 0; tt < 9; tt++) pa[i][tt] = 0ull;
            for (int dp = 0; dp < 32; dp++) {
                ull qv[4];
                #pragma unroll
                for (int i = 0; i < 4; i++) {
                    __half2 qh = *(const __half2*)&Qh[(rb + i) * 72 + 2 * dp];
                    float2 qf = __half22float2(qh);
                    qv[i] = pack2(qf.x, qf.y);
                }
                #pragma unroll
                for (int tt = 0; tt < 9; tt++) {
                    int t = tx + 16 * tt;
                    if (t < NREL) {
                        ull rv = *(const ull*)&relS[t * 66 + 2 * dp];
                        fma2(pa[0][tt], qv[0], rv);
                        fma2(pa[1][tt], qv[1], rv);
                        fma2(pa[2][tt], qv[2], rv);
                        fma2(pa[3][tt], qv[3], rv);
                    }
                }
            }
            #pragma unroll
            for (int tt = 0; tt < 9; tt++) {
                int t = tx + 16 * tt;
                if (t < NREL) {
                    #pragma unroll
                    for (int i = 0; i < 4; i++) {
                        float2 f = unpack2(pa[i][tt]);
                        pbh[(rb + i) * 132 + t] = __float2bfloat16(f.x + f.y);
                    }
                }
            }
        }
    }
    __syncthreads();

    const int rbase = w * 16;
    const int rlo = rbase + grp, rhi = rlo + 8;
    const int rglo = q0 + rlo, rghi = q0 + rhi;
    const unsigned aoffH = (unsigned)((lane & 15) * 144 + (lane >> 4) * 16);
    const unsigned boffK = (unsigned)(((((lane >> 4) << 3) + (lane & 7))) * 144
                                      + ((lane >> 3) & 1) * 16);
    const unsigned boffV = (unsigned)((((lane & 7) + ((lane >> 3) & 1) * 8)) * 144
                                      + (lane >> 4) * 16);
    unsigned qa[4][4];
    {
        const unsigned qbase = smem_u32(Qh) + (unsigned)(rbase * 144) + aoffH;
        #pragma unroll
        for (int kk = 0; kk < 4; kk++)
            ldsm4(qa[kk][0], qa[kk][1], qa[kk][2], qa[kk][3], qbase + kk * 32);
    }
    __syncwarp();
    const float pLo_l = __bfloat162float(pbh[rlo * 132]);
    const float pHi_l = __bfloat162float(pbh[rlo * 132 + 128]);
    const float pLo_h = __bfloat162float(pbh[rhi * 132]);
    const float pHi_h = __bfloat162float(pbh[rhi * 132 + 128]);
    const unsigned ksb = smem_u32(Kh) + boffK;
    const unsigned vsb = smem_u32(Vh) + boffV;
    const unsigned psb = smem_u32(Qh) + (unsigned)(rbase * 144) + aoffH;

    const int krow = tid & 63, kd0 = (tid >> 6) * 16;
    uint4 krh[2], vrh[2];
    float4 mv;
    {
        const float* Kr = Kg + (size_t)krow * DH + kd0;
        const float* Vr = Vg + (size_t)krow * DH + kd0;
        #pragma unroll
        for (int c = 0; c < 2; c++) {
            float4 f0 = *(const float4*)(Kr + 8 * c);
            float4 f1 = *(const float4*)(Kr + 8 * c + 4);
            krh[c] = make_uint4(h2u(f0.x, f0.y), h2u(f0.z, f0.w),
                                h2u(f1.x, f1.y), h2u(f1.z, f1.w));
            f0 = *(const float4*)(Vr + 8 * c);
            f1 = *(const float4*)(Vr + 8 * c + 4);
            vrh[c] = make_uint4(h2u(f0.x, f0.y), h2u(f0.z, f0.w),
                                h2u(f1.x, f1.y), h2u(f1.z, f1.w));
        }
        if (tid < 16) mv = *(const float4*)&maskb[tid * 4];
    }

    float o[8][4];
    #pragma unroll
    for (int n = 0; n < 8; n++)
        #pragma unroll
        for (int c = 0; c < 4; c++) o[n][c] = 0.f;
    float m_lo = -INFINITY, m_hi = -INFINITY, l_lo = 0.f, l_hi = 0.f;

    for (int kt = 0; kt < 32; kt++) {
        const int buf = kt & 1;
        const int k0 = kt * 64;

        {
            __half* Kd = Kh + buf * 4608;
            __half* Vd = Vh + buf * 4608;
            #pragma unroll
            for (int c = 0; c < 2; c++) {
                *(uint4*)&Kd[krow * 72 + kd0 + 8 * c] = krh[c];
                *(uint4*)&Vd[krow * 72 + kd0 + 8 * c] = vrh[c];
            }
            if (tid < 16) *(float4*)&maskS[buf * 68 + tid * 4] = mv;
        }
        if (kt < 31) {
            const float* Kr = Kg + (size_t)(k0 + 64 + krow) * DH + kd0;
            const float* Vr = Vg + (size_t)(k0 + 64 + krow) * DH + kd0;
            #pragma unroll
            for (int c = 0; c < 2; c++) {
                float4 f0 = *(const float4*)(Kr + 8 * c);
                float4 f1 = *(const float4*)(Kr + 8 * c + 4);
                krh[c] = make_uint4(h2u(f0.x, f0.y), h2u(f0.z, f0.w),
                                    h2u(f1.x, f1.y), h2u(f1.z, f1.w));
                f0 = *(const float4*)(Vr + 8 * c);
                f1 = *(const float4*)(Vr + 8 * c + 4);
                vrh[c] = make_uint4(h2u(f0.x, f0.y), h2u(f0.z, f0.w),
                                    h2u(f1.x, f1.y), h2u(f1.z, f1.w));
            }
            if (tid < 16) mv = *(const float4*)&maskb[k0 + 64 + tid * 4];
        }
        __syncthreads();

        float sc[8][4];
        #pragma unroll
        for (int n = 0; n < 8; n++)
            #pragma unroll
            for (int c = 0; c < 4; c++) sc[n][c] = 0.f;
        const unsigned kbuf = ksb + (unsigned)(buf * 9216);
        #pragma unroll
        for (int kk = 0; kk < 4; kk++) {
            #pragma unroll
            for (int np = 0; np < 4; np++) {
                unsigned b0, b1, b2, b3;
                ldsm4(b0, b1, b2, b3, kbuf + np * 2304 + kk * 32);
                mma_f16(sc[2*np][0], sc[2*np][1], sc[2*np][2], sc[2*np][3],
                        qa[kk][0], qa[kk][1], qa[kk][2], qa[kk][3], b0, b1);
                mma_f16(sc[2*np+1][0], sc[2*np+1][1], sc[2*np+1][2], sc[2*np+1][3],
                        qa[kk][0], qa[kk][1], qa[kk][2], qa[kk][3], b2, b3);
            }
        }

        const float* mk = maskS + buf * 68;
        const int ddmin = k0 - (q0 + 127), ddmax = k0 + 63 - q0;
        const bool gen = (ddmax > -64) && (ddmin < 64);
        const float bC_l = (ddmin >= 64) ? pHi_l : pLo_l;
        const float bC_h = (ddmin >= 64) ? pHi_h : pLo_h;
        float mx_lo = -INFINITY, mx_hi = -INFINITY;
        #pragma unroll
        for (int n = 0; n < 8; n++) {
            const int c0 = n * 8 + 2 * tig;
            float2 mk2 = *(const float2*)&mk[c0];
            float b00, b01, b10, b11;
            if (gen) {
                int d0 = k0 + c0 - rglo;
                int t00 = d0     < -64 ? 0 : (d0     > 64 ? 128 : d0 + 64);
                int t01 = d0 + 1 < -64 ? 0 : (d0 + 1 > 64 ? 128 : d0 + 65);
                int d1 = k0 + c0 - rghi;
                int t10 = d1     < -64 ? 0 : (d1     > 64 ? 128 : d1 + 64);
                int t11 = d1 + 1 < -64 ? 0 : (d1 + 1 > 64 ? 128 : d1 + 65);
                b00 = __bfloat162float(pbh[rlo * 132 + t00]);
                b01 = __bfloat162float(pbh[rlo * 132 + t01]);
                b10 = __bfloat162float(pbh[rhi * 132 + t10]);
                b11 = __bfloat162float(pbh[rhi * 132 + t11]);
            } else { b00 = b01 = bC_l; b10 = b11 = bC_h; }
            sc[n][0] = sc[n][0] + b00 + mk2.x;
            sc[n][1] = sc[n][1] + b01 + mk2.y;
            sc[n][2] = sc[n][2] + b10 + mk2.x;
            sc[n][3] = sc[n][3] + b11 + mk2.y;
            mx_lo = fmaxf(mx_lo, fmaxf(sc[n][0], sc[n][1]));
            mx_hi = fmaxf(mx_hi, fmaxf(sc[n][2], sc[n][3]));
        }
        mx_lo = fmaxf(mx_lo, __shfl_xor_sync(0xffffffffu, mx_lo, 1, 4));
        mx_lo = fmaxf(mx_lo, __shfl_xor_sync(0xffffffffu, mx_lo, 2, 4));
        mx_hi = fmaxf(mx_hi, __shfl_xor_sync(0xffffffffu, mx_hi, 1, 4));
        mx_hi = fmaxf(mx_hi, __shfl_xor_sync(0xffffffffu, mx_hi, 2, 4));
        const float mn_lo = fmaxf(m_lo, mx_lo), mn_hi = fmaxf(m_hi, mx_hi);
        const float al_lo = __expf(m_lo - mn_lo), al_hi = __expf(m_hi - mn_hi);
        float rs_lo = 0.f, rs_hi = 0.f;
        #pragma unroll
        for (int n = 0; n < 8; n++) {
            sc[n][0] = __expf(sc[n][0] - mn_lo); rs_lo += sc[n][0];
            sc[n][1] = __expf(sc[n][1] - mn_lo); rs_lo += sc[n][1];
            sc[n][2] = __expf(sc[n][2] - mn_hi); rs_hi += sc[n][2];
            sc[n][3] = __expf(sc[n][3] - mn_hi); rs_hi += sc[n][3];
        }
        rs_lo += __shfl_xor_sync(0xffffffffu, rs_lo, 1, 4);
        rs_lo += __shfl_xor_sync(0xffffffffu, rs_lo, 2, 4);
        rs_hi += __shfl_xor_sync(0xffffffffu, rs_hi, 1, 4);
        rs_hi += __shfl_xor_sync(0xffffffffu, rs_hi, 2, 4);
        l_lo = l_lo * al_lo + rs_lo; m_lo = mn_lo;
        l_hi = l_hi * al_hi + rs_hi; m_hi = mn_hi;
        #pragma unroll
        for (int n = 0; n < 8; n++) {
            o[n][0] *= al_lo; o[n][1] *= al_lo;
            o[n][2] *= al_hi; o[n][3] *= al_hi;
        }
        __syncwarp();
        #pragma unroll
        for (int n = 0; n < 8; n++) {
            const int c0 = n * 8 + 2 * tig;
            *(unsigned*)&Qh[rlo * 72 + c0] = h2u(sc[n][0], sc[n][1]);
            *(unsigned*)&Qh[rhi * 72 + c0] = h2u(sc[n][2], sc[n][3]);
        }
        __syncwarp();

        const unsigned vbuf = vsb + (unsigned)(buf * 9216);
        #pragma unroll
        for (int jj = 0; jj < 4; jj++) {
            unsigned pa0, pa1, pa2, pa3;
            ldsm4(pa0, pa1, pa2, pa3, psb + jj * 32);
            #pragma unroll
            for (int np = 0; np < 4; np++) {
                unsigned b0, b1, b2, b3;
                ldsm4t(b0, b1, b2, b3, vbuf + jj * 2304 + np * 32);
                mma_f16(o[2*np][0], o[2*np][1], o[2*np][2], o[2*np][3],
                        pa0, pa1, pa2, pa3, b0, b1);
                mma_f16(o[2*np+1][0], o[2*np+1][1], o[2*np+1][2], o[2*np+1][3],
                        pa0, pa1, pa2, pa3, b2, b3);
            }
        }
    }

    const float inv_lo = 1.f / l_lo, inv_hi = 1.f / l_hi;
    #pragma unroll
    for (int n = 0; n < 8; n++) {
        const int col = h * DH + n * 8 + 2 * tig;
        *(float2*)&out[((size_t)(b * Sq + rglo)) * Dm + col] =
            make_float2(o[n][0] * inv_lo, o[n][1] * inv_lo);
        *(float2*)&out[((size_t)(b * Sq + rghi)) * Dm + col] =
            make_float2(o[n][2] * inv_hi, o[n][3] * inv_hi);
    }
}

extern "C" void kernel_launch(void* const* d_in, const int* in_sizes, int n_in,
                              void* d_out, int out_size)
{
    const float* query = (const float*)d_in[0];
    const float* key   = (const float*)d_in[1];
    const float* value = (const float*)d_in[2];
    const float* mask  = (const float*)d_in[3];
    const float* Wq    = (const float*)d_in[4];
    const float* bq    = (const float*)d_in[5];
    const float* Wk    = (const float*)d_in[6];
    const float* bk    = (const float*)d_in[7];
    const float* Wv    = (const float*)d_in[8];
    const float* bv    = (const float*)d_in[9];
    const float* rel   = (const float*)d_in[10];
    float* out = (float*)d_out;
    (void)in_sizes; (void)n_in; (void)out_size;

    const int ATTN_SMEM = SMF * (int)sizeof(float);
    cudaFuncSetAttribute(attn_kernel,
                         cudaFuncAttributeMaxDynamicSharedMemorySize, ATTN_SMEM);

    dim3 gemm_grid(Dm / 64, (Bz * Sq) / 128, 3);
    qkv_proj_kernel<<<gemm_grid, 256>>>(query, key, value, Wq, Wk, Wv, bq, bk, bv);

    dim3 attn_grid(Sq / 128, Bz * Hn);
    attn_kernel<<<attn_grid, 256, ATTN_SMEM>>>(mask, rel, out);
}

// round 15
// speedup vs baseline: 2.5738x; 1.2439x over previous
#include <cuda_runtime.h>
#include <cuda_bf16.h>
#include <cuda_fp16.h>
#include <math.h>

#define Bz 2
#define Sq 2048
#define Dm 1024
#define Hn 16
#define DH 64
#define NREL 129
#define BHN (Bz*Hn)

typedef unsigned long long ull;

// fp16 scratch for projected Q,K,V (Q pre-scaled by 0.125)
__device__ __half g_Qh[BHN * Sq * DH];
__device__ __half g_Kh[BHN * Sq * DH];
__device__ __half g_Vh[BHN * Sq * DH];

__device__ __forceinline__ ull pack2(float lo, float hi) {
    ull r; asm("mov.b64 %0, {%1, %2};" : "=l"(r) : "f"(lo), "f"(hi)); return r;
}
__device__ __forceinline__ float2 unpack2(ull v) {
    float2 r; asm("mov.b64 {%0, %1}, %2;" : "=f"(r.x), "=f"(r.y) : "l"(v)); return r;
}
__device__ __forceinline__ void fma2(ull& a, ull x, ull y) {
    asm("fma.rn.f32x2 %0, %1, %2, %0;" : "+l"(a) : "l"(x), "l"(y));
}
__device__ __forceinline__ void mma_f16(float& c0, float& c1, float& c2, float& c3,
                                        unsigned a0, unsigned a1, unsigned a2, unsigned a3,
                                        unsigned b0, unsigned b1) {
    asm("mma.sync.aligned.m16n8k16.row.col.f32.f16.f16.f32 "
        "{%0,%1,%2,%3}, {%4,%5,%6,%7}, {%8,%9}, {%0,%1,%2,%3};"
        : "+f"(c0), "+f"(c1), "+f"(c2), "+f"(c3)
        : "r"(a0), "r"(a1), "r"(a2), "r"(a3), "r"(b0), "r"(b1));
}
__device__ __forceinline__ void ldsm4(unsigned& r0, unsigned& r1, unsigned& r2, unsigned& r3,
                                      unsigned addr) {
    asm volatile("ldmatrix.sync.aligned.m8n8.x4.shared.b16 {%0,%1,%2,%3}, [%4];"
        : "=r"(r0), "=r"(r1), "=r"(r2), "=r"(r3) : "r"(addr));
}
__device__ __forceinline__ void ldsm4t(unsigned& r0, unsigned& r1, unsigned& r2, unsigned& r3,
                                       unsigned addr) {
    asm volatile("ldmatrix.sync.aligned.m8n8.x4.trans.shared.b16 {%0,%1,%2,%3}, [%4];"
        : "=r"(r0), "=r"(r1), "=r"(r2), "=r"(r3) : "r"(addr));
}
__device__ __forceinline__ unsigned smem_u32(const void* p) {
    return (unsigned)__cvta_generic_to_shared(p);
}
__device__ __forceinline__ unsigned h2u(float a, float b) {
    __half2 h = __floats2half2_rn(a, b);
    return *(unsigned*)&h;
}
__device__ __forceinline__ void cp16(void* dst, const void* src) {
    unsigned a = (unsigned)__cvta_generic_to_shared(dst);
    asm volatile("cp.async.cg.shared.global [%0], [%1], 16;" :: "r"(a), "l"(src) : "memory");
}

// ---------------------------------------------------------------------------
// Kernel 1: QKV projection on fp16 mma (round-14 structure), epilogue writes
// fp16 scratch (Q scaled by 0.125). grid (16, 32, 3), 2 CTAs/SM.
// ---------------------------------------------------------------------------
__global__ __launch_bounds__(256, 2)
void qkv_proj_kernel(const float* __restrict__ Xq, const float* __restrict__ Xk,
                     const float* __restrict__ Xv,
                     const float* __restrict__ Wq, const float* __restrict__ Wk,
                     const float* __restrict__ Wv,
                     const float* __restrict__ bq, const float* __restrict__ bk,
                     const float* __restrict__ bv)
{
    const float* X; const float* W; const float* bias; __half* outp; float scale;
    if (blockIdx.z == 0)      { X = Xq; W = Wq; bias = bq; outp = g_Qh; scale = 0.125f; }
    else if (blockIdx.z == 1) { X = Xk; W = Wk; bias = bk; outp = g_Kh; scale = 1.0f; }
    else                      { X = Xv; W = Wv; bias = bv; outp = g_Vh; scale = 1.0f; }

    __shared__ __align__(16) __half Xh[2][128 * 40];   // [m][k] natural, 80B rows
    __shared__ __align__(16) __half Wh[2][32 * 72];    // [k][n] natural, 144B rows

    const int tid = threadIdx.x;
    const int lane = tid & 31, w = tid >> 5;
    const int wm = w >> 1, wn = w & 1;
    const int grp = lane >> 2, tig = lane & 3;
    const int m0 = blockIdx.y * 128, n0 = blockIdx.x * 64;

    const int xr = tid >> 1, xc = (tid & 1) * 16;
    const int wkr = tid >> 3, wnc = (tid & 7) * 8;

    const unsigned aoffX = (unsigned)((lane & 15) * 80 + (lane >> 4) * 16);
    const unsigned boffW = (unsigned)(((lane & 7) + ((lane >> 3) & 1) * 8) * 144
                                      + (lane >> 4) * 16);

    float acc[2][4][4];
    #pragma unroll
    for (int mi = 0; mi < 2; mi++)
        #pragma unroll
        for (int ni = 0; ni < 4; ni++)
            #pragma unroll
            for (int c = 0; c < 4; c++) acc[mi][ni][c] = 0.f;

    const float* Xp = X + (size_t)(m0 + xr) * Dm + xc;
    const float* Wp = W + (size_t)wkr * Dm + n0 + wnc;

    float4 x0 = *(const float4*)Xp;
    float4 x1 = *(const float4*)(Xp + 4);
    float4 x2 = *(const float4*)(Xp + 8);
    float4 x3 = *(const float4*)(Xp + 12);
    float4 w0 = *(const float4*)Wp;
    float4 w1 = *(const float4*)(Wp + 4);

    {
        uint4 p;
        p.x = h2u(x0.x, x0.y); p.y = h2u(x0.z, x0.w);
        p.z = h2u(x1.x, x1.y); p.w = h2u(x1.z, x1.w);
        *(uint4*)&Xh[0][xr * 40 + xc] = p;
        p.x = h2u(x2.x, x2.y); p.y = h2u(x2.z, x2.w);
        p.z = h2u(x3.x, x3.y); p.w = h2u(x3.z, x3.w);
        *(uint4*)&Xh[0][xr * 40 + xc + 8] = p;
        p.x = h2u(w0.x, w0.y); p.y = h2u(w0.z, w0.w);
        p.z = h2u(w1.x, w1.y); p.w = h2u(w1.z, w1.w);
        *(uint4*)&Wh[0][wkr * 72 + wnc] = p;
    }
    __syncthreads();

    for (int t = 0; t < 32; t++) {
        const int cur = t & 1;
        if (t < 31) {
            const float* Xn = Xp + (t + 1) * 32;
            const float* Wn = Wp + (size_t)(t + 1) * 32 * Dm;
            x0 = *(const float4*)Xn;
            x1 = *(const float4*)(Xn + 4);
            x2 = *(const float4*)(Xn + 8);
            x3 = *(const float4*)(Xn + 12);
            w0 = *(const float4*)Wn;
            w1 = *(const float4*)(Wn + 4);
        }
        const unsigned xb = smem_u32(&Xh[cur][0]) + (unsigned)(wm * 32 * 80) + aoffX;
        const unsigned wb = smem_u32(&Wh[cur][0]) + (unsigned)(wn * 64) + boffW;
        #pragma unroll
        for (int kk = 0; kk < 2; kk++) {
            unsigned a0[4], a1[4];
            ldsm4(a0[0], a0[1], a0[2], a0[3], xb + kk * 32);
            ldsm4(a1[0], a1[1], a1[2], a1[3], xb + 16 * 80 + kk * 32);
            #pragma unroll
            for (int np = 0; np < 2; np++) {
                unsigned b0, b1, b2, b3;
                ldsm4t(b0, b1, b2, b3, wb + kk * 2304 + np * 32);
                mma_f16(acc[0][2*np][0], acc[0][2*np][1], acc[0][2*np][2], acc[0][2*np][3],
                        a0[0], a0[1], a0[2], a0[3], b0, b1);
                mma_f16(acc[0][2*np+1][0], acc[0][2*np+1][1], acc[0][2*np+1][2], acc[0][2*np+1][3],
                        a0[0], a0[1], a0[2], a0[3], b2, b3);
                mma_f16(acc[1][2*np][0], acc[1][2*np][1], acc[1][2*np][2], acc[1][2*np][3],
                        a1[0], a1[1], a1[2], a1[3], b0, b1);
                mma_f16(acc[1][2*np+1][0], acc[1][2*np+1][1], acc[1][2*np+1][2], acc[1][2*np+1][3],
                        a1[0], a1[1], a1[2], a1[3], b2, b3);
            }
        }
        if (t < 31) {
            const int nxt = cur ^ 1;
            uint4 p;
            p.x = h2u(x0.x, x0.y); p.y = h2u(x0.z, x0.w);
            p.z = h2u(x1.x, x1.y); p.w = h2u(x1.z, x1.w);
            *(uint4*)&Xh[nxt][xr * 40 + xc] = p;
            p.x = h2u(x2.x, x2.y); p.y = h2u(x2.z, x2.w);
            p.z = h2u(x3.x, x3.y); p.w = h2u(x3.z, x3.w);
            *(uint4*)&Xh[nxt][xr * 40 + xc + 8] = p;
            p.x = h2u(w0.x, w0.y); p.y = h2u(w0.z, w0.w);
            p.z = h2u(w1.x, w1.y); p.w = h2u(w1.z, w1.w);
            *(uint4*)&Wh[nxt][wkr * 72 + wnc] = p;
        }
        __syncthreads();
    }

    // ---- epilogue: +bias, *scale, fp16 head-split store ----
    const int h = blockIdx.x;
    #pragma unroll
    for (int mi = 0; mi < 2; mi++) {
        const int mlo = m0 + wm * 32 + mi * 16 + grp;
        const int mhi = mlo + 8;
        const int blo = mlo >> 11, slo = mlo & 2047;
        const int bhi = mhi >> 11, shi = mhi & 2047;
        #pragma unroll
        for (int ni = 0; ni < 4; ni++) {
            const int col = wn * 32 + ni * 8 + 2 * tig;
            const float b0v = bias[n0 + col], b1v = bias[n0 + col + 1];
            *(unsigned*)&outp[((size_t)((blo * Hn + h) * Sq + slo)) * DH + col] =
                h2u((acc[mi][ni][0] + b0v) * scale, (acc[mi][ni][1] + b1v) * scale);
            *(unsigned*)&outp[((size_t)((bhi * Hn + h) * Sq + shi)) * DH + col] =
                h2u((acc[mi][ni][2] + b0v) * scale, (acc[mi][ni][3] + b1v) * scale);
        }
    }
}

// ---------------------------------------------------------------------------
// Kernel 2: flash attention, fp16 mma, cp.async staging from fp16 scratch,
// 3-buffer K/V ring, 1 sync/tile. 2 CTAs/SM.
// ---------------------------------------------------------------------------
// half-offsets
#define QS_H 0        // Qh[128][72]; Ps overlay after hoist
#define KS_H 9216     // Kh[3][64][72]
#define VS_H 23040    // Vh[3][64][72]
#define MK_H 36864    // maskS: 2x68 floats (as halves offset; float region)
#define PBH_H 37136   // pbh bf16[128][132] (16896 halves)
#define SMH  54032    // total halves -> 108,064 bytes
#define KVBUF_B 9216  // bytes per K/V ring slot (64*72*2)

extern __shared__ __align__(16) __half smh[];

__global__ __launch_bounds__(256, 2)
void attn_kernel(const float* __restrict__ mask,
                 const float* __restrict__ rel,
                 float* __restrict__ out)
{
    __half* Qh = smh + QS_H;
    __half* Kh = smh + KS_H;
    __half* Vh = smh + VS_H;
    float* maskS = (float*)(smh + MK_H);
    __nv_bfloat16* pbh = (__nv_bfloat16*)(smh + PBH_H);
    float* relS = (float*)(smh + KS_H);   // fp32 [129][66] overlay on Kh/Vh

    const int tid = threadIdx.x;
    const int w = tid >> 5, lane = tid & 31;
    const int grp = lane >> 2, tig = lane & 3;
    const int bh = blockIdx.y, b = bh >> 4, h = bh & 15;
    const int q0 = blockIdx.x * 128;

    const __half* Qg = g_Qh + (size_t)bh * (Sq * DH);
    const __half* Kg = g_Kh + (size_t)bh * (Sq * DH);
    const __half* Vg = g_Vh + (size_t)bh * (Sq * DH);
    const float* maskb = mask + (size_t)b * Sq;

    // ---- stage Q via cp.async (already fp16, pre-scaled) ----
    #pragma unroll
    for (int c = 0; c < 4; c++) {
        int id = tid + 256 * c;
        int row = id >> 3, cj = id & 7;
        cp16(&Qh[row * 72 + cj * 8], &Qg[(size_t)(q0 + row) * DH + cj * 8]);
    }
    // ---- stage rel (fp32, stride 66, overlay on Kh/Vh) ----
    for (int i = tid; i < NREL * 32; i += 256) {
        int t = i >> 5, dp = i & 31;
        *(float2*)&relS[t * 66 + 2 * dp] = *(const float2*)&rel[t * DH + 2 * dp];
    }
    // ---- mask tile 0 + prefetch tile 1 ----
    float4 mv;
    if (tid < 16) {
        *(float4*)&maskS[tid * 4] = *(const float4*)&maskb[tid * 4];
        mv = *(const float4*)&maskb[64 + tid * 4];
    }
    asm volatile("cp.async.commit_group;" ::: "memory");
    asm volatile("cp.async.wait_group 0;" ::: "memory");
    __syncthreads();

    // ---- pb[r][t] = (q_r/8) . rel_t  -> bf16 table ----
    {
        const int tx = tid & 15, ty = tid >> 4;
        #pragma unroll
        for (int pass = 0; pass < 2; pass++) {
            const int rb = ty * 8 + pass * 4;
            ull pa[4][9];
            #pragma unroll
            for (int i = 0; i < 4; i++)
                #pragma unroll
                for (int tt = 0; tt < 9; tt++) pa[i][tt] = 0ull;
            for (int dp = 0; dp < 32; dp++) {
                ull qv[4];
                #pragma unroll
                for (int i = 0; i < 4; i++) {
                    __half2 qh = *(const __half2*)&Qh[(rb + i) * 72 + 2 * dp];
                    float2 qf = __half22float2(qh);
                    qv[i] = pack2(qf.x, qf.y);
                }
                #pragma unroll
                for (int tt = 0; tt < 9; tt++) {
                    int t = tx + 16 * tt;
                    if (t < NREL) {
                        ull rv = *(const ull*)&relS[t * 66 + 2 * dp];
                        fma2(pa[0][tt], qv[0], rv);
                        fma2(pa[1][tt], qv[1], rv);
                        fma2(pa[2][tt], qv[2], rv);
                        fma2(pa[3][tt], qv[3], rv);
                    }
                }
            }
            #pragma unroll
            for (int tt = 0; tt < 9; tt++) {
                int t = tx + 16 * tt;
                if (t < NREL) {
                    #pragma unroll
                    for (int i = 0; i < 4; i++) {
                        float2 f = unpack2(pa[i][tt]);
                        pbh[(rb + i) * 132 + t] = __float2bfloat16(f.x + f.y);
                    }
                }
            }
        }
    }
    __syncthreads();   // pb done; relS (Kh/Vh) free

    // ---- issue K/V tiles 0 and 1 (cp.async groups) ----
    #pragma unroll
    for (int c = 0; c < 2; c++) {
        int id = tid + 256 * c;
        int row = id >> 3, cj = id & 7;
        cp16(&Kh[row * 72 + cj * 8], &Kg[(size_t)row * DH + cj * 8]);
        cp16(&Vh[row * 72 + cj * 8], &Vg[(size_t)row * DH + cj * 8]);
    }
    asm volatile("cp.async.commit_group;" ::: "memory");
    #pragma unroll
    for (int c = 0; c < 2; c++) {
        int id = tid + 256 * c;
        int row = id >> 3, cj = id & 7;
        cp16(&Kh[4608 + row * 72 + cj * 8], &Kg[(size_t)(64 + row) * DH + cj * 8]);
        cp16(&Vh[4608 + row * 72 + cj * 8], &Vg[(size_t)(64 + row) * DH + cj * 8]);
    }
    asm volatile("cp.async.commit_group;" ::: "memory");

    // ---- hoist Q a-fragments ----
    const int rbase = w * 16;
    const int rlo = rbase + grp, rhi = rlo + 8;
    const int rglo = q0 + rlo, rghi = q0 + rhi;
    const unsigned aoffH = (unsigned)((lane & 15) * 144 + (lane >> 4) * 16);
    const unsigned boffK = (unsigned)(((((lane >> 4) << 3) + (lane & 7))) * 144
                                      + ((lane >> 3) & 1) * 16);
    const unsigned boffV = (unsigned)((((lane & 7) + ((lane >> 3) & 1) * 8)) * 144
                                      + (lane >> 4) * 16);
    unsigned qa[4][4];
    {
        const unsigned qbase = smem_u32(Qh) + (unsigned)(rbase * 144) + aoffH;
        #pragma unroll
        for (int kk = 0; kk < 4; kk++)
            ldsm4(qa[kk][0], qa[kk][1], qa[kk][2], qa[kk][3], qbase + kk * 32);
    }
    __syncwarp();
    const float pLo_l = __bfloat162float(pbh[rlo * 132]);
    const float pHi_l = __bfloat162float(pbh[rlo * 132 + 128]);
    const float pLo_h = __bfloat162float(pbh[rhi * 132]);
    const float pHi_h = __bfloat162float(pbh[rhi * 132 + 128]);
    const unsigned ksb = smem_u32(Kh) + boffK;
    const unsigned vsb = smem_u32(Vh) + boffV;
    const unsigned psb = smem_u32(Qh) + (unsigned)(rbase * 144) + aoffH;

    float o[8][4];
    #pragma unroll
    for (int n = 0; n < 8; n++)
        #pragma unroll
        for (int c = 0; c < 4; c++) o[n][c] = 0.f;
    float m_lo = -INFINITY, m_hi = -INFINITY, l_lo = 0.f, l_hi = 0.f;

    for (int kt = 0; kt < 32; kt++) {
        const int buf = kt % 3;
        const int k0 = kt * 64;

        // tile kt copies complete (allow 1 newer group pending)
        if (kt < 31) { asm volatile("cp.async.wait_group 1;" ::: "memory"); }
        else         { asm volatile("cp.async.wait_group 0;" ::: "memory"); }
        __syncthreads();   // all threads' copies visible; prev iter fully consumed

        // issue tile kt+2 into ring slot (kt+2)%3 (last read in iter kt-1)
        if (kt + 2 < 32) {
            const int slot = (kt + 2) % 3;
            const __half* Kn = Kg + (size_t)(k0 + 128) * DH;
            const __half* Vn = Vg + (size_t)(k0 + 128) * DH;
            #pragma unroll
            for (int c = 0; c < 2; c++) {
                int id = tid + 256 * c;
                int row = id >> 3, cj = id & 7;
                cp16(&Kh[slot * 4608 + row * 72 + cj * 8], &Kn[(size_t)row * DH + cj * 8]);
                cp16(&Vh[slot * 4608 + row * 72 + cj * 8], &Vn[(size_t)row * DH + cj * 8]);
            }
            asm volatile("cp.async.commit_group;" ::: "memory");
        }
        // mask: store tile kt+1 slot, prefetch tile kt+2
        if (kt < 31 && tid < 16)
            *(float4*)&maskS[((kt + 1) & 1) * 68 + tid * 4] = mv;
        if (kt < 30 && tid < 16)
            mv = *(const float4*)&maskb[(kt + 2) * 64 + tid * 4];

        // ---- scores ----
        float sc[8][4];
        #pragma unroll
        for (int n = 0; n < 8; n++)
            #pragma unroll
            for (int c = 0; c < 4; c++) sc[n][c] = 0.f;
        const unsigned kbuf = ksb + (unsigned)(buf * KVBUF_B);
        #pragma unroll
        for (int kk = 0; kk < 4; kk++) {
            #pragma unroll
            for (int np = 0; np < 4; np++) {
                unsigned b0, b1, b2, b3;
                ldsm4(b0, b1, b2, b3, kbuf + np * 2304 + kk * 32);
                mma_f16(sc[2*np][0], sc[2*np][1], sc[2*np][2], sc[2*np][3],
                        qa[kk][0], qa[kk][1], qa[kk][2], qa[kk][3], b0, b1);
                mma_f16(sc[2*np+1][0], sc[2*np+1][1], sc[2*np+1][2], sc[2*np+1][3],
                        qa[kk][0], qa[kk][1], qa[kk][2], qa[kk][3], b2, b3);
            }
        }

        // ---- bias + mask + warp-local online softmax ----
        const float* mk = maskS + (kt & 1) * 68;
        const int ddmin = k0 - (q0 + 127), ddmax = k0 + 63 - q0;
        const bool gen = (ddmax > -64) && (ddmin < 64);
        const float bC_l = (ddmin >= 64) ? pHi_l : pLo_l;
        const float bC_h = (ddmin >= 64) ? pHi_h : pLo_h;
        float mx_lo = -INFINITY, mx_hi = -INFINITY;
        #pragma unroll
        for (int n = 0; n < 8; n++) {
            const int c0 = n * 8 + 2 * tig;
            float2 mk2 = *(const float2*)&mk[c0];
            float b00, b01, b10, b11;
            if (gen) {
                int d0 = k0 + c0 - rglo;
                int t00 = d0     < -64 ? 0 : (d0     > 64 ? 128 : d0 + 64);
                int t01 = d0 + 1 < -64 ? 0 : (d0 + 1 > 64 ? 128 : d0 + 65);
                int d1 = k0 + c0 - rghi;
                int t10 = d1     < -64 ? 0 : (d1     > 64 ? 128 : d1 + 64);
                int t11 = d1 + 1 < -64 ? 0 : (d1 + 1 > 64 ? 128 : d1 + 65);
                b00 = __bfloat162float(pbh[rlo * 132 + t00]);
                b01 = __bfloat162float(pbh[rlo * 132 + t01]);
                b10 = __bfloat162float(pbh[rhi * 132 + t10]);
                b11 = __bfloat162float(pbh[rhi * 132 + t11]);
            } else { b00 = b01 = bC_l; b10 = b11 = bC_h; }
            sc[n][0] = sc[n][0] + b00 + mk2.x;
            sc[n][1] = sc[n][1] + b01 + mk2.y;
            sc[n][2] = sc[n][2] + b10 + mk2.x;
            sc[n][3] = sc[n][3] + b11 + mk2.y;
            mx_lo = fmaxf(mx_lo, fmaxf(sc[n][0], sc[n][1]));
            mx_hi = fmaxf(mx_hi, fmaxf(sc[n][2], sc[n][3]));
        }
        mx_lo = fmaxf(mx_lo, __shfl_xor_sync(0xffffffffu, mx_lo, 1, 4));
        mx_lo = fmaxf(mx_lo, __shfl_xor_sync(0xffffffffu, mx_lo, 2, 4));
        mx_hi = fmaxf(mx_hi, __shfl_xor_sync(0xffffffffu, mx_hi, 1, 4));
        mx_hi = fmaxf(mx_hi, __shfl_xor_sync(0xffffffffu, mx_hi, 2, 4));
        const float mn_lo = fmaxf(m_lo, mx_lo), mn_hi = fmaxf(m_hi, mx_hi);
        const float al_lo = __expf(m_lo - mn_lo), al_hi = __expf(m_hi - mn_hi);
        float rs_lo = 0.f, rs_hi = 0.f;
        #pragma unroll
        for (int n = 0; n < 8; n++) {
            sc[n][0] = __expf(sc[n][0] - mn_lo); rs_lo += sc[n][0];
            sc[n][1] = __expf(sc[n][1] - mn_lo); rs_lo += sc[n][1];
            sc[n][2] = __expf(sc[n][2] - mn_hi); rs_hi += sc[n][2];
            sc[n][3] = __expf(sc[n][3] - mn_hi); rs_hi += sc[n][3];
        }
        rs_lo += __shfl_xor_sync(0xffffffffu, rs_lo, 1, 4);
        rs_lo += __shfl_xor_sync(0xffffffffu, rs_lo, 2, 4);
        rs_hi += __shfl_xor_sync(0xffffffffu, rs_hi, 1, 4);
        rs_hi += __shfl_xor_sync(0xffffffffu, rs_hi, 2, 4);
        l_lo = l_lo * al_lo + rs_lo; m_lo = mn_lo;
        l_hi = l_hi * al_hi + rs_hi; m_hi = mn_hi;
        #pragma unroll
        for (int n = 0; n < 8; n++) {
            o[n][0] *= al_lo; o[n][1] *= al_lo;
            o[n][2] *= al_hi; o[n][3] *= al_hi;
        }
        // ---- stage P (fp16, warp-local rows in Qh) ----
        __syncwarp();
        #pragma unroll
        for (int n = 0; n < 8; n++) {
            const int c0 = n * 8 + 2 * tig;
            *(unsigned*)&Qh[rlo * 72 + c0] = h2u(sc[n][0], sc[n][1]);
            *(unsigned*)&Qh[rhi * 72 + c0] = h2u(sc[n][2], sc[n][3]);
        }
        __syncwarp();

        // ---- O += P V ----
        const unsigned vbuf = vsb + (unsigned)(buf * KVBUF_B);
        #pragma unroll
        for (int jj = 0; jj < 4; jj++) {
            unsigned pa0, pa1, pa2, pa3;
            ldsm4(pa0, pa1, pa2, pa3, psb + jj * 32);
            #pragma unroll
            for (int np = 0; np < 4; np++) {
                unsigned b0, b1, b2, b3;
                ldsm4t(b0, b1, b2, b3, vbuf + jj * 2304 + np * 32);
                mma_f16(o[2*np][0], o[2*np][1], o[2*np][2], o[2*np][3],
                        pa0, pa1, pa2, pa3, b0, b1);
                mma_f16(o[2*np+1][0], o[2*np+1][1], o[2*np+1][2], o[2*np+1][3],
                        pa0, pa1, pa2, pa3, b2, b3);
            }
        }
    }

    // ---- epilogue ----
    const float inv_lo = 1.f / l_lo, inv_hi = 1.f / l_hi;
    #pragma unroll
    for (int n = 0; n < 8; n++) {
        const int col = h * DH + n * 8 + 2 * tig;
        *(float2*)&out[((size_t)(b * Sq + rglo)) * Dm + col] =
            make_float2(o[n][0] * inv_lo, o[n][1] * inv_lo);
        *(float2*)&out[((size_t)(b * Sq + rghi)) * Dm + col] =
            make_float2(o[n][2] * inv_hi, o[n][3] * inv_hi);
    }
}

extern "C" void kernel_launch(void* const* d_in, const int* in_sizes, int n_in,
                              void* d_out, int out_size)
{
    const float* query = (const float*)d_in[0];
    const float* key   = (const float*)d_in[1];
    const float* value = (const float*)d_in[2];
    const float* mask  = (const float*)d_in[3];
    const float* Wq    = (const float*)d_in[4];
    const float* bq    = (const float*)d_in[5];
    const float* Wk    = (const float*)d_in[6];
    const float* bk    = (const float*)d_in[7];
    const float* Wv    = (const float*)d_in[8];
    const float* bv    = (const float*)d_in[9];
    const float* rel   = (const float*)d_in[10];
    float* out = (float*)d_out;
    (void)in_sizes; (void)n_in; (void)out_size;

    const int ATTN_SMEM = SMH * (int)sizeof(__half);
    cudaFuncSetAttribute(attn_kernel,
                         cudaFuncAttributeMaxDynamicSharedMemorySize, ATTN_SMEM);

    dim3 gemm_grid(Dm / 64, (Bz * Sq) / 128, 3);
    qkv_proj_kernel<<<gemm_grid, 256>>>(query, key, value, Wq, Wk, Wv, bq, bk, bv);

    dim3 attn_grid(Sq / 128, Bz * Hn);
    attn_kernel<<<attn_grid, 256, ATTN_SMEM>>>(mask, rel, out);
}

// round 16
// speedup vs baseline: 3.3273x; 1.2927x over previous
#include <cuda_runtime.h>
#include <cuda_bf16.h>
#include <cuda_fp16.h>
#include <math.h>

#define Bz 2
#define Sq 2048
#define Dm 1024
#define Hn 16
#define DH 64
#define NREL 129
#define BHN (Bz*Hn)

typedef unsigned long long ull;

// fp16 scratch
__device__ __half g_Qh[BHN * Sq * DH];
__device__ __half g_Kh[BHN * Sq * DH];
__device__ __half g_Vh[BHN * Sq * DH];
__device__ __half g_Xh[3][(size_t)Bz * Sq * Dm];   // converted inputs
__device__ __half g_Wh[3][(size_t)Dm * Dm];        // converted weights

__device__ __forceinline__ ull pack2(float lo, float hi) {
    ull r; asm("mov.b64 %0, {%1, %2};" : "=l"(r) : "f"(lo), "f"(hi)); return r;
}
__device__ __forceinline__ float2 unpack2(ull v) {
    float2 r; asm("mov.b64 {%0, %1}, %2;" : "=f"(r.x), "=f"(r.y) : "l"(v)); return r;
}
__device__ __forceinline__ void fma2(ull& a, ull x, ull y) {
    asm("fma.rn.f32x2 %0, %1, %2, %0;" : "+l"(a) : "l"(x), "l"(y));
}
__device__ __forceinline__ void mma_f16(float& c0, float& c1, float& c2, float& c3,
                                        unsigned a0, unsigned a1, unsigned a2, unsigned a3,
                                        unsigned b0, unsigned b1) {
    asm("mma.sync.aligned.m16n8k16.row.col.f32.f16.f16.f32 "
        "{%0,%1,%2,%3}, {%4,%5,%6,%7}, {%8,%9}, {%0,%1,%2,%3};"
        : "+f"(c0), "+f"(c1), "+f"(c2), "+f"(c3)
        : "r"(a0), "r"(a1), "r"(a2), "r"(a3), "r"(b0), "r"(b1));
}
__device__ __forceinline__ void ldsm4(unsigned& r0, unsigned& r1, unsigned& r2, unsigned& r3,
                                      unsigned addr) {
    asm volatile("ldmatrix.sync.aligned.m8n8.x4.shared.b16 {%0,%1,%2,%3}, [%4];"
        : "=r"(r0), "=r"(r1), "=r"(r2), "=r"(r3) : "r"(addr));
}
__device__ __forceinline__ void ldsm4t(unsigned& r0, unsigned& r1, unsigned& r2, unsigned& r3,
                                       unsigned addr) {
    asm volatile("ldmatrix.sync.aligned.m8n8.x4.trans.shared.b16 {%0,%1,%2,%3}, [%4];"
        : "=r"(r0), "=r"(r1), "=r"(r2), "=r"(r3) : "r"(addr));
}
__device__ __forceinline__ unsigned smem_u32(const void* p) {
    return (unsigned)__cvta_generic_to_shared(p);
}
__device__ __forceinline__ unsigned h2u(float a, float b) {
    __half2 h = __floats2half2_rn(a, b);
    return *(unsigned*)&h;
}
__device__ __forceinline__ void cp16(void* dst, const void* src) {
    unsigned a = (unsigned)__cvta_generic_to_shared(dst);
    asm volatile("cp.async.cg.shared.global [%0], [%1], 16;" :: "r"(a), "l"(src) : "memory");
}

// ---------------------------------------------------------------------------
// Kernel 0: fp32 -> fp16 bulk convert (grid-stride over 8-element chunks)
// ---------------------------------------------------------------------------
__global__ void cvt_kernel(const float* __restrict__ src, __half* __restrict__ dst,
                           int n8)
{
    int i = blockIdx.x * blockDim.x + threadIdx.x;
    if (i < n8) {
        const float4 a = *(const float4*)(src + i * 8);
        const float4 b = *(const float4*)(src + i * 8 + 4);
        uint4 p;
        p.x = h2u(a.x, a.y); p.y = h2u(a.z, a.w);
        p.z = h2u(b.x, b.y); p.w = h2u(b.z, b.w);
        *(uint4*)&dst[i * 8] = p;
    }
}

// ---------------------------------------------------------------------------
// Kernel 1: QKV projection, fp16 mma, cp.async 3-slot ring staging.
// 128x64 tile, k-step 32, 8 warps (4m x 2n), 2 CTAs/SM. grid (16, 32, 3).
// ---------------------------------------------------------------------------
#define GX_SL 5120   // halves per X slot (128 rows x 40)
#define GW_SL 2304   // halves per W slot (32 rows x 72)

__global__ __launch_bounds__(256, 2)
void qkv_proj_kernel(const float* __restrict__ bq, const float* __restrict__ bk,
                     const float* __restrict__ bv)
{
    const int z = blockIdx.z;
    const __half* X = g_Xh[z];
    const __half* W = g_Wh[z];
    const float* bias = (z == 0) ? bq : (z == 1) ? bk : bv;
    __half* outp = (z == 0) ? g_Qh : (z == 1) ? g_Kh : g_Vh;
    const float scale = (z == 0) ? 0.125f : 1.0f;

    __shared__ __align__(16) __half Xs[3 * GX_SL];
    __shared__ __align__(16) __half Ws[3 * GW_SL];

    const int tid = threadIdx.x;
    const int lane = tid & 31, w = tid >> 5;
    const int wm = w >> 1, wn = w & 1;
    const int grp = lane >> 2, tig = lane & 3;
    const int m0 = blockIdx.y * 128, n0 = blockIdx.x * 64;

    const unsigned aoffX = (unsigned)((lane & 15) * 80 + (lane >> 4) * 16);
    const unsigned boffW = (unsigned)(((lane & 7) + ((lane >> 3) & 1) * 8) * 144
                                      + (lane >> 4) * 16);

    // copy assignments: X 512 16B-chunks (2/thread), W 256 (1/thread)
    const int xrow0 = tid >> 2, xck = (tid & 3);           // ids 0..255
    const int xrow1 = (tid + 256) >> 2, xck1 = (tid & 3);  // ids 256..511
    const int wrow = tid >> 3, wck = tid & 7;

    float acc[2][4][4];
    #pragma unroll
    for (int mi = 0; mi < 2; mi++)
        #pragma unroll
        for (int ni = 0; ni < 4; ni++)
            #pragma unroll
            for (int c = 0; c < 4; c++) acc[mi][ni][c] = 0.f;

    // issue tiles 0 and 1
    #pragma unroll
    for (int s = 0; s < 2; s++) {
        const __half* Xsrc = X + (size_t)m0 * Dm + s * 32;
        const __half* Wsrc = W + (size_t)(s * 32) * Dm + n0;
        cp16(&Xs[s * GX_SL + xrow0 * 40 + xck * 8], &Xsrc[(size_t)xrow0 * Dm + xck * 8]);
        cp16(&Xs[s * GX_SL + xrow1 * 40 + xck1 * 8], &Xsrc[(size_t)xrow1 * Dm + xck1 * 8]);
        cp16(&Ws[s * GW_SL + wrow * 72 + wck * 8], &Wsrc[(size_t)wrow * Dm + wck * 8]);
        asm volatile("cp.async.commit_group;" ::: "memory");
    }

    for (int t = 0; t < 32; t++) {
        const int slot = t % 3;
        if (t < 31) { asm volatile("cp.async.wait_group 1;" ::: "memory"); }
        else        { asm volatile("cp.async.wait_group 0;" ::: "memory"); }
        __syncthreads();

        if (t + 2 < 32) {
            const int ns = (t + 2) % 3;
            const __half* Xsrc = X + (size_t)m0 * Dm + (t + 2) * 32;
            const __half* Wsrc = W + (size_t)((t + 2) * 32) * Dm + n0;
            cp16(&Xs[ns * GX_SL + xrow0 * 40 + xck * 8], &Xsrc[(size_t)xrow0 * Dm + xck * 8]);
            cp16(&Xs[ns * GX_SL + xrow1 * 40 + xck1 * 8], &Xsrc[(size_t)xrow1 * Dm + xck1 * 8]);
            cp16(&Ws[ns * GW_SL + wrow * 72 + wck * 8], &Wsrc[(size_t)wrow * Dm + wck * 8]);
            asm volatile("cp.async.commit_group;" ::: "memory");
        }

        const unsigned xb = smem_u32(Xs) + (unsigned)(slot * GX_SL * 2)
                            + (unsigned)(wm * 32 * 80) + aoffX;
        const unsigned wb = smem_u32(Ws) + (unsigned)(slot * GW_SL * 2)
                            + (unsigned)(wn * 64) + boffW;
        #pragma unroll
        for (int kk = 0; kk < 2; kk++) {
            unsigned a0[4], a1[4];
            ldsm4(a0[0], a0[1], a0[2], a0[3], xb + kk * 32);
            ldsm4(a1[0], a1[1], a1[2], a1[3], xb + 16 * 80 + kk * 32);
            #pragma unroll
            for (int np = 0; np < 2; np++) {
                unsigned b0, b1, b2, b3;
                ldsm4t(b0, b1, b2, b3, wb + kk * 2304 + np * 32);
                mma_f16(acc[0][2*np][0], acc[0][2*np][1], acc[0][2*np][2], acc[0][2*np][3],
                        a0[0], a0[1], a0[2], a0[3], b0, b1);
                mma_f16(acc[0][2*np+1][0], acc[0][2*np+1][1], acc[0][2*np+1][2], acc[0][2*np+1][3],
                        a0[0], a0[1], a0[2], a0[3], b2, b3);
                mma_f16(acc[1][2*np][0], acc[1][2*np][1], acc[1][2*np][2], acc[1][2*np][3],
                        a1[0], a1[1], a1[2], a1[3], b0, b1);
                mma_f16(acc[1][2*np+1][0], acc[1][2*np+1][1], acc[1][2*np+1][2], acc[1][2*np+1][3],
                        a1[0], a1[1], a1[2], a1[3], b2, b3);
            }
        }
    }

    // ---- epilogue: +bias, *scale, fp16 head-split store ----
    const int h = blockIdx.x;
    #pragma unroll
    for (int mi = 0; mi < 2; mi++) {
        const int mlo = m0 + wm * 32 + mi * 16 + grp;
        const int mhi = mlo + 8;
        const int blo = mlo >> 11, slo = mlo & 2047;
        const int bhi = mhi >> 11, shi = mhi & 2047;
        #pragma unroll
        for (int ni = 0; ni < 4; ni++) {
            const int col = wn * 32 + ni * 8 + 2 * tig;
            const float b0v = bias[n0 + col], b1v = bias[n0 + col + 1];
            *(unsigned*)&outp[((size_t)((blo * Hn + h) * Sq + slo)) * DH + col] =
                h2u((acc[mi][ni][0] + b0v) * scale, (acc[mi][ni][1] + b1v) * scale);
            *(unsigned*)&outp[((size_t)((bhi * Hn + h) * Sq + shi)) * DH + col] =
                h2u((acc[mi][ni][2] + b0v) * scale, (acc[mi][ni][3] + b1v) * scale);
        }
    }
}

// ---------------------------------------------------------------------------
// Kernel 2: flash attention (round-15, unchanged — known good).
// ---------------------------------------------------------------------------
#define QS_H 0
#define KS_H 9216
#define VS_H 23040
#define MK_H 36864
#define PBH_H 37136
#define SMH  54032
#define KVBUF_B 9216

extern __shared__ __align__(16) __half smh[];

__global__ __launch_bounds__(256, 2)
void attn_kernel(const float* __restrict__ mask,
                 const float* __restrict__ rel,
                 float* __restrict__ out)
{
    __half* Qh = smh + QS_H;
    __half* Kh = smh + KS_H;
    __half* Vh = smh + VS_H;
    float* maskS = (float*)(smh + MK_H);
    __nv_bfloat16* pbh = (__nv_bfloat16*)(smh + PBH_H);
    float* relS = (float*)(smh + KS_H);

    const int tid = threadIdx.x;
    const int w = tid >> 5, lane = tid & 31;
    const int grp = lane >> 2, tig = lane & 3;
    const int bh = blockIdx.y, b = bh >> 4, h = bh & 15;
    const int q0 = blockIdx.x * 128;

    const __half* Qg = g_Qh + (size_t)bh * (Sq * DH);
    const __half* Kg = g_Kh + (size_t)bh * (Sq * DH);
    const __half* Vg = g_Vh + (size_t)bh * (Sq * DH);
    const float* maskb = mask + (size_t)b * Sq;

    #pragma unroll
    for (int c = 0; c < 4; c++) {
        int id = tid + 256 * c;
        int row = id >> 3, cj = id & 7;
        cp16(&Qh[row * 72 + cj * 8], &Qg[(size_t)(q0 + row) * DH + cj * 8]);
    }
    for (int i = tid; i < NREL * 32; i += 256) {
        int t = i >> 5, dp = i & 31;
        *(float2*)&relS[t * 66 + 2 * dp] = *(const float2*)&rel[t * DH + 2 * dp];
    }
    float4 mv;
    if (tid < 16) {
        *(float4*)&maskS[tid * 4] = *(const float4*)&maskb[tid * 4];
        mv = *(const float4*)&maskb[64 + tid * 4];
    }
    asm volatile("cp.async.commit_group;" ::: "memory");
    asm volatile("cp.async.wait_group 0;" ::: "memory");
    __syncthreads();

    {
        const int tx = tid & 15, ty = tid >> 4;
        #pragma unroll
        for (int pass = 0; pass < 2; pass++) {
            const int rb = ty * 8 + pass * 4;
            ull pa[4][9];
            #pragma unroll
            for (int i = 0; i < 4; i++)
                #pragma unroll
                for (int tt = 0; tt < 9; tt++) pa[i][tt] = 0ull;
            for (int dp = 0; dp < 32; dp++) {
                ull qv[4];
                #pragma unroll
                for (int i = 0; i < 4; i++) {
                    __half2 qh = *(const __half2*)&Qh[(rb + i) * 72 + 2 * dp];
                    float2 qf = __half22float2(qh);
                    qv[i] = pack2(qf.x, qf.y);
                }
                #pragma unroll
                for (int tt = 0; tt < 9; tt++) {
                    int t = tx + 16 * tt;
                    if (t < NREL) {
                        ull rv = *(const ull*)&relS[t * 66 + 2 * dp];
                        fma2(pa[0][tt], qv[0], rv);
                        fma2(pa[1][tt], qv[1], rv);
                        fma2(pa[2][tt], qv[2], rv);
                        fma2(pa[3][tt], qv[3], rv);
                    }
                }
            }
            #pragma unroll
            for (int tt = 0; tt < 9; tt++) {
                int t = tx + 16 * tt;
                if (t < NREL) {
                    #pragma unroll
                    for (int i = 0; i < 4; i++) {
                        float2 f = unpack2(pa[i][tt]);
                        pbh[(rb + i) * 132 + t] = __float2bfloat16(f.x + f.y);
                    }
                }
            }
        }
    }
    __syncthreads();

    #pragma unroll
    for (int c = 0; c < 2; c++) {
        int id = tid + 256 * c;
        int row = id >> 3, cj = id & 7;
        cp16(&Kh[row * 72 + cj * 8], &Kg[(size_t)row * DH + cj * 8]);
        cp16(&Vh[row * 72 + cj * 8], &Vg[(size_t)row * DH + cj * 8]);
    }
    asm volatile("cp.async.commit_group;" ::: "memory");
    #pragma unroll
    for (int c = 0; c < 2; c++) {
        int id = tid + 256 * c;
        int row = id >> 3, cj = id & 7;
        cp16(&Kh[4608 + row * 72 + cj * 8], &Kg[(size_t)(64 + row) * DH + cj * 8]);
        cp16(&Vh[4608 + row * 72 + cj * 8], &Vg[(size_t)(64 + row) * DH + cj * 8]);
    }
    asm volatile("cp.async.commit_group;" ::: "memory");

    const int rbase = w * 16;
    const int rlo = rbase + grp, rhi = rlo + 8;
    const int rglo = q0 + rlo, rghi = q0 + rhi;
    const unsigned aoffH = (unsigned)((lane & 15) * 144 + (lane >> 4) * 16);
    const unsigned boffK = (unsigned)(((((lane >> 4) << 3) + (lane & 7))) * 144
                                      + ((lane >> 3) & 1) * 16);
    const unsigned boffV = (unsigned)((((lane & 7) + ((lane >> 3) & 1) * 8)) * 144
                                      + (lane >> 4) * 16);
    unsigned qa[4][4];
    {
        const unsigned qbase = smem_u32(Qh) + (unsigned)(rbase * 144) + aoffH;
        #pragma unroll
        for (int kk = 0; kk < 4; kk++)
            ldsm4(qa[kk][0], qa[kk][1], qa[kk][2], qa[kk][3], qbase + kk * 32);
    }
    __syncwarp();
    const float pLo_l = __bfloat162float(pbh[rlo * 132]);
    const float pHi_l = __bfloat162float(pbh[rlo * 132 + 128]);
    const float pLo_h = __bfloat162float(pbh[rhi * 132]);
    const float pHi_h = __bfloat162float(pbh[rhi * 132 + 128]);
    const unsigned ksb = smem_u32(Kh) + boffK;
    const unsigned vsb = smem_u32(Vh) + boffV;
    const unsigned psb = smem_u32(Qh) + (unsigned)(rbase * 144) + aoffH;

    float o[8][4];
    #pragma unroll
    for (int n = 0; n < 8; n++)
        #pragma unroll
        for (int c = 0; c < 4; c++) o[n][c] = 0.f;
    float m_lo = -INFINITY, m_hi = -INFINITY, l_lo = 0.f, l_hi = 0.f;

    for (int kt = 0; kt < 32; kt++) {
        const int buf = kt % 3;
        const int k0 = kt * 64;

        if (kt < 31) { asm volatile("cp.async.wait_group 1;" ::: "memory"); }
        else         { asm volatile("cp.async.wait_group 0;" ::: "memory"); }
        __syncthreads();

        if (kt + 2 < 32) {
            const int slot = (kt + 2) % 3;
            const __half* Kn = Kg + (size_t)(k0 + 128) * DH;
            const __half* Vn = Vg + (size_t)(k0 + 128) * DH;
            #pragma unroll
            for (int c = 0; c < 2; c++) {
                int id = tid + 256 * c;
                int row = id >> 3, cj = id & 7;
                cp16(&Kh[slot * 4608 + row * 72 + cj * 8], &Kn[(size_t)row * DH + cj * 8]);
                cp16(&Vh[slot * 4608 + row * 72 + cj * 8], &Vn[(size_t)row * DH + cj * 8]);
            }
            asm volatile("cp.async.commit_group;" ::: "memory");
        }
        if (kt < 31 && tid < 16)
            *(float4*)&maskS[((kt + 1) & 1) * 68 + tid * 4] = mv;
        if (kt < 30 && tid < 16)
            mv = *(const float4*)&maskb[(kt + 2) * 64 + tid * 4];

        float sc[8][4];
        #pragma unroll
        for (int n = 0; n < 8; n++)
            #pragma unroll
            for (int c = 0; c < 4; c++) sc[n][c] = 0.f;
        const unsigned kbuf = ksb + (unsigned)(buf * KVBUF_B);
        #pragma unroll
        for (int kk = 0; kk < 4; kk++) {
            #pragma unroll
            for (int np = 0; np < 4; np++) {
                unsigned b0, b1, b2, b3;
                ldsm4(b0, b1, b2, b3, kbuf + np * 2304 + kk * 32);
                mma_f16(sc[2*np][0], sc[2*np][1], sc[2*np][2], sc[2*np][3],
                        qa[kk][0], qa[kk][1], qa[kk][2], qa[kk][3], b0, b1);
                mma_f16(sc[2*np+1][0], sc[2*np+1][1], sc[2*np+1][2], sc[2*np+1][3],
                        qa[kk][0], qa[kk][1], qa[kk][2], qa[kk][3], b2, b3);
            }
        }

        const float* mk = maskS + (kt & 1) * 68;
        const int ddmin = k0 - (q0 + 127), ddmax = k0 + 63 - q0;
        const bool gen = (ddmax > -64) && (ddmin < 64);
        const float bC_l = (ddmin >= 64) ? pHi_l : pLo_l;
        const float bC_h = (ddmin >= 64) ? pHi_h : pLo_h;
        float mx_lo = -INFINITY, mx_hi = -INFINITY;
        #pragma unroll
        for (int n = 0; n < 8; n++) {
            const int c0 = n * 8 + 2 * tig;
            float2 mk2 = *(const float2*)&mk[c0];
            float b00, b01, b10, b11;
            if (gen) {
                int d0 = k0 + c0 - rglo;
                int t00 = d0     < -64 ? 0 : (d0     > 64 ? 128 : d0 + 64);
                int t01 = d0 + 1 < -64 ? 0 : (d0 + 1 > 64 ? 128 : d0 + 65);
                int d1 = k0 + c0 - rghi;
                int t10 = d1     < -64 ? 0 : (d1     > 64 ? 128 : d1 + 64);
                int t11 = d1 + 1 < -64 ? 0 : (d1 + 1 > 64 ? 128 : d1 + 65);
                b00 = __bfloat162float(pbh[rlo * 132 + t00]);
                b01 = __bfloat162float(pbh[rlo * 132 + t01]);
                b10 = __bfloat162float(pbh[rhi * 132 + t10]);
                b11 = __bfloat162float(pbh[rhi * 132 + t11]);
            } else { b00 = b01 = bC_l; b10 = b11 = bC_h; }
            sc[n][0] = sc[n][0] + b00 + mk2.x;
            sc[n][1] = sc[n][1] + b01 + mk2.y;
            sc[n][2] = sc[n][2] + b10 + mk2.x;
            sc[n][3] = sc[n][3] + b11 + mk2.y;
            mx_lo = fmaxf(mx_lo, fmaxf(sc[n][0], sc[n][1]));
            mx_hi = fmaxf(mx_hi, fmaxf(sc[n][2], sc[n][3]));
        }
        mx_lo = fmaxf(mx_lo, __shfl_xor_sync(0xffffffffu, mx_lo, 1, 4));
        mx_lo = fmaxf(mx_lo, __shfl_xor_sync(0xffffffffu, mx_lo, 2, 4));
        mx_hi = fmaxf(mx_hi, __shfl_xor_sync(0xffffffffu, mx_hi, 1, 4));
        mx_hi = fmaxf(mx_hi, __shfl_xor_sync(0xffffffffu, mx_hi, 2, 4));
        const float mn_lo = fmaxf(m_lo, mx_lo), mn_hi = fmaxf(m_hi, mx_hi);
        const float al_lo = __expf(m_lo - mn_lo), al_hi = __expf(m_hi - mn_hi);
        float rs_lo = 0.f, rs_hi = 0.f;
        #pragma unroll
        for (int n = 0; n < 8; n++) {
            sc[n][0] = __expf(sc[n][0] - mn_lo); rs_lo += sc[n][0];
            sc[n][1] = __expf(sc[n][1] - mn_lo); rs_lo += sc[n][1];
            sc[n][2] = __expf(sc[n][2] - mn_hi); rs_hi += sc[n][2];
            sc[n][3] = __expf(sc[n][3] - mn_hi); rs_hi += sc[n][3];
        }
        rs_lo += __shfl_xor_sync(0xffffffffu, rs_lo, 1, 4);
        rs_lo += __shfl_xor_sync(0xffffffffu, rs_lo, 2, 4);
        rs_hi += __shfl_xor_sync(0xffffffffu, rs_hi, 1, 4);
        rs_hi += __shfl_xor_sync(0xffffffffu, rs_hi, 2, 4);
        l_lo = l_lo * al_lo + rs_lo; m_lo = mn_lo;
        l_hi = l_hi * al_hi + rs_hi; m_hi = mn_hi;
        #pragma unroll
        for (int n = 0; n < 8; n++) {
            o[n][0] *= al_lo; o[n][1] *= al_lo;
            o[n][2] *= al_hi; o[n][3] *= al_hi;
        }
        __syncwarp();
        #pragma unroll
        for (int n = 0; n < 8; n++) {
            const int c0 = n * 8 + 2 * tig;
            *(unsigned*)&Qh[rlo * 72 + c0] = h2u(sc[n][0], sc[n][1]);
            *(unsigned*)&Qh[rhi * 72 + c0] = h2u(sc[n][2], sc[n][3]);
        }
        __syncwarp();

        const unsigned vbuf = vsb + (unsigned)(buf * KVBUF_B);
        #pragma unroll
        for (int jj = 0; jj < 4; jj++) {
            unsigned pa0, pa1, pa2, pa3;
            ldsm4(pa0, pa1, pa2, pa3, psb + jj * 32);
            #pragma unroll
            for (int np = 0; np < 4; np++) {
                unsigned b0, b1, b2, b3;
                ldsm4t(b0, b1, b2, b3, vbuf + jj * 2304 + np * 32);
                mma_f16(o[2*np][0], o[2*np][1], o[2*np][2], o[2*np][3],
                        pa0, pa1, pa2, pa3, b0, b1);
                mma_f16(o[2*np+1][0], o[2*np+1][1], o[2*np+1][2], o[2*np+1][3],
                        pa0, pa1, pa2, pa3, b2, b3);
            }
        }
    }

    const float inv_lo = 1.f / l_lo, inv_hi = 1.f / l_hi;
    #pragma unroll
    for (int n = 0; n < 8; n++) {
        const int col = h * DH + n * 8 + 2 * tig;
        *(float2*)&out[((size_t)(b * Sq + rglo)) * Dm + col] =
            make_float2(o[n][0] * inv_lo, o[n][1] * inv_lo);
        *(float2*)&out[((size_t)(b * Sq + rghi)) * Dm + col] =
            make_float2(o[n][2] * inv_hi, o[n][3] * inv_hi);
    }
}

extern "C" void kernel_launch(void* const* d_in, const int* in_sizes, int n_in,
                              void* d_out, int out_size)
{
    const float* query = (const float*)d_in[0];
    const float* key   = (const float*)d_in[1];
    const float* value = (const float*)d_in[2];
    const float* mask  = (const float*)d_in[3];
    const float* Wq    = (const float*)d_in[4];
    const float* bq    = (const float*)d_in[5];
    const float* Wk    = (const float*)d_in[6];
    const float* bk    = (const float*)d_in[7];
    const float* Wv    = (const float*)d_in[8];
    const float* bv    = (const float*)d_in[9];
    const float* rel   = (const float*)d_in[10];
    float* out = (float*)d_out;
    (void)in_sizes; (void)n_in; (void)out_size;

    __half* xh0; __half* xh1; __half* xh2;
    __half* wh0; __half* wh1; __half* wh2;
    cudaGetSymbolAddress((void**)&xh0, g_Xh);
    xh1 = xh0 + (size_t)Bz * Sq * Dm;
    xh2 = xh1 + (size_t)Bz * Sq * Dm;
    cudaGetSymbolAddress((void**)&wh0, g_Wh);
    wh1 = wh0 + (size_t)Dm * Dm;
    wh2 = wh1 + (size_t)Dm * Dm;

    const int NX8 = (Bz * Sq * Dm) / 8;     // 524288
    const int NW8 = (Dm * Dm) / 8;          // 131072
    cvt_kernel<<<(NX8 + 255) / 256, 256>>>(query, xh0, NX8);
    cvt_kernel<<<(NX8 + 255) / 256, 256>>>(key,   xh1, NX8);
    cvt_kernel<<<(NX8 + 255) / 256, 256>>>(value, xh2, NX8);
    cvt_kernel<<<(NW8 + 255) / 256, 256>>>(Wq, wh0, NW8);
    cvt_kernel<<<(NW8 + 255) / 256, 256>>>(Wk, wh1, NW8);
    cvt_kernel<<<(NW8 + 255) / 256, 256>>>(Wv, wh2, NW8);

    dim3 gemm_grid(Dm / 64, (Bz * Sq) / 128, 3);
    qkv_proj_kernel<<<gemm_grid, 256>>>(bq, bk, bv);

    const int ATTN_SMEM = SMH * (int)sizeof(__half);
    cudaFuncSetAttribute(attn_kernel,
                         cudaFuncAttributeMaxDynamicSharedMemorySize, ATTN_SMEM);
    dim3 attn_grid(Sq / 128, Bz * Hn);
    attn_kernel<<<attn_grid, 256, ATTN_SMEM>>>(mask, rel, out);
}

// round 17
// speedup vs baseline: 3.8666x; 1.1621x over previous
#include <cuda_runtime.h>
#include <cuda_bf16.h>
#include <cuda_fp16.h>
#include <math.h>

#define Bz 2
#define Sq 2048
#define Dm 1024
#define Hn 16
#define DH 64
#define NREL 129
#define BHN (Bz*Hn)
#define L2E 1.44269504f

typedef unsigned long long ull;

__device__ __half g_Qh[BHN * Sq * DH];
__device__ __half g_Kh[BHN * Sq * DH];
__device__ __half g_Vh[BHN * Sq * DH];
__device__ __half g_Xh[3][(size_t)Bz * Sq * Dm];
__device__ __half g_Wh[3][(size_t)Dm * Dm];

__device__ __forceinline__ ull pack2(float lo, float hi) {
    ull r; asm("mov.b64 %0, {%1, %2};" : "=l"(r) : "f"(lo), "f"(hi)); return r;
}
__device__ __forceinline__ float2 unpack2(ull v) {
    float2 r; asm("mov.b64 {%0, %1}, %2;" : "=f"(r.x), "=f"(r.y) : "l"(v)); return r;
}
__device__ __forceinline__ void fma2(ull& a, ull x, ull y) {
    asm("fma.rn.f32x2 %0, %1, %2, %0;" : "+l"(a) : "l"(x), "l"(y));
}
__device__ __forceinline__ void mma_f16(float& c0, float& c1, float& c2, float& c3,
                                        unsigned a0, unsigned a1, unsigned a2, unsigned a3,
                                        unsigned b0, unsigned b1) {
    asm("mma.sync.aligned.m16n8k16.row.col.f32.f16.f16.f32 "
        "{%0,%1,%2,%3}, {%4,%5,%6,%7}, {%8,%9}, {%0,%1,%2,%3};"
        : "+f"(c0), "+f"(c1), "+f"(c2), "+f"(c3)
        : "r"(a0), "r"(a1), "r"(a2), "r"(a3), "r"(b0), "r"(b1));
}
__device__ __forceinline__ void ldsm4(unsigned& r0, unsigned& r1, unsigned& r2, unsigned& r3,
                                      unsigned addr) {
    asm volatile("ldmatrix.sync.aligned.m8n8.x4.shared.b16 {%0,%1,%2,%3}, [%4];"
        : "=r"(r0), "=r"(r1), "=r"(r2), "=r"(r3) : "r"(addr));
}
__device__ __forceinline__ void ldsm4t(unsigned& r0, unsigned& r1, unsigned& r2, unsigned& r3,
                                       unsigned addr) {
    asm volatile("ldmatrix.sync.aligned.m8n8.x4.trans.shared.b16 {%0,%1,%2,%3}, [%4];"
        : "=r"(r0), "=r"(r1), "=r"(r2), "=r"(r3) : "r"(addr));
}
__device__ __forceinline__ unsigned smem_u32(const void* p) {
    return (unsigned)__cvta_generic_to_shared(p);
}
__device__ __forceinline__ unsigned h2u(float a, float b) {
    __half2 h = __floats2half2_rn(a, b);
    return *(unsigned*)&h;
}
__device__ __forceinline__ __half2 h2exp2_(__half2 x) {
    unsigned r, xi = *(unsigned*)&x;
    asm("ex2.approx.f16x2 %0, %1;" : "=r"(r) : "r"(xi));
    return *(__half2*)&r;
}
__device__ __forceinline__ void cp16(void* dst, const void* src) {
    unsigned a = (unsigned)__cvta_generic_to_shared(dst);
    asm volatile("cp.async.cg.shared.global [%0], [%1], 16;" :: "r"(a), "l"(src) : "memory");
}

// ---------------------------------------------------------------------------
// Kernel 0: fused fp32->fp16 convert of all 6 tensors. NX8=2^19, NW8=2^17.
// ---------------------------------------------------------------------------
#define NX8 524288
#define NW8 131072

__global__ void cvt_all_kernel(const float* __restrict__ q, const float* __restrict__ k,
                               const float* __restrict__ v, const float* __restrict__ wq,
                               const float* __restrict__ wk, const float* __restrict__ wv)
{
    const unsigned i = blockIdx.x * 256 + threadIdx.x;
    const float* src; __half* dst; size_t off;
    if (i < 3u * NX8) {
        const unsigned sec = i >> 19;
        off = (size_t)(i & (NX8 - 1)) * 8;
        src = (sec == 0) ? q : (sec == 1) ? k : v;
        dst = g_Xh[sec];
    } else {
        const unsigned j = i - 3u * NX8;
        const unsigned sec = j >> 17;
        off = (size_t)(j & (NW8 - 1)) * 8;
        src = (sec == 0) ? wq : (sec == 1) ? wk : wv;
        dst = g_Wh[sec];
    }
    const float4 a = *(const float4*)(src + off);
    const float4 b = *(const float4*)(src + off + 4);
    uint4 p;
    p.x = h2u(a.x, a.y); p.y = h2u(a.z, a.w);
    p.z = h2u(b.x, b.y); p.w = h2u(b.z, b.w);
    *(uint4*)&dst[off] = p;
}

// ---------------------------------------------------------------------------
// Kernel 1: QKV projection (round-16, Q scale now 0.125*log2e).
// ---------------------------------------------------------------------------
#define GX_SL 5120
#define GW_SL 2304

__global__ __launch_bounds__(256, 2)
void qkv_proj_kernel(const float* __restrict__ bq, const float* __restrict__ bk,
                     const float* __restrict__ bv)
{
    const int z = blockIdx.z;
    const __half* X = g_Xh[z];
    const __half* W = g_Wh[z];
    const float* bias = (z == 0) ? bq : (z == 1) ? bk : bv;
    __half* outp = (z == 0) ? g_Qh : (z == 1) ? g_Kh : g_Vh;
    const float scale = (z == 0) ? (0.125f * L2E) : 1.0f;

    __shared__ __align__(16) __half Xs[3 * GX_SL];
    __shared__ __align__(16) __half Ws[3 * GW_SL];

    const int tid = threadIdx.x;
    const int lane = tid & 31, w = tid >> 5;
    const int wm = w >> 1, wn = w & 1;
    const int grp = lane >> 2, tig = lane & 3;
    const int m0 = blockIdx.y * 128, n0 = blockIdx.x * 64;

    const unsigned aoffX = (unsigned)((lane & 15) * 80 + (lane >> 4) * 16);
    const unsigned boffW = (unsigned)(((lane & 7) + ((lane >> 3) & 1) * 8) * 144
                                      + (lane >> 4) * 16);

    const int xrow0 = tid >> 2, xck = (tid & 3);
    const int xrow1 = (tid + 256) >> 2, xck1 = (tid & 3);
    const int wrow = tid >> 3, wck = tid & 7;

    float acc[2][4][4];
    #pragma unroll
    for (int mi = 0; mi < 2; mi++)
        #pragma unroll
        for (int ni = 0; ni < 4; ni++)
            #pragma unroll
            for (int c = 0; c < 4; c++) acc[mi][ni][c] = 0.f;

    #pragma unroll
    for (int s = 0; s < 2; s++) {
        const __half* Xsrc = X + (size_t)m0 * Dm + s * 32;
        const __half* Wsrc = W + (size_t)(s * 32) * Dm + n0;
        cp16(&Xs[s * GX_SL + xrow0 * 40 + xck * 8], &Xsrc[(size_t)xrow0 * Dm + xck * 8]);
        cp16(&Xs[s * GX_SL + xrow1 * 40 + xck1 * 8], &Xsrc[(size_t)xrow1 * Dm + xck1 * 8]);
        cp16(&Ws[s * GW_SL + wrow * 72 + wck * 8], &Wsrc[(size_t)wrow * Dm + wck * 8]);
        asm volatile("cp.async.commit_group;" ::: "memory");
    }

    for (int t = 0; t < 32; t++) {
        const int slot = t % 3;
        if (t < 31) { asm volatile("cp.async.wait_group 1;" ::: "memory"); }
        else        { asm volatile("cp.async.wait_group 0;" ::: "memory"); }
        __syncthreads();

        if (t + 2 < 32) {
            const int ns = (t + 2) % 3;
            const __half* Xsrc = X + (size_t)m0 * Dm + (t + 2) * 32;
            const __half* Wsrc = W + (size_t)((t + 2) * 32) * Dm + n0;
            cp16(&Xs[ns * GX_SL + xrow0 * 40 + xck * 8], &Xsrc[(size_t)xrow0 * Dm + xck * 8]);
            cp16(&Xs[ns * GX_SL + xrow1 * 40 + xck1 * 8], &Xsrc[(size_t)xrow1 * Dm + xck1 * 8]);
            cp16(&Ws[ns * GW_SL + wrow * 72 + wck * 8], &Wsrc[(size_t)wrow * Dm + wck * 8]);
            asm volatile("cp.async.commit_group;" ::: "memory");
        }

        const unsigned xb = smem_u32(Xs) + (unsigned)(slot * GX_SL * 2)
                            + (unsigned)(wm * 32 * 80) + aoffX;
        const unsigned wb = smem_u32(Ws) + (unsigned)(slot * GW_SL * 2)
                            + (unsigned)(wn * 64) + boffW;
        #pragma unroll
        for (int kk = 0; kk < 2; kk++) {
            unsigned a0[4], a1[4];
            ldsm4(a0[0], a0[1], a0[2], a0[3], xb + kk * 32);
            ldsm4(a1[0], a1[1], a1[2], a1[3], xb + 16 * 80 + kk * 32);
            #pragma unroll
            for (int np = 0; np < 2; np++) {
                unsigned b0, b1, b2, b3;
                ldsm4t(b0, b1, b2, b3, wb + kk * 2304 + np * 32);
                mma_f16(acc[0][2*np][0], acc[0][2*np][1], acc[0][2*np][2], acc[0][2*np][3],
                        a0[0], a0[1], a0[2], a0[3], b0, b1);
                mma_f16(acc[0][2*np+1][0], acc[0][2*np+1][1], acc[0][2*np+1][2], acc[0][2*np+1][3],
                        a0[0], a0[1], a0[2], a0[3], b2, b3);
                mma_f16(acc[1][2*np][0], acc[1][2*np][1], acc[1][2*np][2], acc[1][2*np][3],
                        a1[0], a1[1], a1[2], a1[3], b0, b1);
                mma_f16(acc[1][2*np+1][0], acc[1][2*np+1][1], acc[1][2*np+1][2], acc[1][2*np+1][3],
                        a1[0], a1[1], a1[2], a1[3], b2, b3);
            }
        }
    }

    const int h = blockIdx.x;
    #pragma unroll
    for (int mi = 0; mi < 2; mi++) {
        const int mlo = m0 + wm * 32 + mi * 16 + grp;
        const int mhi = mlo + 8;
        const int blo = mlo >> 11, slo = mlo & 2047;
        const int bhi = mhi >> 11, shi = mhi & 2047;
        #pragma unroll
        for (int ni = 0; ni < 4; ni++) {
            const int col = wn * 32 + ni * 8 + 2 * tig;
            const float b0v = bias[n0 + col], b1v = bias[n0 + col + 1];
            *(unsigned*)&outp[((size_t)((blo * Hn + h) * Sq + slo)) * DH + col] =
                h2u((acc[mi][ni][0] + b0v) * scale, (acc[mi][ni][1] + b1v) * scale);
            *(unsigned*)&outp[((size_t)((bhi * Hn + h) * Sq + shi)) * DH + col] =
                h2u((acc[mi][ni][2] + b0v) * scale, (acc[mi][ni][3] + b1v) * scale);
        }
    }
}

// ---------------------------------------------------------------------------
// Kernel 2: flash attention, fp16 mma, half2 log2-domain softmax.
// ---------------------------------------------------------------------------
#define QS_H 0
#define KS_H 9216
#define VS_H 23040
#define MK_H 36864
#define PBH_H 37136
#define SMH  54032
#define KVBUF_B 9216

extern __shared__ __align__(16) __half smh[];

__global__ __launch_bounds__(256, 2)
void attn_kernel(const float* __restrict__ mask,
                 const float* __restrict__ rel,
                 float* __restrict__ out)
{
    __half* Qh = smh + QS_H;
    __half* Kh = smh + KS_H;
    __half* Vh = smh + VS_H;
    __half2* maskH = (__half2*)(smh + MK_H);   // [2][32] half2 (mask * log2e)
    __nv_bfloat16* pbh = (__nv_bfloat16*)(smh + PBH_H);
    float* relS = (float*)(smh + KS_H);

    const int tid = threadIdx.x;
    const int w = tid >> 5, lane = tid & 31;
    const int grp = lane >> 2, tig = lane & 3;
    const int bh = blockIdx.y, b = bh >> 4, h = bh & 15;
    const int q0 = blockIdx.x * 128;

    const __half* Qg = g_Qh + (size_t)bh * (Sq * DH);
    const __half* Kg = g_Kh + (size_t)bh * (Sq * DH);
    const __half* Vg = g_Vh + (size_t)bh * (Sq * DH);
    const float* maskb = mask + (size_t)b * Sq;

    #pragma unroll
    for (int c = 0; c < 4; c++) {
        int id = tid + 256 * c;
        int row = id >> 3, cj = id & 7;
        cp16(&Qh[row * 72 + cj * 8], &Qg[(size_t)(q0 + row) * DH + cj * 8]);
    }
    for (int i = tid; i < NREL * 32; i += 256) {
        int t = i >> 5, dp = i & 31;
        *(float2*)&relS[t * 66 + 2 * dp] = *(const float2*)&rel[t * DH + 2 * dp];
    }
    float4 mv;
    if (tid < 16) {
        float4 m0v = *(const float4*)&maskb[tid * 4];
        maskH[tid * 2]     = __floats2half2_rn(m0v.x * L2E, m0v.y * L2E);
        maskH[tid * 2 + 1] = __floats2half2_rn(m0v.z * L2E, m0v.w * L2E);
        mv = *(const float4*)&maskb[64 + tid * 4];
    }
    asm volatile("cp.async.commit_group;" ::: "memory");
    asm volatile("cp.async.wait_group 0;" ::: "memory");
    __syncthreads();

    // ---- pb table (log2 domain automatically: Qh pre-scaled by 0.125*log2e) ----
    {
        const int tx = tid & 15, ty = tid >> 4;
        #pragma unroll
        for (int pass = 0; pass < 2; pass++) {
            const int rb = ty * 8 + pass * 4;
            ull pa[4][9];
            #pragma unroll
            for (int i = 0; i < 4; i++)
                #pragma unroll
                for (int tt = 0; tt < 9; tt++) pa[i][tt] = 0ull;
            for (int dp = 0; dp < 32; dp++) {
                ull qv[4];
                #pragma unroll
                for (int i = 0; i < 4; i++) {
                    __half2 qh = *(const __half2*)&Qh[(rb + i) * 72 + 2 * dp];
                    float2 qf = __half22float2(qh);
                    qv[i] = pack2(qf.x, qf.y);
                }
                #pragma unroll
                for (int tt = 0; tt < 9; tt++) {
                    int t = tx + 16 * tt;
                    if (t < NREL) {
                        ull rv = *(const ull*)&relS[t * 66 + 2 * dp];
                        fma2(pa[0][tt], qv[0], rv);
                        fma2(pa[1][tt], qv[1], rv);
                        fma2(pa[2][tt], qv[2], rv);
                        fma2(pa[3][tt], qv[3], rv);
                    }
                }
            }
            #pragma unroll
            for (int tt = 0; tt < 9; tt++) {
                int t = tx + 16 * tt;
                if (t < NREL) {
                    #pragma unroll
                    for (int i = 0; i < 4; i++) {
                        float2 f = unpack2(pa[i][tt]);
                        pbh[(rb + i) * 132 + t] = __float2bfloat16(f.x + f.y);
                    }
                }
            }
        }
    }
    __syncthreads();

    #pragma unroll
    for (int c = 0; c < 2; c++) {
        int id = tid + 256 * c;
        int row = id >> 3, cj = id & 7;
        cp16(&Kh[row * 72 + cj * 8], &Kg[(size_t)row * DH + cj * 8]);
        cp16(&Vh[row * 72 + cj * 8], &Vg[(size_t)row * DH + cj * 8]);
    }
    asm volatile("cp.async.commit_group;" ::: "memory");
    #pragma unroll
    for (int c = 0; c < 2; c++) {
        int id = tid + 256 * c;
        int row = id >> 3, cj = id & 7;
        cp16(&Kh[4608 + row * 72 + cj * 8], &Kg[(size_t)(64 + row) * DH + cj * 8]);
        cp16(&Vh[4608 + row * 72 + cj * 8], &Vg[(size_t)(64 + row) * DH + cj * 8]);
    }
    asm volatile("cp.async.commit_group;" ::: "memory");

    const int rbase = w * 16;
    const int rlo = rbase + grp, rhi = rlo + 8;
    const int rglo = q0 + rlo, rghi = q0 + rhi;
    const unsigned aoffH = (unsigned)((lane & 15) * 144 + (lane >> 4) * 16);
    const unsigned boffK = (unsigned)(((((lane >> 4) << 3) + (lane & 7))) * 144
                                      + ((lane >> 3) & 1) * 16);
    const unsigned boffV = (unsigned)((((lane & 7) + ((lane >> 3) & 1) * 8)) * 144
                                      + (lane >> 4) * 16);
    unsigned qa[4][4];
    {
        const unsigned qbase = smem_u32(Qh) + (unsigned)(rbase * 144) + aoffH;
        #pragma unroll
        for (int kk = 0; kk < 4; kk++)
            ldsm4(qa[kk][0], qa[kk][1], qa[kk][2], qa[kk][3], qbase + kk * 32);
    }
    __syncwarp();
    const float pLo_l = __bfloat162float(pbh[rlo * 132]);
    const float pHi_l = __bfloat162float(pbh[rlo * 132 + 128]);
    const float pLo_h = __bfloat162float(pbh[rhi * 132]);
    const float pHi_h = __bfloat162float(pbh[rhi * 132 + 128]);
    const unsigned ksb = smem_u32(Kh) + boffK;
    const unsigned vsb = smem_u32(Vh) + boffV;
    const unsigned psb = smem_u32(Qh) + (unsigned)(rbase * 144) + aoffH;

    float o[8][4];
    #pragma unroll
    for (int n = 0; n < 8; n++)
        #pragma unroll
        for (int c = 0; c < 4; c++) o[n][c] = 0.f;
    float m_lo = -INFINITY, m_hi = -INFINITY, l_lo = 0.f, l_hi = 0.f;

    for (int kt = 0; kt < 32; kt++) {
        const int buf = kt % 3;
        const int k0 = kt * 64;

        if (kt < 31) { asm volatile("cp.async.wait_group 1;" ::: "memory"); }
        else         { asm volatile("cp.async.wait_group 0;" ::: "memory"); }
        __syncthreads();

        if (kt + 2 < 32) {
            const int slot = (kt + 2) % 3;
            const __half* Kn = Kg + (size_t)(k0 + 128) * DH;
            const __half* Vn = Vg + (size_t)(k0 + 128) * DH;
            #pragma unroll
            for (int c = 0; c < 2; c++) {
                int id = tid + 256 * c;
                int row = id >> 3, cj = id & 7;
                cp16(&Kh[slot * 4608 + row * 72 + cj * 8], &Kn[(size_t)row * DH + cj * 8]);
                cp16(&Vh[slot * 4608 + row * 72 + cj * 8], &Vn[(size_t)row * DH + cj * 8]);
            }
            asm volatile("cp.async.commit_group;" ::: "memory");
        }
        if (kt < 31 && tid < 16) {
            __half2* mh = maskH + ((kt + 1) & 1) * 32 + tid * 2;
            mh[0] = __floats2half2_rn(mv.x * L2E, mv.y * L2E);
            mh[1] = __floats2half2_rn(mv.z * L2E, mv.w * L2E);
        }
        if (kt < 30 && tid < 16) mv = *(const float4*)&maskb[(kt + 2) * 64 + tid * 4];

        // ---- scores ----
        float sc[8][4];
        #pragma unroll
        for (int n = 0; n < 8; n++)
            #pragma unroll
            for (int c = 0; c < 4; c++) sc[n][c] = 0.f;
        const unsigned kbuf = ksb + (unsigned)(buf * KVBUF_B);
        #pragma unroll
        for (int kk = 0; kk < 4; kk++) {
            #pragma unroll
            for (int np = 0; np < 4; np++) {
                unsigned b0, b1, b2, b3;
                ldsm4(b0, b1, b2, b3, kbuf + np * 2304 + kk * 32);
                mma_f16(sc[2*np][0], sc[2*np][1], sc[2*np][2], sc[2*np][3],
                        qa[kk][0], qa[kk][1], qa[kk][2], qa[kk][3], b0, b1);
                mma_f16(sc[2*np+1][0], sc[2*np+1][1], sc[2*np+1][2], sc[2*np+1][3],
                        qa[kk][0], qa[kk][1], qa[kk][2], qa[kk][3], b2, b3);
            }
        }

        // ---- bias + mask (half2, log2 domain) ----
        const __half2* mkh = maskH + (kt & 1) * 32;
        const int ddmin = k0 - (q0 + 127), ddmax = k0 + 63 - q0;
        const bool gen = (ddmax > -64) && (ddmin < 64);
        __half2 pl[8], ph[8];
        if (!gen) {
            const float bCl = (ddmin >= 64) ? pHi_l : pLo_l;
            const float bCh = (ddmin >= 64) ? pHi_h : pLo_h;
            const __half2 bl2 = __float2half2_rn(bCl);
            const __half2 bh2 = __float2half2_rn(bCh);
            #pragma unroll
            for (int n = 0; n < 8; n++) {
                __half2 mk2 = mkh[n * 4 + tig];
                pl[n] = __hadd2(__floats2half2_rn(sc[n][0], sc[n][1]), __hadd2(bl2, mk2));
                ph[n] = __hadd2(__floats2half2_rn(sc[n][2], sc[n][3]), __hadd2(bh2, mk2));
            }
        } else {
            #pragma unroll
            for (int n = 0; n < 8; n++) {
                const int c0 = n * 8 + 2 * tig;
                float2 mkf = __half22float2(mkh[n * 4 + tig]);
                int d0 = k0 + c0 - rglo;
                int t00 = d0     < -64 ? 0 : (d0     > 64 ? 128 : d0 + 64);
                int t01 = d0 + 1 < -64 ? 0 : (d0 + 1 > 64 ? 128 : d0 + 65);
                int d1 = k0 + c0 - rghi;
                int t10 = d1     < -64 ? 0 : (d1     > 64 ? 128 : d1 + 64);
                int t11 = d1 + 1 < -64 ? 0 : (d1 + 1 > 64 ? 128 : d1 + 65);
                float b00 = __bfloat162float(pbh[rlo * 132 + t00]);
                float b01 = __bfloat162float(pbh[rlo * 132 + t01]);
                float b10 = __bfloat162float(pbh[rhi * 132 + t10]);
                float b11 = __bfloat162float(pbh[rhi * 132 + t11]);
                pl[n] = __floats2half2_rn(sc[n][0] + b00 + mkf.x, sc[n][1] + b01 + mkf.y);
                ph[n] = __floats2half2_rn(sc[n][2] + b10 + mkf.x, sc[n][3] + b11 + mkf.y);
            }
        }

        // ---- max (half2 trees -> fp32 cross-thread) ----
        __half2 hml = pl[0], hmh = ph[0];
        #pragma unroll
        for (int n = 1; n < 8; n++) {
            hml = __hmax2(hml, pl[n]);
            hmh = __hmax2(hmh, ph[n]);
        }
        float mx_lo = fmaxf(__low2float(hml), __high2float(hml));
        float mx_hi = fmaxf(__low2float(hmh), __high2float(hmh));
        mx_lo = fmaxf(mx_lo, __shfl_xor_sync(0xffffffffu, mx_lo, 1, 4));
        mx_lo = fmaxf(mx_lo, __shfl_xor_sync(0xffffffffu, mx_lo, 2, 4));
        mx_hi = fmaxf(mx_hi, __shfl_xor_sync(0xffffffffu, mx_hi, 1, 4));
        mx_hi = fmaxf(mx_hi, __shfl_xor_sync(0xffffffffu, mx_hi, 2, 4));
        const float mn_lo = fmaxf(m_lo, mx_lo), mn_hi = fmaxf(m_hi, mx_hi);
        const float al_lo = exp2f(m_lo - mn_lo), al_hi = exp2f(m_hi - mn_hi);

        // ---- exp (ex2.f16x2) + sums ----
        const __half2 mn2l = __float2half2_rn(mn_lo);
        const __half2 mn2h = __float2half2_rn(mn_hi);
        __half2 rs2l = __float2half2_rn(0.f), rs2h = rs2l;
        #pragma unroll
        for (int n = 0; n < 8; n++) {
            pl[n] = h2exp2_(__hsub2(pl[n], mn2l));
            ph[n] = h2exp2_(__hsub2(ph[n], mn2h));
            rs2l = __hadd2(rs2l, pl[n]);
            rs2h = __hadd2(rs2h, ph[n]);
        }
        float2 fl = __half22float2(rs2l), fh = __half22float2(rs2h);
        float rs_lo = fl.x + fl.y, rs_hi = fh.x + fh.y;
        rs_lo += __shfl_xor_sync(0xffffffffu, rs_lo, 1, 4);
        rs_lo += __shfl_xor_sync(0xffffffffu, rs_lo, 2, 4);
        rs_hi += __shfl_xor_sync(0xffffffffu, rs_hi, 1, 4);
        rs_hi += __shfl_xor_sync(0xffffffffu, rs_hi, 2, 4);
        l_lo = l_lo * al_lo + rs_lo; m_lo = mn_lo;
        l_hi = l_hi * al_hi + rs_hi; m_hi = mn_hi;
        #pragma unroll
        for (int n = 0; n < 8; n++) {
            o[n][0] *= al_lo; o[n][1] *= al_lo;
            o[n][2] *= al_hi; o[n][3] *= al_hi;
        }

        // ---- stage P (already half2) ----
        __syncwarp();
        #pragma unroll
        for (int n = 0; n < 8; n++) {
            const int c0 = n * 8 + 2 * tig;
            *(__half2*)&Qh[rlo * 72 + c0] = pl[n];
            *(__half2*)&Qh[rhi * 72 + c0] = ph[n];
        }
        __syncwarp();

        // ---- O += P V ----
        const unsigned vbuf = vsb + (unsigned)(buf * KVBUF_B);
        #pragma unroll
        for (int jj = 0; jj < 4; jj++) {
            unsigned pa0, pa1, pa2, pa3;
            ldsm4(pa0, pa1, pa2, pa3, psb + jj * 32);
            #pragma unroll
            for (int np = 0; np < 4; np++) {
                unsigned b0, b1, b2, b3;
                ldsm4t(b0, b1, b2, b3, vbuf + jj * 2304 + np * 32);
                mma_f16(o[2*np][0], o[2*np][1], o[2*np][2], o[2*np][3],
                        pa0, pa1, pa2, pa3, b0, b1);
                mma_f16(o[2*np+1][0], o[2*np+1][1], o[2*np+1][2], o[2*np+1][3],
                        pa0, pa1, pa2, pa3, b2, b3);
            }
        }
    }

    const float inv_lo = 1.f / l_lo, inv_hi = 1.f / l_hi;
    #pragma unroll
    for (int n = 0; n < 8; n++) {
        const int col = h * DH + n * 8 + 2 * tig;
        *(float2*)&out[((size_t)(b * Sq + rglo)) * Dm + col] =
            make_float2(o[n][0] * inv_lo, o[n][1] * inv_lo);
        *(float2*)&out[((size_t)(b * Sq + rghi)) * Dm + col] =
            make_float2(o[n][2] * inv_hi, o[n][3] * inv_hi);
    }
}

extern "C" void kernel_launch(void* const* d_in, const int* in_sizes, int n_in,
                              void* d_out, int out_size)
{
    const float* query = (const float*)d_in[0];
    const float* key   = (const float*)d_in[1];
    const float* value = (const float*)d_in[2];
    const float* mask  = (const float*)d_in[3];
    const float* Wq    = (const float*)d_in[4];
    const float* bq    = (const float*)d_in[5];
    const float* Wk    = (const float*)d_in[6];
    const float* bk    = (const float*)d_in[7];
    const float* Wv    = (const float*)d_in[8];
    const float* bv    = (const float*)d_in[9];
    const float* rel   = (const float*)d_in[10];
    float* out = (float*)d_out;
    (void)in_sizes; (void)n_in; (void)out_size;

    const unsigned total8 = 3u * NX8 + 3u * NW8;   // 1,966,080
    cvt_all_kernel<<<total8 / 256, 256>>>(query, key, value, Wq, Wk, Wv);

    dim3 gemm_grid(Dm / 64, (Bz * Sq) / 128, 3);
    qkv_proj_kernel<<<gemm_grid, 256>>>(bq, bk, bv);

    const int ATTN_SMEM = SMH * (int)sizeof(__half);
    cudaFuncSetAttribute(attn_kernel,
                         cudaFuncAttributeMaxDynamicSharedMemorySize, ATTN_SMEM);
    dim3 attn_grid(Sq / 128, Bz * Hn);
    attn_kernel<<<attn_grid, 256, ATTN_SMEM>>>(mask, rel, out);
}